// round 1
// baseline (speedup 1.0000x reference)
#include <cuda_runtime.h>
#include <math.h>

#define LQ 1600
#define CD 256
#define NH 8
#define HD 32
#define DFF 1024
#define H2D 40
#define W2D 40
#define WS 15
#define WSQ 225
#define PADR 7
#define SCALE 0.17677669529663687f  // 1/sqrt(32)

// ---------------- scratch (device globals; no allocation) ----------------
__device__ float g_tln[LQ * CD];
__device__ float g_qkin[LQ * CD];
__device__ float g_q[LQ * CD];
__device__ float g_k[LQ * CD];
__device__ float g_v[LQ * CD];
__device__ float g_att[LQ * CD];
__device__ float g_tgt1[LQ * CD];
__device__ float g_q2[LQ * CD];      // curr_Q
__device__ float g_v2[LQ * CD];      // curr_V
__device__ float g_idkv[LQ * 264];
__device__ float g_gK[LQ * CD];
__device__ float g_gV[LQ * CD];
__device__ float g_st[LQ * CD];
__device__ float g_tmp[LQ * CD];
__device__ float g_tgt2[LQ * CD];
__device__ float g_x1[LQ * DFF];
__device__ float g_x2[LQ * DFF];
__device__ float g_gn[32 * 2];

// ---------------- reductions ----------------
__device__ __forceinline__ float block_reduce(float v, float* red, bool is_max) {
    int lane = threadIdx.x & 31, wid = threadIdx.x >> 5;
#pragma unroll
    for (int o = 16; o; o >>= 1) {
        float u = __shfl_xor_sync(0xffffffffu, v, o);
        v = is_max ? fmaxf(v, u) : v + u;
    }
    if (!lane) red[wid] = v;
    __syncthreads();
    int nw = (blockDim.x + 31) >> 5;
    v = (lane < nw) ? red[lane] : (is_max ? -1e30f : 0.0f);
    if (!wid) {
#pragma unroll
        for (int o = 16; o; o >>= 1) {
            float u = __shfl_xor_sync(0xffffffffu, v, o);
            v = is_max ? fmaxf(v, u) : v + u;
        }
        if (!lane) red[0] = v;
    }
    __syncthreads();
    v = red[0];
    __syncthreads();
    return v;
}

// ---------------- LayerNorm (one block per row, 256 threads) ----------------
__global__ void ln_kernel(const float* __restrict__ in, const float* __restrict__ g,
                          const float* __restrict__ b, float* __restrict__ out,
                          const float* __restrict__ pos, float* __restrict__ out2) {
    __shared__ float red[32];
    int l = blockIdx.x, c = threadIdx.x;
    float x = in[l * CD + c];
    float m = block_reduce(x, red, false) * (1.0f / CD);
    float d = x - m;
    float var = block_reduce(d * d, red, false) * (1.0f / CD);
    float y = d * rsqrtf(var + 1e-5f) * g[c] + b[c];
    out[l * CD + c] = y;
    if (out2) out2[l * CD + c] = y + pos[l * CD + c];
}

// ---------------- GEMM: C[m,n] = sum_k A[m,k]*W[n,k] + bias[n] (+res) ----------------
// BM=BN=64, BK=16, 256 threads, 4x4 micro-tile
__global__ void gemm_kernel(const float* __restrict__ A, const float* __restrict__ W,
                            const float* __restrict__ bias, const float* __restrict__ res,
                            float* __restrict__ C, int M, int N, int K) {
    __shared__ float As[64][17];
    __shared__ float Ws[64][17];
    int tid = threadIdx.x;
    int bm = blockIdx.y * 64, bn = blockIdx.x * 64;
    int tr = tid / 16, tc = tid % 16;
    float acc[4][4] = {};
    int lr = tid / 4, lc4 = (tid % 4) * 4;
    for (int k0 = 0; k0 < K; k0 += 16) {
        int gm = bm + lr;
        if (gm < M) {
            float4 va = *reinterpret_cast<const float4*>(A + (size_t)gm * K + k0 + lc4);
            As[lr][lc4 + 0] = va.x; As[lr][lc4 + 1] = va.y;
            As[lr][lc4 + 2] = va.z; As[lr][lc4 + 3] = va.w;
        } else {
            As[lr][lc4 + 0] = As[lr][lc4 + 1] = As[lr][lc4 + 2] = As[lr][lc4 + 3] = 0.f;
        }
        int gn = bn + lr;
        if (gn < N) {
            float4 vw = *reinterpret_cast<const float4*>(W + (size_t)gn * K + k0 + lc4);
            Ws[lr][lc4 + 0] = vw.x; Ws[lr][lc4 + 1] = vw.y;
            Ws[lr][lc4 + 2] = vw.z; Ws[lr][lc4 + 3] = vw.w;
        } else {
            Ws[lr][lc4 + 0] = Ws[lr][lc4 + 1] = Ws[lr][lc4 + 2] = Ws[lr][lc4 + 3] = 0.f;
        }
        __syncthreads();
#pragma unroll
        for (int kk = 0; kk < 16; kk++) {
            float a[4], w[4];
#pragma unroll
            for (int i = 0; i < 4; i++) a[i] = As[tr * 4 + i][kk];
#pragma unroll
            for (int j = 0; j < 4; j++) w[j] = Ws[tc * 4 + j][kk];
#pragma unroll
            for (int i = 0; i < 4; i++)
#pragma unroll
                for (int j = 0; j < 4; j++) acc[i][j] = fmaf(a[i], w[j], acc[i][j]);
        }
        __syncthreads();
    }
#pragma unroll
    for (int i = 0; i < 4; i++) {
        int m = bm + tr * 4 + i;
        if (m >= M) continue;
#pragma unroll
        for (int j = 0; j < 4; j++) {
            int n = bn + tc * 4 + j;
            if (n >= N) continue;
            float v = acc[i][j] + bias[n];
            if (res) v += res[(size_t)m * N + n];
            C[(size_t)m * N + n] = v;
        }
    }
}

// ---------------- dense MHA (one block per (query, head)) ----------------
__global__ void attn_kernel(const float* __restrict__ Q, const float* __restrict__ K,
                            const float* __restrict__ V, float* __restrict__ O, int Lk) {
    __shared__ float qs[HD];
    __shared__ float lg[LQ];
    __shared__ float red[32];
    __shared__ float accs[8][33];
    int m = blockIdx.x, h = blockIdx.y, tid = threadIdx.x;
    if (tid < HD) qs[tid] = Q[m * CD + h * HD + tid] * SCALE;
    __syncthreads();
    float lmax = -1e30f;
    for (int k = tid; k < Lk; k += blockDim.x) {
        const float* kp = K + (size_t)k * CD + h * HD;
        float d = 0.f;
#pragma unroll
        for (int j = 0; j < HD; j++) d = fmaf(qs[j], kp[j], d);
        lg[k] = d;
        lmax = fmaxf(lmax, d);
    }
    float gmax = block_reduce(lmax, red, true);
    float lsum = 0.f;
    for (int k = tid; k < Lk; k += blockDim.x) {
        float e = __expf(lg[k] - gmax);
        lg[k] = e;
        lsum += e;
    }
    float gsum = block_reduce(lsum, red, false);
    __syncthreads();
    int grp = tid >> 5, lane = tid & 31;
    float acc = 0.f;
    for (int k = grp; k < Lk; k += 8)
        acc = fmaf(lg[k], V[(size_t)k * CD + h * HD + lane], acc);
    accs[grp][lane] = acc;
    __syncthreads();
    if (tid < HD) {
        float s = 0.f;
#pragma unroll
        for (int g2 = 0; g2 < 8; g2++) s += accs[g2][tid];
        O[m * CD + h * HD + tid] = s / gsum;
    }
}

// ---------------- local attention (15x15 window) ----------------
__global__ void local_attn_kernel(const float* __restrict__ Q, const float* __restrict__ K,
                                  const float* __restrict__ V, float* __restrict__ O) {
    __shared__ float qs[HD];
    __shared__ float lg[WSQ];
    __shared__ float red[32];
    __shared__ float accs[8][33];
    int n = blockIdx.x, h = blockIdx.y, tid = threadIdx.x;
    int y = n / W2D, x = n % W2D;
    if (tid < HD) qs[tid] = Q[n * CD + h * HD + tid] * SCALE;
    __syncthreads();
    float lmax = -1e30f;
    if (tid < WSQ) {
        int dy = tid / WS - PADR, dx = tid % WS - PADR;
        int ny = y + dy, nx = x + dx;
        float d;
        if (ny >= 0 && ny < H2D && nx >= 0 && nx < W2D) {
            const float* kp = K + (size_t)(ny * W2D + nx) * CD + h * HD;
            d = 0.f;
#pragma unroll
            for (int j = 0; j < HD; j++) d = fmaf(qs[j], kp[j], d);
        } else {
            d = -1e9f;
        }
        lg[tid] = d;
        lmax = d;
    }
    float gmax = block_reduce(lmax, red, true);
    float lsum = 0.f;
    if (tid < WSQ) {
        float e = __expf(lg[tid] - gmax);
        lg[tid] = e;
        lsum = e;
    }
    float gsum = block_reduce(lsum, red, false);
    __syncthreads();
    int grp = tid >> 5, lane = tid & 31;
    float acc = 0.f;
    for (int w = grp; w < WSQ; w += 8) {
        int dy = w / WS - PADR, dx = w % WS - PADR;
        int ny = y + dy, nx = x + dx;
        if (ny < 0 || ny >= H2D || nx < 0 || nx >= W2D) continue;
        acc = fmaf(lg[w], V[(size_t)(ny * W2D + nx) * CD + h * HD + lane], acc);
    }
    accs[grp][lane] = acc;
    __syncthreads();
    if (tid < HD) {
        float s = 0.f;
#pragma unroll
        for (int g2 = 0; g2 < 8; g2++) s += accs[g2][tid];
        O[n * CD + h * HD + tid] = s / gsum;
    }
}

// ---------------- global K/V construction ----------------
__global__ void make_global_kv(const float* __restrict__ q, const float* __restrict__ v,
                               const float* __restrict__ idkv, float* __restrict__ gK,
                               float* __restrict__ gV) {
    int i = blockIdx.x * blockDim.x + threadIdx.x;
    if (i >= LQ * CD) return;
    int l = i >> 8, c = i & 255, h = c >> 5;
    float ik = idkv[l * 264 + h];
    gK[i] = q[i] * (1.0f + tanhf(ik));
    gV[i] = v[i] + idkv[l * 264 + 8 + c];
}

// ---------------- GroupNorm stats (32 blocks) ----------------
__global__ void gn_stats(const float* __restrict__ x, float* __restrict__ stats) {
    __shared__ float red[32];
    int g = blockIdx.x;
    float s = 0.f, ss = 0.f;
    for (int i = threadIdx.x; i < LQ * 32; i += blockDim.x) {
        int l = i >> 5, c = (g << 5) + (i & 31);
        float v = x[(size_t)l * DFF + c];
        s += v;
        ss = fmaf(v, v, ss);
    }
    s = block_reduce(s, red, false);
    ss = block_reduce(ss, red, false);
    if (!threadIdx.x) {
        const float inv = 1.0f / (LQ * 32.0f);
        float m = s * inv;
        float var = ss * inv - m * m;
        stats[g * 2] = m;
        stats[g * 2 + 1] = rsqrtf(var + 1e-5f);
    }
}

// ---------------- GN apply + affine + exact GELU ----------------
__global__ void gn_apply_gelu(const float* __restrict__ x, const float* __restrict__ stats,
                              const float* __restrict__ gg, const float* __restrict__ gb,
                              float* __restrict__ y) {
    int i = blockIdx.x * blockDim.x + threadIdx.x;
    if (i >= LQ * DFF) return;
    int c = i & (DFF - 1);
    int grp = c >> 5;
    float m = stats[grp * 2], r = stats[grp * 2 + 1];
    float v = (x[i] - m) * r * gg[c] + gb[c];
    y[i] = 0.5f * v * (1.0f + erff(v * 0.70710678118654752f));
}

// ---------------- depthwise 5x5 conv, pad 2 ----------------
__global__ void dwconv_kernel(const float* __restrict__ x, const float* __restrict__ k,
                              float* __restrict__ y) {
    int l = blockIdx.x;
    int yy = l / W2D, xx = l % W2D;
    for (int c = threadIdx.x; c < DFF; c += blockDim.x) {
        float acc = 0.f;
#pragma unroll
        for (int i = 0; i < 5; i++) {
            int ny = yy + i - 2;
            if (ny < 0 || ny >= H2D) continue;
#pragma unroll
            for (int j = 0; j < 5; j++) {
                int nx = xx + j - 2;
                if (nx < 0 || nx >= W2D) continue;
                acc = fmaf(x[(size_t)(ny * W2D + nx) * DFF + c], k[c * 25 + i * 5 + j], acc);
            }
        }
        y[(size_t)l * DFF + c] = acc;
    }
}

// ---------------- host ----------------
static void launch_gemm(const float* A, const float* W, const float* bias, const float* res,
                        float* C, int M, int N, int K) {
    dim3 grid((N + 63) / 64, (M + 63) / 64);
    gemm_kernel<<<grid, 256>>>(A, W, bias, res, C, M, N, K);
}

extern "C" void kernel_launch(void* const* d_in, const int* in_sizes, int n_in,
                              void* d_out, int out_size) {
    const float* tgt = (const float*)d_in[0];
    const float* curr_id_emb = (const float*)d_in[1];
    const float* self_pos = (const float*)d_in[2];
    const float* ln1_g = (const float*)d_in[3];
    const float* ln1_b = (const float*)d_in[4];
    const float* sa_wq = (const float*)d_in[5];
    const float* sa_bq = (const float*)d_in[6];
    const float* sa_wk = (const float*)d_in[7];
    const float* sa_bk = (const float*)d_in[8];
    const float* sa_wv = (const float*)d_in[9];
    const float* sa_bv = (const float*)d_in[10];
    const float* sa_wo = (const float*)d_in[11];
    const float* sa_bo = (const float*)d_in[12];
    const float* ln2_g = (const float*)d_in[13];
    const float* ln2_b = (const float*)d_in[14];
    const float* w_qv = (const float*)d_in[15];
    const float* b_qv = (const float*)d_in[16];
    const float* w_id = (const float*)d_in[17];
    const float* b_id = (const float*)d_in[18];
    const float* lt_wo = (const float*)d_in[19];
    const float* lt_bo = (const float*)d_in[20];
    const float* st_wo = (const float*)d_in[21];
    const float* st_bo = (const float*)d_in[22];
    const float* ln3_g = (const float*)d_in[23];
    const float* ln3_b = (const float*)d_in[24];
    const float* w1 = (const float*)d_in[25];
    const float* b1 = (const float*)d_in[26];
    const float* gn_g = (const float*)d_in[27];
    const float* gn_b = (const float*)d_in[28];
    const float* dw_k = (const float*)d_in[29];
    const float* w2 = (const float*)d_in[30];
    const float* b2 = (const float*)d_in[31];
    float* out = (float*)d_out;

    float *tln, *qkin, *q, *k, *v, *att, *tgt1, *q2, *v2, *idkv, *gK, *gV, *st, *tmp, *tgt2, *x1, *x2, *gn;
    cudaGetSymbolAddress((void**)&tln, g_tln);
    cudaGetSymbolAddress((void**)&qkin, g_qkin);
    cudaGetSymbolAddress((void**)&q, g_q);
    cudaGetSymbolAddress((void**)&k, g_k);
    cudaGetSymbolAddress((void**)&v, g_v);
    cudaGetSymbolAddress((void**)&att, g_att);
    cudaGetSymbolAddress((void**)&tgt1, g_tgt1);
    cudaGetSymbolAddress((void**)&q2, g_q2);
    cudaGetSymbolAddress((void**)&v2, g_v2);
    cudaGetSymbolAddress((void**)&idkv, g_idkv);
    cudaGetSymbolAddress((void**)&gK, g_gK);
    cudaGetSymbolAddress((void**)&gV, g_gV);
    cudaGetSymbolAddress((void**)&st, g_st);
    cudaGetSymbolAddress((void**)&tmp, g_tmp);
    cudaGetSymbolAddress((void**)&tgt2, g_tgt2);
    cudaGetSymbolAddress((void**)&x1, g_x1);
    cudaGetSymbolAddress((void**)&x2, g_x2);
    cudaGetSymbolAddress((void**)&gn, g_gn);

    // ---- self-attention block ----
    ln_kernel<<<LQ, 256>>>(tgt, ln1_g, ln1_b, tln, self_pos, qkin);
    launch_gemm(qkin, sa_wq, sa_bq, nullptr, q, LQ, CD, CD);
    launch_gemm(qkin, sa_wk, sa_bk, nullptr, k, LQ, CD, CD);
    launch_gemm(tln, sa_wv, sa_bv, nullptr, v, LQ, CD, CD);
    attn_kernel<<<dim3(LQ, NH), 256>>>(q, k, v, att, LQ);
    launch_gemm(att, sa_wo, sa_bo, tgt, tgt1, LQ, CD, CD);   // tgt1 = tgt + SA(tgt)

    // ---- long/short-term block ----
    ln_kernel<<<LQ, 256>>>(tgt1, ln2_g, ln2_b, tln, nullptr, nullptr);
    launch_gemm(tln, w_qv, b_qv, nullptr, q2, LQ, CD, CD);                 // curr_Q
    launch_gemm(tln, w_qv + CD * CD, b_qv + CD, nullptr, v2, LQ, CD, CD);  // curr_V
    launch_gemm(curr_id_emb, w_id, b_id, nullptr, idkv, LQ, CD + NH, CD);
    make_global_kv<<<(LQ * CD + 255) / 256, 256>>>(q2, v2, idkv, gK, gV);
    attn_kernel<<<dim3(LQ, NH), 256>>>(q2, gK, gV, att, LQ);
    launch_gemm(att, lt_wo, lt_bo, tgt1, tmp, LQ, CD, CD);   // tmp = tgt1 + LT
    local_attn_kernel<<<dim3(LQ, NH), 256>>>(q2, gK, gV, st);
    launch_gemm(st, st_wo, st_bo, tmp, tgt2, LQ, CD, CD);    // tgt2 = tgt1 + LT + ST

    // ---- FFN block ----
    ln_kernel<<<LQ, 256>>>(tgt2, ln3_g, ln3_b, tln, nullptr, nullptr);
    launch_gemm(tln, w1, b1, nullptr, x1, LQ, DFF, CD);
    gn_stats<<<32, 256>>>(x1, gn);
    gn_apply_gelu<<<(LQ * DFF + 255) / 256, 256>>>(x1, gn, gn_g, gn_b, x2);
    dwconv_kernel<<<LQ, 256>>>(x2, dw_k, x1);
    launch_gemm(x1, w2, b2, tgt2, out, LQ, CD, DFF);         // out = tgt2 + FFN
}

// round 2
// speedup vs baseline: 5.4145x; 5.4145x over previous
#include <cuda_runtime.h>
#include <math.h>

#define LQ 1600
#define CD 256
#define NH 8
#define HD 32
#define DFF 1024
#define H2D 40
#define W2D 40
#define WS 15
#define WSQ 225
#define PADR 7
#define SCALE 0.17677669529663687f  // 1/sqrt(32)

#define BQ 64
#define BK 64

// ---------------- scratch (device globals; no allocation) ----------------
__device__ float g_tln[LQ * CD];
__device__ float g_qkin[LQ * CD];
__device__ float g_q[LQ * CD];
__device__ float g_k[LQ * CD];
__device__ float g_v[LQ * CD];
__device__ float g_att[LQ * CD];
__device__ float g_tgt1[LQ * CD];
__device__ float g_q2[LQ * CD];      // curr_Q
__device__ float g_v2[LQ * CD];      // curr_V
__device__ float g_idkv[LQ * 264];
__device__ float g_gK[LQ * CD];
__device__ float g_gV[LQ * CD];
__device__ float g_st[LQ * CD];
__device__ float g_tmp[LQ * CD];
__device__ float g_tgt2[LQ * CD];
__device__ float g_x1[LQ * DFF];
__device__ float g_x2[LQ * DFF];
__device__ float g_gn[32 * 2];

// ---------------- reductions ----------------
__device__ __forceinline__ float block_reduce(float v, float* red, bool is_max) {
    int lane = threadIdx.x & 31, wid = threadIdx.x >> 5;
#pragma unroll
    for (int o = 16; o; o >>= 1) {
        float u = __shfl_xor_sync(0xffffffffu, v, o);
        v = is_max ? fmaxf(v, u) : v + u;
    }
    if (!lane) red[wid] = v;
    __syncthreads();
    int nw = (blockDim.x + 31) >> 5;
    v = (lane < nw) ? red[lane] : (is_max ? -1e30f : 0.0f);
    if (!wid) {
#pragma unroll
        for (int o = 16; o; o >>= 1) {
            float u = __shfl_xor_sync(0xffffffffu, v, o);
            v = is_max ? fmaxf(v, u) : v + u;
        }
        if (!lane) red[0] = v;
    }
    __syncthreads();
    v = red[0];
    __syncthreads();
    return v;
}

// ---------------- LayerNorm (one block per row, 256 threads) ----------------
__global__ void ln_kernel(const float* __restrict__ in, const float* __restrict__ g,
                          const float* __restrict__ b, float* __restrict__ out,
                          const float* __restrict__ pos, float* __restrict__ out2) {
    __shared__ float red[32];
    int l = blockIdx.x, c = threadIdx.x;
    float x = in[l * CD + c];
    float m = block_reduce(x, red, false) * (1.0f / CD);
    float d = x - m;
    float var = block_reduce(d * d, red, false) * (1.0f / CD);
    float y = d * rsqrtf(var + 1e-5f) * g[c] + b[c];
    out[l * CD + c] = y;
    if (out2) out2[l * CD + c] = y + pos[l * CD + c];
}

// ---------------- GEMM: C[m,n] = sum_k A[m,k]*W[n,k] + bias[n] (+res) ----------------
// BM=BN=64, BK=16, 256 threads, 4x4 micro-tile (strided rows, conflict-free),
// register double-buffered global prefetch. Requires M % 64 == 0, K % 16 == 0.
__global__ __launch_bounds__(256) void gemm_kernel(
        const float* __restrict__ A, const float* __restrict__ W,
        const float* __restrict__ bias, const float* __restrict__ res,
        float* __restrict__ C, int M, int N, int K) {
    __shared__ float As[64][17];
    __shared__ float Ws[64][17];
    int tid = threadIdx.x;
    int bm = blockIdx.y * 64, bn = blockIdx.x * 64;
    int tr = tid >> 4, tc = tid & 15;
    int lr = tid >> 2, lc4 = (tid & 3) * 4;
    float acc[4][4] = {};

    int gm = bm + lr;
    int gn = bn + lr;
    const float* Ap = A + (size_t)gm * K + lc4;
    const float* Wp = W + (size_t)gn * K + lc4;
    bool wok = (gn < N);
    float4 pa = *reinterpret_cast<const float4*>(Ap);
    float4 pw = wok ? *reinterpret_cast<const float4*>(Wp)
                    : make_float4(0.f, 0.f, 0.f, 0.f);

    for (int k0 = 0; k0 < K; k0 += 16) {
        As[lr][lc4 + 0] = pa.x; As[lr][lc4 + 1] = pa.y;
        As[lr][lc4 + 2] = pa.z; As[lr][lc4 + 3] = pa.w;
        Ws[lr][lc4 + 0] = pw.x; Ws[lr][lc4 + 1] = pw.y;
        Ws[lr][lc4 + 2] = pw.z; Ws[lr][lc4 + 3] = pw.w;
        __syncthreads();
        if (k0 + 16 < K) {
            pa = *reinterpret_cast<const float4*>(Ap + k0 + 16);
            pw = wok ? *reinterpret_cast<const float4*>(Wp + k0 + 16)
                     : make_float4(0.f, 0.f, 0.f, 0.f);
        }
#pragma unroll
        for (int kk = 0; kk < 16; kk++) {
            float a[4], w[4];
#pragma unroll
            for (int i = 0; i < 4; i++) a[i] = As[tr + 16 * i][kk];
#pragma unroll
            for (int j = 0; j < 4; j++) w[j] = Ws[tc + 16 * j][kk];
#pragma unroll
            for (int i = 0; i < 4; i++)
#pragma unroll
                for (int j = 0; j < 4; j++) acc[i][j] = fmaf(a[i], w[j], acc[i][j]);
        }
        __syncthreads();
    }
#pragma unroll
    for (int i = 0; i < 4; i++) {
        int m = bm + tr + 16 * i;
#pragma unroll
        for (int j = 0; j < 4; j++) {
            int n = bn + tc + 16 * j;
            if (n >= N) continue;
            float v = acc[i][j] + bias[n];
            if (res) v += res[(size_t)m * N + n];
            C[(size_t)m * N + n] = v;
        }
    }
}

// ---------------- flash attention: block = (64 queries, 1 head) ----------------
__global__ __launch_bounds__(256) void flash_attn(
        const float* __restrict__ Q, const float* __restrict__ K,
        const float* __restrict__ V, float* __restrict__ O) {
    __shared__ float Qs[BQ][33];
    __shared__ float Ks[BK][33];
    __shared__ float Vs[BK][33];
    __shared__ float Ps[BQ][BK + 1];
    int h = blockIdx.y;
    int q0 = blockIdx.x * BQ;
    int tid = threadIdx.x;
    int tr = tid >> 4, tc = tid & 15;
    int lrow = tid >> 2, lcol = (tid & 3) * 8;

    // load + scale Q tile (coalesced float4 x2 per thread)
    {
        const float* qp = Q + (size_t)(q0 + lrow) * CD + h * HD + lcol;
        float4 v0 = *reinterpret_cast<const float4*>(qp);
        float4 v1 = *reinterpret_cast<const float4*>(qp + 4);
        Qs[lrow][lcol + 0] = v0.x * SCALE; Qs[lrow][lcol + 1] = v0.y * SCALE;
        Qs[lrow][lcol + 2] = v0.z * SCALE; Qs[lrow][lcol + 3] = v0.w * SCALE;
        Qs[lrow][lcol + 4] = v1.x * SCALE; Qs[lrow][lcol + 5] = v1.y * SCALE;
        Qs[lrow][lcol + 6] = v1.z * SCALE; Qs[lrow][lcol + 7] = v1.w * SCALE;
    }

    float m[4], l[4], acc[4][2];
#pragma unroll
    for (int i = 0; i < 4; i++) {
        m[i] = -1e30f; l[i] = 0.f; acc[i][0] = 0.f; acc[i][1] = 0.f;
    }

    for (int kt = 0; kt < LQ; kt += BK) {
        // prefetch K/V tile to regs
        const float* kp = K + (size_t)(kt + lrow) * CD + h * HD + lcol;
        const float* vp = V + (size_t)(kt + lrow) * CD + h * HD + lcol;
        float4 k0v = *reinterpret_cast<const float4*>(kp);
        float4 k1v = *reinterpret_cast<const float4*>(kp + 4);
        float4 v0v = *reinterpret_cast<const float4*>(vp);
        float4 v1v = *reinterpret_cast<const float4*>(vp + 4);
        __syncthreads();  // previous tile's PV done reading Vs/Ps
        Ks[lrow][lcol + 0] = k0v.x; Ks[lrow][lcol + 1] = k0v.y;
        Ks[lrow][lcol + 2] = k0v.z; Ks[lrow][lcol + 3] = k0v.w;
        Ks[lrow][lcol + 4] = k1v.x; Ks[lrow][lcol + 5] = k1v.y;
        Ks[lrow][lcol + 6] = k1v.z; Ks[lrow][lcol + 7] = k1v.w;
        Vs[lrow][lcol + 0] = v0v.x; Vs[lrow][lcol + 1] = v0v.y;
        Vs[lrow][lcol + 2] = v0v.z; Vs[lrow][lcol + 3] = v0v.w;
        Vs[lrow][lcol + 4] = v1v.x; Vs[lrow][lcol + 5] = v1v.y;
        Vs[lrow][lcol + 6] = v1v.z; Vs[lrow][lcol + 7] = v1v.w;
        __syncthreads();

        // S[i][j] : q = tr + 16i, k = tc + 16j
        float S[4][4] = {};
#pragma unroll
        for (int d = 0; d < 32; d++) {
            float a[4], b[4];
#pragma unroll
            for (int i = 0; i < 4; i++) a[i] = Qs[tr + 16 * i][d];
#pragma unroll
            for (int j = 0; j < 4; j++) b[j] = Ks[tc + 16 * j][d];
#pragma unroll
            for (int i = 0; i < 4; i++)
#pragma unroll
                for (int j = 0; j < 4; j++) S[i][j] = fmaf(a[i], b[j], S[i][j]);
        }

        // online softmax per query row (row = 16 lanes sharing tr, width-16 shuffles)
#pragma unroll
        for (int i = 0; i < 4; i++) {
            float tm = fmaxf(fmaxf(S[i][0], S[i][1]), fmaxf(S[i][2], S[i][3]));
#pragma unroll
            for (int o = 8; o; o >>= 1)
                tm = fmaxf(tm, __shfl_xor_sync(0xffffffffu, tm, o, 16));
            float nm = fmaxf(m[i], tm);
            float alpha = __expf(m[i] - nm);
            m[i] = nm;
            float p0 = __expf(S[i][0] - nm), p1 = __expf(S[i][1] - nm);
            float p2 = __expf(S[i][2] - nm), p3 = __expf(S[i][3] - nm);
            float ts = (p0 + p1) + (p2 + p3);
#pragma unroll
            for (int o = 8; o; o >>= 1)
                ts += __shfl_xor_sync(0xffffffffu, ts, o, 16);
            l[i] = l[i] * alpha + ts;
            acc[i][0] *= alpha; acc[i][1] *= alpha;
            int qr = tr + 16 * i;
            Ps[qr][tc] = p0; Ps[qr][tc + 16] = p1;
            Ps[qr][tc + 32] = p2; Ps[qr][tc + 48] = p3;
        }
        __syncthreads();

        // PV: acc[i][j] += sum_k P[q][k] * V[k][d], d = tc*2 + j
        int d0 = tc * 2;
#pragma unroll 16
        for (int k = 0; k < BK; k++) {
            float v0 = Vs[k][d0], v1 = Vs[k][d0 + 1];
            float p[4];
#pragma unroll
            for (int i = 0; i < 4; i++) p[i] = Ps[tr + 16 * i][k];
#pragma unroll
            for (int i = 0; i < 4; i++) {
                acc[i][0] = fmaf(p[i], v0, acc[i][0]);
                acc[i][1] = fmaf(p[i], v1, acc[i][1]);
            }
        }
    }

    // epilogue
#pragma unroll
    for (int i = 0; i < 4; i++) {
        float inv = 1.0f / l[i];
        int q = q0 + tr + 16 * i;
        float* op = O + (size_t)q * CD + h * HD + tc * 2;
        op[0] = acc[i][0] * inv;
        op[1] = acc[i][1] * inv;
    }
}

// ---------------- local attention (15x15 window) ----------------
__global__ void local_attn_kernel(const float* __restrict__ Q, const float* __restrict__ K,
                                  const float* __restrict__ V, float* __restrict__ O) {
    __shared__ float qs[HD];
    __shared__ float lg[WSQ];
    __shared__ float red[32];
    __shared__ float accs[8][33];
    int n = blockIdx.x, h = blockIdx.y, tid = threadIdx.x;
    int y = n / W2D, x = n % W2D;
    if (tid < HD) qs[tid] = Q[n * CD + h * HD + tid] * SCALE;
    __syncthreads();
    float lmax = -1e30f;
    if (tid < WSQ) {
        int dy = tid / WS - PADR, dx = tid % WS - PADR;
        int ny = y + dy, nx = x + dx;
        float d;
        if (ny >= 0 && ny < H2D && nx >= 0 && nx < W2D) {
            const float* kp = K + (size_t)(ny * W2D + nx) * CD + h * HD;
            d = 0.f;
#pragma unroll
            for (int j = 0; j < HD; j++) d = fmaf(qs[j], kp[j], d);
        } else {
            d = -1e9f;
        }
        lg[tid] = d;
        lmax = d;
    }
    float gmax = block_reduce(lmax, red, true);
    float lsum = 0.f;
    if (tid < WSQ) {
        float e = __expf(lg[tid] - gmax);
        lg[tid] = e;
        lsum = e;
    }
    float gsum = block_reduce(lsum, red, false);
    __syncthreads();
    int grp = tid >> 5, lane = tid & 31;
    float acc = 0.f;
    for (int w = grp; w < WSQ; w += 8) {
        int dy = w / WS - PADR, dx = w % WS - PADR;
        int ny = y + dy, nx = x + dx;
        if (ny < 0 || ny >= H2D || nx < 0 || nx >= W2D) continue;
        acc = fmaf(lg[w], V[(size_t)(ny * W2D + nx) * CD + h * HD + lane], acc);
    }
    accs[grp][lane] = acc;
    __syncthreads();
    if (tid < HD) {
        float s = 0.f;
#pragma unroll
        for (int g2 = 0; g2 < 8; g2++) s += accs[g2][tid];
        O[n * CD + h * HD + tid] = s / gsum;
    }
}

// ---------------- global K/V construction ----------------
__global__ void make_global_kv(const float* __restrict__ q, const float* __restrict__ v,
                               const float* __restrict__ idkv, float* __restrict__ gK,
                               float* __restrict__ gV) {
    int i = blockIdx.x * blockDim.x + threadIdx.x;
    if (i >= LQ * CD) return;
    int l = i >> 8, c = i & 255, h = c >> 5;
    float ik = idkv[l * 264 + h];
    gK[i] = q[i] * (1.0f + tanhf(ik));
    gV[i] = v[i] + idkv[l * 264 + 8 + c];
}

// ---------------- GroupNorm stats (32 blocks) ----------------
__global__ void gn_stats(const float* __restrict__ x, float* __restrict__ stats) {
    __shared__ float red[32];
    int g = blockIdx.x;
    float s = 0.f, ss = 0.f;
    for (int i = threadIdx.x; i < LQ * 32; i += blockDim.x) {
        int l = i >> 5, c = (g << 5) + (i & 31);
        float v = x[(size_t)l * DFF + c];
        s += v;
        ss = fmaf(v, v, ss);
    }
    s = block_reduce(s, red, false);
    ss = block_reduce(ss, red, false);
    if (!threadIdx.x) {
        const float inv = 1.0f / (LQ * 32.0f);
        float m = s * inv;
        float var = ss * inv - m * m;
        stats[g * 2] = m;
        stats[g * 2 + 1] = rsqrtf(var + 1e-5f);
    }
}

// ---------------- GN apply + affine + exact GELU ----------------
__global__ void gn_apply_gelu(const float* __restrict__ x, const float* __restrict__ stats,
                              const float* __restrict__ gg, const float* __restrict__ gb,
                              float* __restrict__ y) {
    int i = blockIdx.x * blockDim.x + threadIdx.x;
    if (i >= LQ * DFF) return;
    int c = i & (DFF - 1);
    int grp = c >> 5;
    float m = stats[grp * 2], r = stats[grp * 2 + 1];
    float v = (x[i] - m) * r * gg[c] + gb[c];
    y[i] = 0.5f * v * (1.0f + erff(v * 0.70710678118654752f));
}

// ---------------- depthwise 5x5 conv, pad 2 ----------------
__global__ void dwconv_kernel(const float* __restrict__ x, const float* __restrict__ k,
                              float* __restrict__ y) {
    int l = blockIdx.x;
    int yy = l / W2D, xx = l % W2D;
    for (int c = threadIdx.x; c < DFF; c += blockDim.x) {
        float acc = 0.f;
#pragma unroll
        for (int i = 0; i < 5; i++) {
            int ny = yy + i - 2;
            if (ny < 0 || ny >= H2D) continue;
#pragma unroll
            for (int j = 0; j < 5; j++) {
                int nx = xx + j - 2;
                if (nx < 0 || nx >= W2D) continue;
                acc = fmaf(x[(size_t)(ny * W2D + nx) * DFF + c], k[c * 25 + i * 5 + j], acc);
            }
        }
        y[(size_t)l * DFF + c] = acc;
    }
}

// ---------------- host ----------------
static void launch_gemm(const float* A, const float* W, const float* bias, const float* res,
                        float* C, int M, int N, int K) {
    dim3 grid((N + 63) / 64, (M + 63) / 64);
    gemm_kernel<<<grid, 256>>>(A, W, bias, res, C, M, N, K);
}

extern "C" void kernel_launch(void* const* d_in, const int* in_sizes, int n_in,
                              void* d_out, int out_size) {
    const float* tgt = (const float*)d_in[0];
    const float* curr_id_emb = (const float*)d_in[1];
    const float* self_pos = (const float*)d_in[2];
    const float* ln1_g = (const float*)d_in[3];
    const float* ln1_b = (const float*)d_in[4];
    const float* sa_wq = (const float*)d_in[5];
    const float* sa_bq = (const float*)d_in[6];
    const float* sa_wk = (const float*)d_in[7];
    const float* sa_bk = (const float*)d_in[8];
    const float* sa_wv = (const float*)d_in[9];
    const float* sa_bv = (const float*)d_in[10];
    const float* sa_wo = (const float*)d_in[11];
    const float* sa_bo = (const float*)d_in[12];
    const float* ln2_g = (const float*)d_in[13];
    const float* ln2_b = (const float*)d_in[14];
    const float* w_qv = (const float*)d_in[15];
    const float* b_qv = (const float*)d_in[16];
    const float* w_id = (const float*)d_in[17];
    const float* b_id = (const float*)d_in[18];
    const float* lt_wo = (const float*)d_in[19];
    const float* lt_bo = (const float*)d_in[20];
    const float* st_wo = (const float*)d_in[21];
    const float* st_bo = (const float*)d_in[22];
    const float* ln3_g = (const float*)d_in[23];
    const float* ln3_b = (const float*)d_in[24];
    const float* w1 = (const float*)d_in[25];
    const float* b1 = (const float*)d_in[26];
    const float* gn_g = (const float*)d_in[27];
    const float* gn_b = (const float*)d_in[28];
    const float* dw_k = (const float*)d_in[29];
    const float* w2 = (const float*)d_in[30];
    const float* b2 = (const float*)d_in[31];
    float* out = (float*)d_out;

    float *tln, *qkin, *q, *k, *v, *att, *tgt1, *q2, *v2, *idkv, *gK, *gV, *st, *tmp, *tgt2, *x1, *x2, *gn;
    cudaGetSymbolAddress((void**)&tln, g_tln);
    cudaGetSymbolAddress((void**)&qkin, g_qkin);
    cudaGetSymbolAddress((void**)&q, g_q);
    cudaGetSymbolAddress((void**)&k, g_k);
    cudaGetSymbolAddress((void**)&v, g_v);
    cudaGetSymbolAddress((void**)&att, g_att);
    cudaGetSymbolAddress((void**)&tgt1, g_tgt1);
    cudaGetSymbolAddress((void**)&q2, g_q2);
    cudaGetSymbolAddress((void**)&v2, g_v2);
    cudaGetSymbolAddress((void**)&idkv, g_idkv);
    cudaGetSymbolAddress((void**)&gK, g_gK);
    cudaGetSymbolAddress((void**)&gV, g_gV);
    cudaGetSymbolAddress((void**)&st, g_st);
    cudaGetSymbolAddress((void**)&tmp, g_tmp);
    cudaGetSymbolAddress((void**)&tgt2, g_tgt2);
    cudaGetSymbolAddress((void**)&x1, g_x1);
    cudaGetSymbolAddress((void**)&x2, g_x2);
    cudaGetSymbolAddress((void**)&gn, g_gn);

    // ---- self-attention block ----
    ln_kernel<<<LQ, 256>>>(tgt, ln1_g, ln1_b, tln, self_pos, qkin);
    launch_gemm(qkin, sa_wq, sa_bq, nullptr, q, LQ, CD, CD);
    launch_gemm(qkin, sa_wk, sa_bk, nullptr, k, LQ, CD, CD);
    launch_gemm(tln, sa_wv, sa_bv, nullptr, v, LQ, CD, CD);
    flash_attn<<<dim3(LQ / BQ, NH), 256>>>(q, k, v, att);
    launch_gemm(att, sa_wo, sa_bo, tgt, tgt1, LQ, CD, CD);   // tgt1 = tgt + SA(tgt)

    // ---- long/short-term block ----
    ln_kernel<<<LQ, 256>>>(tgt1, ln2_g, ln2_b, tln, nullptr, nullptr);
    launch_gemm(tln, w_qv, b_qv, nullptr, q2, LQ, CD, CD);                 // curr_Q
    launch_gemm(tln, w_qv + CD * CD, b_qv + CD, nullptr, v2, LQ, CD, CD);  // curr_V
    launch_gemm(curr_id_emb, w_id, b_id, nullptr, idkv, LQ, CD + NH, CD);
    make_global_kv<<<(LQ * CD + 255) / 256, 256>>>(q2, v2, idkv, gK, gV);
    flash_attn<<<dim3(LQ / BQ, NH), 256>>>(q2, gK, gV, att);
    launch_gemm(att, lt_wo, lt_bo, tgt1, tmp, LQ, CD, CD);   // tmp = tgt1 + LT
    local_attn_kernel<<<dim3(LQ, NH), 256>>>(q2, gK, gV, st);
    launch_gemm(st, st_wo, st_bo, tmp, tgt2, LQ, CD, CD);    // tgt2 = tgt1 + LT + ST

    // ---- FFN block ----
    ln_kernel<<<LQ, 256>>>(tgt2, ln3_g, ln3_b, tln, nullptr, nullptr);
    launch_gemm(tln, w1, b1, nullptr, x1, LQ, DFF, CD);
    gn_stats<<<32, 256>>>(x1, gn);
    gn_apply_gelu<<<(LQ * DFF + 255) / 256, 256>>>(x1, gn, gn_g, gn_b, x2);
    dwconv_kernel<<<LQ, 256>>>(x2, dw_k, x1);
    launch_gemm(x1, w2, b2, tgt2, out, LQ, CD, DFF);         // out = tgt2 + FFN
}

// round 3
// speedup vs baseline: 6.6539x; 1.2289x over previous
#include <cuda_runtime.h>
#include <math.h>

#define LQ 1600
#define CD 256
#define NH 8
#define HD 32
#define DFF 1024
#define H2D 40
#define W2D 40
#define WS 15
#define WSQ 225
#define PADR 7
#define SCALE 0.17677669529663687f  // 1/sqrt(32)

#define BQ 64
#define BK 64

// ---------------- scratch (device globals; no allocation) ----------------
__device__ float g_tln[LQ * CD];
__device__ float g_qkin[LQ * CD];
__device__ float g_q[LQ * CD];
__device__ float g_k[LQ * CD];
__device__ float g_v[LQ * CD];
__device__ float g_att[LQ * CD];
__device__ float g_tgt1[LQ * CD];
__device__ float g_qv[LQ * 512];     // [curr_Q | curr_V] fused
__device__ float g_idkv[LQ * 264];
__device__ float g_gK[LQ * CD];
__device__ float g_gV[LQ * CD];
__device__ float g_st[LQ * CD];
__device__ float g_tmp[LQ * CD];
__device__ float g_tgt2[LQ * CD];
__device__ float g_x1[LQ * DFF];
__device__ float g_x2[LQ * DFF];
__device__ float g_gn[32 * 2];

// ---------------- reductions ----------------
__device__ __forceinline__ float block_reduce(float v, float* red, bool is_max) {
    int lane = threadIdx.x & 31, wid = threadIdx.x >> 5;
#pragma unroll
    for (int o = 16; o; o >>= 1) {
        float u = __shfl_xor_sync(0xffffffffu, v, o);
        v = is_max ? fmaxf(v, u) : v + u;
    }
    if (!lane) red[wid] = v;
    __syncthreads();
    int nw = (blockDim.x + 31) >> 5;
    v = (lane < nw) ? red[lane] : (is_max ? -1e30f : 0.0f);
    if (!wid) {
#pragma unroll
        for (int o = 16; o; o >>= 1) {
            float u = __shfl_xor_sync(0xffffffffu, v, o);
            v = is_max ? fmaxf(v, u) : v + u;
        }
        if (!lane) red[0] = v;
    }
    __syncthreads();
    v = red[0];
    __syncthreads();
    return v;
}

// ---------------- LayerNorm (one block per row, 256 threads) ----------------
__global__ void ln_kernel(const float* __restrict__ in, const float* __restrict__ g,
                          const float* __restrict__ b, float* __restrict__ out,
                          const float* __restrict__ pos, float* __restrict__ out2) {
    __shared__ float red[32];
    int l = blockIdx.x, c = threadIdx.x;
    float x = in[l * CD + c];
    float m = block_reduce(x, red, false) * (1.0f / CD);
    float d = x - m;
    float var = block_reduce(d * d, red, false) * (1.0f / CD);
    float y = d * rsqrtf(var + 1e-5f) * g[c] + b[c];
    out[l * CD + c] = y;
    if (out2) out2[l * CD + c] = y + pos[l * CD + c];
}

// ---------------- GEMM: C[m,n] = sum_k A[m,k]*W[n,k] + bias[n] (+res) ----------------
// BM=BN=64, BK=16, 256 threads, 4x4 contiguous micro-tile.
// Smem stored k-major so micro-tile reads are 2x LDS.128 (A op is a 16-way broadcast).
// Requires M % 64 == 0, K % 16 == 0. N arbitrary.
__global__ __launch_bounds__(256) void gemm_kernel(
        const float* __restrict__ A, const float* __restrict__ W,
        const float* __restrict__ bias, const float* __restrict__ res,
        float* __restrict__ C, int M, int N, int K) {
    __shared__ float As[16][68];   // [kk][row], row-length 272B (16B aligned)
    __shared__ float Ws[16][68];
    int tid = threadIdx.x;
    int bm = blockIdx.y * 64, bn = blockIdx.x * 64;
    int tr = tid >> 4, tc = tid & 15;
    int lr = tid >> 2, lc4 = (tid & 3) * 4;
    float acc[4][4] = {};

    const float* Ap = A + (size_t)(bm + lr) * K + lc4;
    bool wok = (bn + lr) < N;
    const float* Wp = W + (size_t)(wok ? bn + lr : 0) * K + lc4;
    float4 pa = *reinterpret_cast<const float4*>(Ap);
    float4 pw = wok ? *reinterpret_cast<const float4*>(Wp)
                    : make_float4(0.f, 0.f, 0.f, 0.f);

    for (int k0 = 0; k0 < K; k0 += 16) {
        As[lc4 + 0][lr] = pa.x; As[lc4 + 1][lr] = pa.y;
        As[lc4 + 2][lr] = pa.z; As[lc4 + 3][lr] = pa.w;
        Ws[lc4 + 0][lr] = pw.x; Ws[lc4 + 1][lr] = pw.y;
        Ws[lc4 + 2][lr] = pw.z; Ws[lc4 + 3][lr] = pw.w;
        __syncthreads();
        if (k0 + 16 < K) {
            pa = *reinterpret_cast<const float4*>(Ap + k0 + 16);
            pw = wok ? *reinterpret_cast<const float4*>(Wp + k0 + 16)
                     : make_float4(0.f, 0.f, 0.f, 0.f);
        }
#pragma unroll
        for (int kk = 0; kk < 16; kk++) {
            float4 a = *reinterpret_cast<const float4*>(&As[kk][tr * 4]);
            float4 w = *reinterpret_cast<const float4*>(&Ws[kk][tc * 4]);
            float av[4] = {a.x, a.y, a.z, a.w};
            float wv[4] = {w.x, w.y, w.z, w.w};
#pragma unroll
            for (int i = 0; i < 4; i++)
#pragma unroll
                for (int j = 0; j < 4; j++) acc[i][j] = fmaf(av[i], wv[j], acc[i][j]);
        }
        __syncthreads();
    }

    if (bn + 64 <= N) {  // full tile: vector epilogue
        float4 bv = *reinterpret_cast<const float4*>(bias + bn + tc * 4);
#pragma unroll
        for (int i = 0; i < 4; i++) {
            int m = bm + tr * 4 + i;
            size_t off = (size_t)m * N + bn + tc * 4;
            float4 o;
            o.x = acc[i][0] + bv.x; o.y = acc[i][1] + bv.y;
            o.z = acc[i][2] + bv.z; o.w = acc[i][3] + bv.w;
            if (res) {
                float4 r = *reinterpret_cast<const float4*>(res + off);
                o.x += r.x; o.y += r.y; o.z += r.z; o.w += r.w;
            }
            *reinterpret_cast<float4*>(C + off) = o;
        }
    } else {
#pragma unroll
        for (int i = 0; i < 4; i++) {
            int m = bm + tr * 4 + i;
#pragma unroll
            for (int j = 0; j < 4; j++) {
                int n = bn + tc * 4 + j;
                if (n >= N) continue;
                float v = acc[i][j] + bias[n];
                if (res) v += res[(size_t)m * N + n];
                C[(size_t)m * N + n] = v;
            }
        }
    }
}

// ---------------- flash attention: block = (64 queries, 1 head) ----------------
__global__ __launch_bounds__(256) void flash_attn(
        const float* __restrict__ Q, int ldq,
        const float* __restrict__ K, int ldk,
        const float* __restrict__ V, int ldv,
        float* __restrict__ O) {
    __shared__ float Qs[BQ][33];
    __shared__ float Ks[BK][33];
    __shared__ float Vs[BK][33];
    __shared__ float Ps[BQ][BK + 1];
    int h = blockIdx.y;
    int q0 = blockIdx.x * BQ;
    int tid = threadIdx.x;
    int tr = tid >> 4, tc = tid & 15;
    int lrow = tid >> 2, lcol = (tid & 3) * 8;

    {
        const float* qp = Q + (size_t)(q0 + lrow) * ldq + h * HD + lcol;
        float4 v0 = *reinterpret_cast<const float4*>(qp);
        float4 v1 = *reinterpret_cast<const float4*>(qp + 4);
        Qs[lrow][lcol + 0] = v0.x * SCALE; Qs[lrow][lcol + 1] = v0.y * SCALE;
        Qs[lrow][lcol + 2] = v0.z * SCALE; Qs[lrow][lcol + 3] = v0.w * SCALE;
        Qs[lrow][lcol + 4] = v1.x * SCALE; Qs[lrow][lcol + 5] = v1.y * SCALE;
        Qs[lrow][lcol + 6] = v1.z * SCALE; Qs[lrow][lcol + 7] = v1.w * SCALE;
    }

    float m[4], l[4], acc[4][2];
#pragma unroll
    for (int i = 0; i < 4; i++) {
        m[i] = -1e30f; l[i] = 0.f; acc[i][0] = 0.f; acc[i][1] = 0.f;
    }

    for (int kt = 0; kt < LQ; kt += BK) {
        const float* kp = K + (size_t)(kt + lrow) * ldk + h * HD + lcol;
        const float* vp = V + (size_t)(kt + lrow) * ldv + h * HD + lcol;
        float4 k0v = *reinterpret_cast<const float4*>(kp);
        float4 k1v = *reinterpret_cast<const float4*>(kp + 4);
        float4 v0v = *reinterpret_cast<const float4*>(vp);
        float4 v1v = *reinterpret_cast<const float4*>(vp + 4);
        __syncthreads();
        Ks[lrow][lcol + 0] = k0v.x; Ks[lrow][lcol + 1] = k0v.y;
        Ks[lrow][lcol + 2] = k0v.z; Ks[lrow][lcol + 3] = k0v.w;
        Ks[lrow][lcol + 4] = k1v.x; Ks[lrow][lcol + 5] = k1v.y;
        Ks[lrow][lcol + 6] = k1v.z; Ks[lrow][lcol + 7] = k1v.w;
        Vs[lrow][lcol + 0] = v0v.x; Vs[lrow][lcol + 1] = v0v.y;
        Vs[lrow][lcol + 2] = v0v.z; Vs[lrow][lcol + 3] = v0v.w;
        Vs[lrow][lcol + 4] = v1v.x; Vs[lrow][lcol + 5] = v1v.y;
        Vs[lrow][lcol + 6] = v1v.z; Vs[lrow][lcol + 7] = v1v.w;
        __syncthreads();

        float S[4][4] = {};
#pragma unroll
        for (int d = 0; d < 32; d++) {
            float a[4], b[4];
#pragma unroll
            for (int i = 0; i < 4; i++) a[i] = Qs[tr + 16 * i][d];
#pragma unroll
            for (int j = 0; j < 4; j++) b[j] = Ks[tc + 16 * j][d];
#pragma unroll
            for (int i = 0; i < 4; i++)
#pragma unroll
                for (int j = 0; j < 4; j++) S[i][j] = fmaf(a[i], b[j], S[i][j]);
        }

#pragma unroll
        for (int i = 0; i < 4; i++) {
            float tm = fmaxf(fmaxf(S[i][0], S[i][1]), fmaxf(S[i][2], S[i][3]));
#pragma unroll
            for (int o = 8; o; o >>= 1)
                tm = fmaxf(tm, __shfl_xor_sync(0xffffffffu, tm, o, 16));
            float nm = fmaxf(m[i], tm);
            float alpha = __expf(m[i] - nm);
            m[i] = nm;
            float p0 = __expf(S[i][0] - nm), p1 = __expf(S[i][1] - nm);
            float p2 = __expf(S[i][2] - nm), p3 = __expf(S[i][3] - nm);
            float ts = (p0 + p1) + (p2 + p3);
#pragma unroll
            for (int o = 8; o; o >>= 1)
                ts += __shfl_xor_sync(0xffffffffu, ts, o, 16);
            l[i] = l[i] * alpha + ts;
            acc[i][0] *= alpha; acc[i][1] *= alpha;
            int qr = tr + 16 * i;
            Ps[qr][tc] = p0; Ps[qr][tc + 16] = p1;
            Ps[qr][tc + 32] = p2; Ps[qr][tc + 48] = p3;
        }
        __syncthreads();

        int d0 = tc * 2;
#pragma unroll 16
        for (int k = 0; k < BK; k++) {
            float v0 = Vs[k][d0], v1 = Vs[k][d0 + 1];
            float p[4];
#pragma unroll
            for (int i = 0; i < 4; i++) p[i] = Ps[tr + 16 * i][k];
#pragma unroll
            for (int i = 0; i < 4; i++) {
                acc[i][0] = fmaf(p[i], v0, acc[i][0]);
                acc[i][1] = fmaf(p[i], v1, acc[i][1]);
            }
        }
    }

#pragma unroll
    for (int i = 0; i < 4; i++) {
        float inv = 1.0f / l[i];
        int q = q0 + tr + 16 * i;
        float* op = O + (size_t)q * CD + h * HD + tc * 2;
        op[0] = acc[i][0] * inv;
        op[1] = acc[i][1] * inv;
    }
}

// ---------------- local attention (15x15 window), smem-staged K/V ----------------
__global__ __launch_bounds__(256) void local_attn_kernel(
        const float* __restrict__ Q, int ldq,
        const float* __restrict__ K, const float* __restrict__ V,
        float* __restrict__ O) {
    __shared__ float win[WSQ][33];   // staged K, then reused for V (29.7KB)
    __shared__ float qs[HD];
    __shared__ float lg[WSQ];
    __shared__ float red[32];
    __shared__ float accs[8][33];
    int n = blockIdx.x, h = blockIdx.y, tid = threadIdx.x;
    int y = n / W2D, x = n % W2D;
    if (tid < HD) qs[tid] = Q[(size_t)n * ldq + h * HD + tid] * SCALE;

    // stage K window (coalesced: warp = 32 consecutive channels)
    for (int idx = tid; idx < WSQ * HD; idx += 256) {
        int w = idx >> 5, d = idx & 31;
        int ny = y + w / WS - PADR, nx = x + w % WS - PADR;
        bool ok = ((unsigned)ny < H2D) && ((unsigned)nx < W2D);
        win[w][d] = ok ? K[(size_t)(ny * W2D + nx) * CD + h * HD + d] : 0.f;
    }
    __syncthreads();

    float lmax = -1e30f;
    if (tid < WSQ) {
        int ny = y + tid / WS - PADR, nx = x + tid % WS - PADR;
        bool ok = ((unsigned)ny < H2D) && ((unsigned)nx < W2D);
        float d = 0.f;
#pragma unroll
        for (int j = 0; j < HD; j++) d = fmaf(qs[j], win[tid][j], d);
        d = ok ? d : -1e9f;
        lg[tid] = d;
        lmax = d;
    }
    float gmax = block_reduce(lmax, red, true);
    float lsum = 0.f;
    if (tid < WSQ) {
        float e = __expf(lg[tid] - gmax);  // invalid rows underflow to 0
        lg[tid] = e;
        lsum = e;
    }
    float gsum = block_reduce(lsum, red, false);
    __syncthreads();

    // stage V window into same buffer
    for (int idx = tid; idx < WSQ * HD; idx += 256) {
        int w = idx >> 5, d = idx & 31;
        int ny = y + w / WS - PADR, nx = x + w % WS - PADR;
        bool ok = ((unsigned)ny < H2D) && ((unsigned)nx < W2D);
        win[w][d] = ok ? V[(size_t)(ny * W2D + nx) * CD + h * HD + d] : 0.f;
    }
    __syncthreads();

    int grp = tid >> 5, lane = tid & 31;
    float acc = 0.f;
    for (int w = grp; w < WSQ; w += 8)
        acc = fmaf(lg[w], win[w][lane], acc);
    accs[grp][lane] = acc;
    __syncthreads();
    if (tid < HD) {
        float s = 0.f;
#pragma unroll
        for (int g2 = 0; g2 < 8; g2++) s += accs[g2][tid];
        O[(size_t)n * CD + h * HD + tid] = s / gsum;
    }
}

// ---------------- global K/V construction (reads fused QV buffer) ----------------
__global__ void make_global_kv(const float* __restrict__ qv, const float* __restrict__ idkv,
                               float* __restrict__ gK, float* __restrict__ gV) {
    int i = blockIdx.x * blockDim.x + threadIdx.x;
    if (i >= LQ * CD) return;
    int l = i >> 8, c = i & 255, h = c >> 5;
    float ik = idkv[l * 264 + h];
    gK[i] = qv[(size_t)l * 512 + c] * (1.0f + tanhf(ik));
    gV[i] = qv[(size_t)l * 512 + 256 + c] + idkv[l * 264 + 8 + c];
}

// ---------------- GroupNorm stats (32 blocks) ----------------
__global__ void gn_stats(const float* __restrict__ x, float* __restrict__ stats) {
    __shared__ float red[32];
    int g = blockIdx.x;
    float s = 0.f, ss = 0.f;
    for (int i = threadIdx.x; i < LQ * 32; i += blockDim.x) {
        int l = i >> 5, c = (g << 5) + (i & 31);
        float v = x[(size_t)l * DFF + c];
        s += v;
        ss = fmaf(v, v, ss);
    }
    s = block_reduce(s, red, false);
    ss = block_reduce(ss, red, false);
    if (!threadIdx.x) {
        const float inv = 1.0f / (LQ * 32.0f);
        float m = s * inv;
        float var = ss * inv - m * m;
        stats[g * 2] = m;
        stats[g * 2 + 1] = rsqrtf(var + 1e-5f);
    }
}

// ---------------- GN apply + affine + exact GELU ----------------
__global__ void gn_apply_gelu(const float* __restrict__ x, const float* __restrict__ stats,
                              const float* __restrict__ gg, const float* __restrict__ gb,
                              float* __restrict__ y) {
    int i = blockIdx.x * blockDim.x + threadIdx.x;
    if (i >= LQ * DFF) return;
    int c = i & (DFF - 1);
    int grp = c >> 5;
    float m = stats[grp * 2], r = stats[grp * 2 + 1];
    float v = (x[i] - m) * r * gg[c] + gb[c];
    y[i] = 0.5f * v * (1.0f + erff(v * 0.70710678118654752f));
}

// ---------------- depthwise 5x5 conv, pad 2 ----------------
__global__ void dwconv_kernel(const float* __restrict__ x, const float* __restrict__ k,
                              float* __restrict__ y) {
    int l = blockIdx.x;
    int yy = l / W2D, xx = l % W2D;
    for (int c = threadIdx.x; c < DFF; c += blockDim.x) {
        float acc = 0.f;
#pragma unroll
        for (int i = 0; i < 5; i++) {
            int ny = yy + i - 2;
            if (ny < 0 || ny >= H2D) continue;
#pragma unroll
            for (int j = 0; j < 5; j++) {
                int nx = xx + j - 2;
                if (nx < 0 || nx >= W2D) continue;
                acc = fmaf(x[(size_t)(ny * W2D + nx) * DFF + c], k[c * 25 + i * 5 + j], acc);
            }
        }
        y[(size_t)l * DFF + c] = acc;
    }
}

// ---------------- host ----------------
static void launch_gemm(const float* A, const float* W, const float* bias, const float* res,
                        float* C, int M, int N, int K) {
    dim3 grid((N + 63) / 64, (M + 63) / 64);
    gemm_kernel<<<grid, 256>>>(A, W, bias, res, C, M, N, K);
}

extern "C" void kernel_launch(void* const* d_in, const int* in_sizes, int n_in,
                              void* d_out, int out_size) {
    const float* tgt = (const float*)d_in[0];
    const float* curr_id_emb = (const float*)d_in[1];
    const float* self_pos = (const float*)d_in[2];
    const float* ln1_g = (const float*)d_in[3];
    const float* ln1_b = (const float*)d_in[4];
    const float* sa_wq = (const float*)d_in[5];
    const float* sa_bq = (const float*)d_in[6];
    const float* sa_wk = (const float*)d_in[7];
    const float* sa_bk = (const float*)d_in[8];
    const float* sa_wv = (const float*)d_in[9];
    const float* sa_bv = (const float*)d_in[10];
    const float* sa_wo = (const float*)d_in[11];
    const float* sa_bo = (const float*)d_in[12];
    const float* ln2_g = (const float*)d_in[13];
    const float* ln2_b = (const float*)d_in[14];
    const float* w_qv = (const float*)d_in[15];
    const float* b_qv = (const float*)d_in[16];
    const float* w_id = (const float*)d_in[17];
    const float* b_id = (const float*)d_in[18];
    const float* lt_wo = (const float*)d_in[19];
    const float* lt_bo = (const float*)d_in[20];
    const float* st_wo = (const float*)d_in[21];
    const float* st_bo = (const float*)d_in[22];
    const float* ln3_g = (const float*)d_in[23];
    const float* ln3_b = (const float*)d_in[24];
    const float* w1 = (const float*)d_in[25];
    const float* b1 = (const float*)d_in[26];
    const float* gn_g = (const float*)d_in[27];
    const float* gn_b = (const float*)d_in[28];
    const float* dw_k = (const float*)d_in[29];
    const float* w2 = (const float*)d_in[30];
    const float* b2 = (const float*)d_in[31];
    float* out = (float*)d_out;

    float *tln, *qkin, *q, *k, *v, *att, *tgt1, *qv, *idkv, *gK, *gV, *st, *tmp, *tgt2, *x1, *x2, *gn;
    cudaGetSymbolAddress((void**)&tln, g_tln);
    cudaGetSymbolAddress((void**)&qkin, g_qkin);
    cudaGetSymbolAddress((void**)&q, g_q);
    cudaGetSymbolAddress((void**)&k, g_k);
    cudaGetSymbolAddress((void**)&v, g_v);
    cudaGetSymbolAddress((void**)&att, g_att);
    cudaGetSymbolAddress((void**)&tgt1, g_tgt1);
    cudaGetSymbolAddress((void**)&qv, g_qv);
    cudaGetSymbolAddress((void**)&idkv, g_idkv);
    cudaGetSymbolAddress((void**)&gK, g_gK);
    cudaGetSymbolAddress((void**)&gV, g_gV);
    cudaGetSymbolAddress((void**)&st, g_st);
    cudaGetSymbolAddress((void**)&tmp, g_tmp);
    cudaGetSymbolAddress((void**)&tgt2, g_tgt2);
    cudaGetSymbolAddress((void**)&x1, g_x1);
    cudaGetSymbolAddress((void**)&x2, g_x2);
    cudaGetSymbolAddress((void**)&gn, g_gn);

    // ---- self-attention block ----
    ln_kernel<<<LQ, 256>>>(tgt, ln1_g, ln1_b, tln, self_pos, qkin);
    launch_gemm(qkin, sa_wq, sa_bq, nullptr, q, LQ, CD, CD);
    launch_gemm(qkin, sa_wk, sa_bk, nullptr, k, LQ, CD, CD);
    launch_gemm(tln, sa_wv, sa_bv, nullptr, v, LQ, CD, CD);
    flash_attn<<<dim3(LQ / BQ, NH), 256>>>(q, CD, k, CD, v, CD, att);
    launch_gemm(att, sa_wo, sa_bo, tgt, tgt1, LQ, CD, CD);   // tgt1 = tgt + SA(tgt)

    // ---- long/short-term block ----
    ln_kernel<<<LQ, 256>>>(tgt1, ln2_g, ln2_b, tln, nullptr, nullptr);
    launch_gemm(tln, w_qv, b_qv, nullptr, qv, LQ, 512, CD);          // [curr_Q|curr_V]
    launch_gemm(curr_id_emb, w_id, b_id, nullptr, idkv, LQ, CD + NH, CD);
    make_global_kv<<<(LQ * CD + 255) / 256, 256>>>(qv, idkv, gK, gV);
    flash_attn<<<dim3(LQ / BQ, NH), 256>>>(qv, 512, gK, CD, gV, CD, att);
    launch_gemm(att, lt_wo, lt_bo, tgt1, tmp, LQ, CD, CD);   // tmp = tgt1 + LT
    local_attn_kernel<<<dim3(LQ, NH), 256>>>(qv, 512, gK, gV, st);
    launch_gemm(st, st_wo, st_bo, tmp, tgt2, LQ, CD, CD);    // tgt2 = tgt1 + LT + ST

    // ---- FFN block ----
    ln_kernel<<<LQ, 256>>>(tgt2, ln3_g, ln3_b, tln, nullptr, nullptr);
    launch_gemm(tln, w1, b1, nullptr, x1, LQ, DFF, CD);
    gn_stats<<<32, 256>>>(x1, gn);
    gn_apply_gelu<<<(LQ * DFF + 255) / 256, 256>>>(x1, gn, gn_g, gn_b, x2);
    dwconv_kernel<<<LQ, 256>>>(x2, dw_k, x1);
    launch_gemm(x1, w2, b2, tgt2, out, LQ, CD, DFF);         // out = tgt2 + FFN
}

// round 4
// speedup vs baseline: 6.6594x; 1.0008x over previous
#include <cuda_runtime.h>
#include <math.h>
#include <stdint.h>

#define LQ 1600
#define CD 256
#define NH 8
#define HD 32
#define DFF 1024
#define H2D 40
#define W2D 40
#define WS 15
#define WSQ 225
#define PADR 7
#define SCALE 0.17677669529663687f  // 1/sqrt(32)

#define BQ 64
#define BK 64

// ---------------- scratch (device globals; no allocation) ----------------
__device__ float g_tln[LQ * CD];
__device__ float g_qkin[LQ * CD];
__device__ float g_q[LQ * CD];
__device__ float g_k[LQ * CD];
__device__ float g_v[LQ * CD];
__device__ float g_att[LQ * CD];
__device__ float g_tgt1[LQ * CD];
__device__ float g_qv[LQ * 512];     // [curr_Q | curr_V] fused
__device__ float g_idkv[LQ * 264];
__device__ float g_gK[LQ * CD];
__device__ float g_gV[LQ * CD];
__device__ float g_st[LQ * CD];
__device__ float g_tmp[LQ * CD];
__device__ float g_tgt2[LQ * CD];
__device__ float g_x1[LQ * DFF];
__device__ float g_x2[LQ * DFF];
__device__ float g_gn[32 * 2];

// ---------------- tf32 helpers ----------------
__device__ __forceinline__ uint32_t f2tf32(float x) {
    uint32_t r;
    asm("cvt.rna.tf32.f32 %0, %1;" : "=r"(r) : "f"(x));
    return r;
}

__device__ __forceinline__ void mma16n8k8(float* c, const uint32_t* a, const uint32_t* b) {
    asm volatile(
        "mma.sync.aligned.m16n8k8.row.col.f32.tf32.tf32.f32 "
        "{%0,%1,%2,%3}, {%4,%5,%6,%7}, {%8,%9}, {%0,%1,%2,%3};"
        : "+f"(c[0]), "+f"(c[1]), "+f"(c[2]), "+f"(c[3])
        : "r"(a[0]), "r"(a[1]), "r"(a[2]), "r"(a[3]), "r"(b[0]), "r"(b[1]));
}

// ---------------- reductions ----------------
__device__ __forceinline__ float block_reduce(float v, float* red, bool is_max) {
    int lane = threadIdx.x & 31, wid = threadIdx.x >> 5;
#pragma unroll
    for (int o = 16; o; o >>= 1) {
        float u = __shfl_xor_sync(0xffffffffu, v, o);
        v = is_max ? fmaxf(v, u) : v + u;
    }
    if (!lane) red[wid] = v;
    __syncthreads();
    int nw = (blockDim.x + 31) >> 5;
    v = (lane < nw) ? red[lane] : (is_max ? -1e30f : 0.0f);
    if (!wid) {
#pragma unroll
        for (int o = 16; o; o >>= 1) {
            float u = __shfl_xor_sync(0xffffffffu, v, o);
            v = is_max ? fmaxf(v, u) : v + u;
        }
        if (!lane) red[0] = v;
    }
    __syncthreads();
    v = red[0];
    __syncthreads();
    return v;
}

// ---------------- LayerNorm (one block per row, 256 threads) ----------------
__global__ void ln_kernel(const float* __restrict__ in, const float* __restrict__ g,
                          const float* __restrict__ b, float* __restrict__ out,
                          const float* __restrict__ pos, float* __restrict__ out2) {
    __shared__ float red[32];
    int l = blockIdx.x, c = threadIdx.x;
    float x = in[l * CD + c];
    float m = block_reduce(x, red, false) * (1.0f / CD);
    float d = x - m;
    float var = block_reduce(d * d, red, false) * (1.0f / CD);
    float y = d * rsqrtf(var + 1e-5f) * g[c] + b[c];
    out[l * CD + c] = y;
    if (out2) out2[l * CD + c] = y + pos[l * CD + c];
}

// ---------------- GEMM: C[m,n] = sum_k A[m,k]*W[n,k] + bias[n] (+res) ----------------
// 3xTF32 tensor-core GEMM. BM=BN=64, BK=16, 256 threads = 8 warps (4m x 2n).
// Warp tile 16x32 = 4 x m16n8k8 per k-step, 2 k-steps, 3 mma each (hi*hi+hi*lo+lo*hi).
// Requires M % 64 == 0, K % 16 == 0. N arbitrary.
__global__ __launch_bounds__(256) void gemm_kernel(
        const float* __restrict__ A, const float* __restrict__ W,
        const float* __restrict__ bias, const float* __restrict__ res,
        float* __restrict__ C, int M, int N, int K) {
    __shared__ uint32_t Ah[64][20], Al[64][20];
    __shared__ uint32_t Wh[64][20], Wl[64][20];
    int tid = threadIdx.x;
    int bm = blockIdx.y * 64, bn = blockIdx.x * 64;
    int lr = tid >> 2, lc4 = (tid & 3) * 4;
    int wid = tid >> 5, lane = tid & 31;
    int wm = wid & 3, wn = wid >> 2;
    int g = lane >> 2, t = lane & 3;
    float acc[4][4] = {};

    const float* Ap = A + (size_t)(bm + lr) * K + lc4;
    bool wok = (bn + lr) < N;
    const float* Wp = W + (size_t)(wok ? bn + lr : 0) * K + lc4;
    float4 pa = *reinterpret_cast<const float4*>(Ap);
    float4 pw = wok ? *reinterpret_cast<const float4*>(Wp)
                    : make_float4(0.f, 0.f, 0.f, 0.f);

    for (int k0 = 0; k0 < K; k0 += 16) {
        float av[4] = {pa.x, pa.y, pa.z, pa.w};
        float wv[4] = {pw.x, pw.y, pw.z, pw.w};
#pragma unroll
        for (int e = 0; e < 4; e++) {
            uint32_t h = f2tf32(av[e]);
            Ah[lr][lc4 + e] = h;
            Al[lr][lc4 + e] = f2tf32(av[e] - __uint_as_float(h));
            uint32_t h2 = f2tf32(wv[e]);
            Wh[lr][lc4 + e] = h2;
            Wl[lr][lc4 + e] = f2tf32(wv[e] - __uint_as_float(h2));
        }
        __syncthreads();
        if (k0 + 16 < K) {
            pa = *reinterpret_cast<const float4*>(Ap + k0 + 16);
            pw = wok ? *reinterpret_cast<const float4*>(Wp + k0 + 16)
                     : make_float4(0.f, 0.f, 0.f, 0.f);
        }
#pragma unroll
        for (int ks = 0; ks < 2; ks++) {
            int kk = ks * 8 + t;
            int mr = wm * 16 + g;
            uint32_t ah[4], al[4];
            ah[0] = Ah[mr][kk];     ah[1] = Ah[mr + 8][kk];
            ah[2] = Ah[mr][kk + 4]; ah[3] = Ah[mr + 8][kk + 4];
            al[0] = Al[mr][kk];     al[1] = Al[mr + 8][kk];
            al[2] = Al[mr][kk + 4]; al[3] = Al[mr + 8][kk + 4];
#pragma unroll
            for (int nt = 0; nt < 4; nt++) {
                int nr = wn * 32 + nt * 8 + g;
                uint32_t bh[2], bl[2];
                bh[0] = Wh[nr][kk]; bh[1] = Wh[nr][kk + 4];
                bl[0] = Wl[nr][kk]; bl[1] = Wl[nr][kk + 4];
                mma16n8k8(acc[nt], ah, bh);
                mma16n8k8(acc[nt], ah, bl);
                mma16n8k8(acc[nt], al, bh);
            }
        }
        __syncthreads();
    }

    // epilogue: acc[nt] = {c(g,2t), c(g,2t+1), c(g+8,2t), c(g+8,2t+1)}
    int m0 = bm + wm * 16 + g;
    if (bn + 64 <= N) {
#pragma unroll
        for (int nt = 0; nt < 4; nt++) {
            int n = bn + wn * 32 + nt * 8 + 2 * t;
            float2 bv = *reinterpret_cast<const float2*>(bias + n);
            size_t o0 = (size_t)m0 * N + n;
            size_t o1 = (size_t)(m0 + 8) * N + n;
            float2 r0 = make_float2(acc[nt][0] + bv.x, acc[nt][1] + bv.y);
            float2 r1 = make_float2(acc[nt][2] + bv.x, acc[nt][3] + bv.y);
            if (res) {
                float2 e0 = *reinterpret_cast<const float2*>(res + o0);
                float2 e1 = *reinterpret_cast<const float2*>(res + o1);
                r0.x += e0.x; r0.y += e0.y; r1.x += e1.x; r1.y += e1.y;
            }
            *reinterpret_cast<float2*>(C + o0) = r0;
            *reinterpret_cast<float2*>(C + o1) = r1;
        }
    } else {
#pragma unroll
        for (int nt = 0; nt < 4; nt++) {
            int n = bn + wn * 32 + nt * 8 + 2 * t;
#pragma unroll
            for (int e = 0; e < 2; e++) {
                if (n + e >= N) continue;
                float v0 = acc[nt][e] + bias[n + e];
                float v1 = acc[nt][2 + e] + bias[n + e];
                if (res) {
                    v0 += res[(size_t)m0 * N + n + e];
                    v1 += res[(size_t)(m0 + 8) * N + n + e];
                }
                C[(size_t)m0 * N + n + e] = v0;
                C[(size_t)(m0 + 8) * N + n + e] = v1;
            }
        }
    }
}

// ---------------- flash attention: block = (64 queries, 1 head) ----------------
__global__ __launch_bounds__(256) void flash_attn(
        const float* __restrict__ Q, int ldq,
        const float* __restrict__ K, int ldk,
        const float* __restrict__ V, int ldv,
        float* __restrict__ O) {
    __shared__ float Qs[BQ][33];
    __shared__ float Ks[BK][33];
    __shared__ float Vs[BK][33];
    __shared__ float Ps[BQ][BK + 1];
    int h = blockIdx.y;
    int q0 = blockIdx.x * BQ;
    int tid = threadIdx.x;
    int tr = tid >> 4, tc = tid & 15;
    int lrow = tid >> 2, lcol = (tid & 3) * 8;

    {
        const float* qp = Q + (size_t)(q0 + lrow) * ldq + h * HD + lcol;
        float4 v0 = *reinterpret_cast<const float4*>(qp);
        float4 v1 = *reinterpret_cast<const float4*>(qp + 4);
        Qs[lrow][lcol + 0] = v0.x * SCALE; Qs[lrow][lcol + 1] = v0.y * SCALE;
        Qs[lrow][lcol + 2] = v0.z * SCALE; Qs[lrow][lcol + 3] = v0.w * SCALE;
        Qs[lrow][lcol + 4] = v1.x * SCALE; Qs[lrow][lcol + 5] = v1.y * SCALE;
        Qs[lrow][lcol + 6] = v1.z * SCALE; Qs[lrow][lcol + 7] = v1.w * SCALE;
    }

    float m[4], l[4], acc[4][2];
#pragma unroll
    for (int i = 0; i < 4; i++) {
        m[i] = -1e30f; l[i] = 0.f; acc[i][0] = 0.f; acc[i][1] = 0.f;
    }

    for (int kt = 0; kt < LQ; kt += BK) {
        const float* kp = K + (size_t)(kt + lrow) * ldk + h * HD + lcol;
        const float* vp = V + (size_t)(kt + lrow) * ldv + h * HD + lcol;
        float4 k0v = *reinterpret_cast<const float4*>(kp);
        float4 k1v = *reinterpret_cast<const float4*>(kp + 4);
        float4 v0v = *reinterpret_cast<const float4*>(vp);
        float4 v1v = *reinterpret_cast<const float4*>(vp + 4);
        __syncthreads();
        Ks[lrow][lcol + 0] = k0v.x; Ks[lrow][lcol + 1] = k0v.y;
        Ks[lrow][lcol + 2] = k0v.z; Ks[lrow][lcol + 3] = k0v.w;
        Ks[lrow][lcol + 4] = k1v.x; Ks[lrow][lcol + 5] = k1v.y;
        Ks[lrow][lcol + 6] = k1v.z; Ks[lrow][lcol + 7] = k1v.w;
        Vs[lrow][lcol + 0] = v0v.x; Vs[lrow][lcol + 1] = v0v.y;
        Vs[lrow][lcol + 2] = v0v.z; Vs[lrow][lcol + 3] = v0v.w;
        Vs[lrow][lcol + 4] = v1v.x; Vs[lrow][lcol + 5] = v1v.y;
        Vs[lrow][lcol + 6] = v1v.z; Vs[lrow][lcol + 7] = v1v.w;
        __syncthreads();

        float S[4][4] = {};
#pragma unroll
        for (int d = 0; d < 32; d++) {
            float a[4], b[4];
#pragma unroll
            for (int i = 0; i < 4; i++) a[i] = Qs[tr + 16 * i][d];
#pragma unroll
            for (int j = 0; j < 4; j++) b[j] = Ks[tc + 16 * j][d];
#pragma unroll
            for (int i = 0; i < 4; i++)
#pragma unroll
                for (int j = 0; j < 4; j++) S[i][j] = fmaf(a[i], b[j], S[i][j]);
        }

#pragma unroll
        for (int i = 0; i < 4; i++) {
            float tm = fmaxf(fmaxf(S[i][0], S[i][1]), fmaxf(S[i][2], S[i][3]));
#pragma unroll
            for (int o = 8; o; o >>= 1)
                tm = fmaxf(tm, __shfl_xor_sync(0xffffffffu, tm, o, 16));
            float nm = fmaxf(m[i], tm);
            float alpha = __expf(m[i] - nm);
            m[i] = nm;
            float p0 = __expf(S[i][0] - nm), p1 = __expf(S[i][1] - nm);
            float p2 = __expf(S[i][2] - nm), p3 = __expf(S[i][3] - nm);
            float ts = (p0 + p1) + (p2 + p3);
#pragma unroll
            for (int o = 8; o; o >>= 1)
                ts += __shfl_xor_sync(0xffffffffu, ts, o, 16);
            l[i] = l[i] * alpha + ts;
            acc[i][0] *= alpha; acc[i][1] *= alpha;
            int qr = tr + 16 * i;
            Ps[qr][tc] = p0; Ps[qr][tc + 16] = p1;
            Ps[qr][tc + 32] = p2; Ps[qr][tc + 48] = p3;
        }
        __syncthreads();

        int d0 = tc * 2;
#pragma unroll 16
        for (int k = 0; k < BK; k++) {
            float v0 = Vs[k][d0], v1 = Vs[k][d0 + 1];
            float p[4];
#pragma unroll
            for (int i = 0; i < 4; i++) p[i] = Ps[tr + 16 * i][k];
#pragma unroll
            for (int i = 0; i < 4; i++) {
                acc[i][0] = fmaf(p[i], v0, acc[i][0]);
                acc[i][1] = fmaf(p[i], v1, acc[i][1]);
            }
        }
    }

#pragma unroll
    for (int i = 0; i < 4; i++) {
        float inv = 1.0f / l[i];
        int q = q0 + tr + 16 * i;
        float* op = O + (size_t)q * CD + h * HD + tc * 2;
        op[0] = acc[i][0] * inv;
        op[1] = acc[i][1] * inv;
    }
}

// ---------------- local attention (15x15 window), smem-staged K/V ----------------
__global__ __launch_bounds__(256) void local_attn_kernel(
        const float* __restrict__ Q, int ldq,
        const float* __restrict__ K, const float* __restrict__ V,
        float* __restrict__ O) {
    __shared__ float win[WSQ][33];   // staged K, then reused for V (29.7KB)
    __shared__ float qs[HD];
    __shared__ float lg[WSQ];
    __shared__ float red[32];
    __shared__ float accs[8][33];
    int n = blockIdx.x, h = blockIdx.y, tid = threadIdx.x;
    int y = n / W2D, x = n % W2D;
    if (tid < HD) qs[tid] = Q[(size_t)n * ldq + h * HD + tid] * SCALE;

    for (int idx = tid; idx < WSQ * HD; idx += 256) {
        int w = idx >> 5, d = idx & 31;
        int ny = y + w / WS - PADR, nx = x + w % WS - PADR;
        bool ok = ((unsigned)ny < H2D) && ((unsigned)nx < W2D);
        win[w][d] = ok ? K[(size_t)(ny * W2D + nx) * CD + h * HD + d] : 0.f;
    }
    __syncthreads();

    float lmax = -1e30f;
    if (tid < WSQ) {
        int ny = y + tid / WS - PADR, nx = x + tid % WS - PADR;
        bool ok = ((unsigned)ny < H2D) && ((unsigned)nx < W2D);
        float d = 0.f;
#pragma unroll
        for (int j = 0; j < HD; j++) d = fmaf(qs[j], win[tid][j], d);
        d = ok ? d : -1e9f;
        lg[tid] = d;
        lmax = d;
    }
    float gmax = block_reduce(lmax, red, true);
    float lsum = 0.f;
    if (tid < WSQ) {
        float e = __expf(lg[tid] - gmax);
        lg[tid] = e;
        lsum = e;
    }
    float gsum = block_reduce(lsum, red, false);
    __syncthreads();

    for (int idx = tid; idx < WSQ * HD; idx += 256) {
        int w = idx >> 5, d = idx & 31;
        int ny = y + w / WS - PADR, nx = x + w % WS - PADR;
        bool ok = ((unsigned)ny < H2D) && ((unsigned)nx < W2D);
        win[w][d] = ok ? V[(size_t)(ny * W2D + nx) * CD + h * HD + d] : 0.f;
    }
    __syncthreads();

    int grp = tid >> 5, lane = tid & 31;
    float acc = 0.f;
    for (int w = grp; w < WSQ; w += 8)
        acc = fmaf(lg[w], win[w][lane], acc);
    accs[grp][lane] = acc;
    __syncthreads();
    if (tid < HD) {
        float s = 0.f;
#pragma unroll
        for (int g2 = 0; g2 < 8; g2++) s += accs[g2][tid];
        O[(size_t)n * CD + h * HD + tid] = s / gsum;
    }
}

// ---------------- global K/V construction (reads fused QV buffer) ----------------
__global__ void make_global_kv(const float* __restrict__ qv, const float* __restrict__ idkv,
                               float* __restrict__ gK, float* __restrict__ gV) {
    int i = blockIdx.x * blockDim.x + threadIdx.x;
    if (i >= LQ * CD) return;
    int l = i >> 8, c = i & 255, h = c >> 5;
    float ik = idkv[l * 264 + h];
    gK[i] = qv[(size_t)l * 512 + c] * (1.0f + tanhf(ik));
    gV[i] = qv[(size_t)l * 512 + 256 + c] + idkv[l * 264 + 8 + c];
}

// ---------------- GroupNorm stats (32 blocks) ----------------
__global__ void gn_stats(const float* __restrict__ x, float* __restrict__ stats) {
    __shared__ float red[32];
    int g = blockIdx.x;
    float s = 0.f, ss = 0.f;
    for (int i = threadIdx.x; i < LQ * 32; i += blockDim.x) {
        int l = i >> 5, c = (g << 5) + (i & 31);
        float v = x[(size_t)l * DFF + c];
        s += v;
        ss = fmaf(v, v, ss);
    }
    s = block_reduce(s, red, false);
    ss = block_reduce(ss, red, false);
    if (!threadIdx.x) {
        const float inv = 1.0f / (LQ * 32.0f);
        float m = s * inv;
        float var = ss * inv - m * m;
        stats[g * 2] = m;
        stats[g * 2 + 1] = rsqrtf(var + 1e-5f);
    }
}

// ---------------- GN apply + affine + exact GELU ----------------
__global__ void gn_apply_gelu(const float* __restrict__ x, const float* __restrict__ stats,
                              const float* __restrict__ gg, const float* __restrict__ gb,
                              float* __restrict__ y) {
    int i = blockIdx.x * blockDim.x + threadIdx.x;
    if (i >= LQ * DFF) return;
    int c = i & (DFF - 1);
    int grp = c >> 5;
    float m = stats[grp * 2], r = stats[grp * 2 + 1];
    float v = (x[i] - m) * r * gg[c] + gb[c];
    y[i] = 0.5f * v * (1.0f + erff(v * 0.70710678118654752f));
}

// ---------------- depthwise 5x5 conv, pad 2 ----------------
__global__ void dwconv_kernel(const float* __restrict__ x, const float* __restrict__ k,
                              float* __restrict__ y) {
    int l = blockIdx.x;
    int yy = l / W2D, xx = l % W2D;
    for (int c = threadIdx.x; c < DFF; c += blockDim.x) {
        float acc = 0.f;
#pragma unroll
        for (int i = 0; i < 5; i++) {
            int ny = yy + i - 2;
            if (ny < 0 || ny >= H2D) continue;
#pragma unroll
            for (int j = 0; j < 5; j++) {
                int nx = xx + j - 2;
                if (nx < 0 || nx >= W2D) continue;
                acc = fmaf(x[(size_t)(ny * W2D + nx) * DFF + c], k[c * 25 + i * 5 + j], acc);
            }
        }
        y[(size_t)l * DFF + c] = acc;
    }
}

// ---------------- host ----------------
static void launch_gemm(const float* A, const float* W, const float* bias, const float* res,
                        float* C, int M, int N, int K) {
    dim3 grid((N + 63) / 64, (M + 63) / 64);
    gemm_kernel<<<grid, 256>>>(A, W, bias, res, C, M, N, K);
}

extern "C" void kernel_launch(void* const* d_in, const int* in_sizes, int n_in,
                              void* d_out, int out_size) {
    const float* tgt = (const float*)d_in[0];
    const float* curr_id_emb = (const float*)d_in[1];
    const float* self_pos = (const float*)d_in[2];
    const float* ln1_g = (const float*)d_in[3];
    const float* ln1_b = (const float*)d_in[4];
    const float* sa_wq = (const float*)d_in[5];
    const float* sa_bq = (const float*)d_in[6];
    const float* sa_wk = (const float*)d_in[7];
    const float* sa_bk = (const float*)d_in[8];
    const float* sa_wv = (const float*)d_in[9];
    const float* sa_bv = (const float*)d_in[10];
    const float* sa_wo = (const float*)d_in[11];
    const float* sa_bo = (const float*)d_in[12];
    const float* ln2_g = (const float*)d_in[13];
    const float* ln2_b = (const float*)d_in[14];
    const float* w_qv = (const float*)d_in[15];
    const float* b_qv = (const float*)d_in[16];
    const float* w_id = (const float*)d_in[17];
    const float* b_id = (const float*)d_in[18];
    const float* lt_wo = (const float*)d_in[19];
    const float* lt_bo = (const float*)d_in[20];
    const float* st_wo = (const float*)d_in[21];
    const float* st_bo = (const float*)d_in[22];
    const float* ln3_g = (const float*)d_in[23];
    const float* ln3_b = (const float*)d_in[24];
    const float* w1 = (const float*)d_in[25];
    const float* b1 = (const float*)d_in[26];
    const float* gn_g = (const float*)d_in[27];
    const float* gn_b = (const float*)d_in[28];
    const float* dw_k = (const float*)d_in[29];
    const float* w2 = (const float*)d_in[30];
    const float* b2 = (const float*)d_in[31];
    float* out = (float*)d_out;

    float *tln, *qkin, *q, *k, *v, *att, *tgt1, *qv, *idkv, *gK, *gV, *st, *tmp, *tgt2, *x1, *x2, *gn;
    cudaGetSymbolAddress((void**)&tln, g_tln);
    cudaGetSymbolAddress((void**)&qkin, g_qkin);
    cudaGetSymbolAddress((void**)&q, g_q);
    cudaGetSymbolAddress((void**)&k, g_k);
    cudaGetSymbolAddress((void**)&v, g_v);
    cudaGetSymbolAddress((void**)&att, g_att);
    cudaGetSymbolAddress((void**)&tgt1, g_tgt1);
    cudaGetSymbolAddress((void**)&qv, g_qv);
    cudaGetSymbolAddress((void**)&idkv, g_idkv);
    cudaGetSymbolAddress((void**)&gK, g_gK);
    cudaGetSymbolAddress((void**)&gV, g_gV);
    cudaGetSymbolAddress((void**)&st, g_st);
    cudaGetSymbolAddress((void**)&tmp, g_tmp);
    cudaGetSymbolAddress((void**)&tgt2, g_tgt2);
    cudaGetSymbolAddress((void**)&x1, g_x1);
    cudaGetSymbolAddress((void**)&x2, g_x2);
    cudaGetSymbolAddress((void**)&gn, g_gn);

    // ---- self-attention block ----
    ln_kernel<<<LQ, 256>>>(tgt, ln1_g, ln1_b, tln, self_pos, qkin);
    launch_gemm(qkin, sa_wq, sa_bq, nullptr, q, LQ, CD, CD);
    launch_gemm(qkin, sa_wk, sa_bk, nullptr, k, LQ, CD, CD);
    launch_gemm(tln, sa_wv, sa_bv, nullptr, v, LQ, CD, CD);
    flash_attn<<<dim3(LQ / BQ, NH), 256>>>(q, CD, k, CD, v, CD, att);
    launch_gemm(att, sa_wo, sa_bo, tgt, tgt1, LQ, CD, CD);   // tgt1 = tgt + SA(tgt)

    // ---- long/short-term block ----
    ln_kernel<<<LQ, 256>>>(tgt1, ln2_g, ln2_b, tln, nullptr, nullptr);
    launch_gemm(tln, w_qv, b_qv, nullptr, qv, LQ, 512, CD);          // [curr_Q|curr_V]
    launch_gemm(curr_id_emb, w_id, b_id, nullptr, idkv, LQ, CD + NH, CD);
    make_global_kv<<<(LQ * CD + 255) / 256, 256>>>(qv, idkv, gK, gV);
    flash_attn<<<dim3(LQ / BQ, NH), 256>>>(qv, 512, gK, CD, gV, CD, att);
    launch_gemm(att, lt_wo, lt_bo, tgt1, tmp, LQ, CD, CD);   // tmp = tgt1 + LT
    local_attn_kernel<<<dim3(LQ, NH), 256>>>(qv, 512, gK, gV, st);
    launch_gemm(st, st_wo, st_bo, tmp, tgt2, LQ, CD, CD);    // tgt2 = tgt1 + LT + ST

    // ---- FFN block ----
    ln_kernel<<<LQ, 256>>>(tgt2, ln3_g, ln3_b, tln, nullptr, nullptr);
    launch_gemm(tln, w1, b1, nullptr, x1, LQ, DFF, CD);
    gn_stats<<<32, 256>>>(x1, gn);
    gn_apply_gelu<<<(LQ * DFF + 255) / 256, 256>>>(x1, gn, gn_g, gn_b, x2);
    dwconv_kernel<<<LQ, 256>>>(x2, dw_k, x1);
    launch_gemm(x1, w2, b2, tgt2, out, LQ, CD, DFF);         // out = tgt2 + FFN
}

// round 5
// speedup vs baseline: 11.0196x; 1.6548x over previous
#include <cuda_runtime.h>
#include <cuda_bf16.h>
#include <math.h>
#include <stdint.h>

#define LQ 1600
#define CD 256
#define NH 8
#define HD 32
#define DFF 1024
#define H2D 40
#define W2D 40
#define WS 15
#define WSQ 225
#define PADR 7
#define SCALE 0.17677669529663687f  // 1/sqrt(32)

#define BQ 64
#define BK 64
#define LTW 22
#define LTWW (LTW * LTW)  // 484

// ---------------- scratch (device globals; no allocation) ----------------
__device__ float g_tln[LQ * CD];
__device__ float g_qkin[LQ * CD];
__device__ float g_q[LQ * CD];
__device__ float g_k[LQ * CD];
__device__ float g_v[LQ * CD];
__device__ float g_att[LQ * CD];
__device__ float g_tgt1[LQ * CD];
__device__ float g_qv[LQ * 512];     // [curr_Q | curr_V] fused
__device__ float g_idkv[LQ * 264];
__device__ float g_gK[LQ * CD];
__device__ float g_gV[LQ * CD];
__device__ float g_st[LQ * CD];
__device__ float g_tmp[LQ * CD];
__device__ float g_tgt2[LQ * CD];
__device__ float g_x1[LQ * DFF];
__device__ float g_x2[LQ * DFF];
__device__ float g_gn[32 * 2];

// ---------------- mma helpers ----------------
__device__ __forceinline__ uint32_t f2tf32(float x) {
    uint32_t r;
    asm("cvt.rna.tf32.f32 %0, %1;" : "=r"(r) : "f"(x));
    return r;
}

__device__ __forceinline__ void mma16n8k8(float* c, const uint32_t* a, const uint32_t* b) {
    asm volatile(
        "mma.sync.aligned.m16n8k8.row.col.f32.tf32.tf32.f32 "
        "{%0,%1,%2,%3}, {%4,%5,%6,%7}, {%8,%9}, {%0,%1,%2,%3};"
        : "+f"(c[0]), "+f"(c[1]), "+f"(c[2]), "+f"(c[3])
        : "r"(a[0]), "r"(a[1]), "r"(a[2]), "r"(a[3]), "r"(b[0]), "r"(b[1]));
}

__device__ __forceinline__ void mma_bf16(float* c, const uint32_t* a, const uint32_t* b) {
    asm volatile(
        "mma.sync.aligned.m16n8k16.row.col.f32.bf16.bf16.f32 "
        "{%0,%1,%2,%3}, {%4,%5,%6,%7}, {%8,%9}, {%0,%1,%2,%3};"
        : "+f"(c[0]), "+f"(c[1]), "+f"(c[2]), "+f"(c[3])
        : "r"(a[0]), "r"(a[1]), "r"(a[2]), "r"(a[3]), "r"(b[0]), "r"(b[1]));
}

// pack two floats to bf16x2: low half = lo_elem (element with lower index)
__device__ __forceinline__ uint32_t pack_bf16(float lo, float hi) {
    uint32_t r;
    asm("cvt.rn.bf16x2.f32 %0, %1, %2;" : "=r"(r) : "f"(hi), "f"(lo));
    return r;
}

// split pair: returns hi-packed, writes lo-packed
__device__ __forceinline__ void split_bf16_pair(float x0, float x1, uint32_t& hi, uint32_t& lo) {
    hi = pack_bf16(x0, x1);
    float h0 = __uint_as_float(hi << 16);
    float h1 = __uint_as_float(hi & 0xffff0000u);
    lo = pack_bf16(x0 - h0, x1 - h1);
}

// ---------------- reductions ----------------
__device__ __forceinline__ float block_reduce(float v, float* red, bool is_max) {
    int lane = threadIdx.x & 31, wid = threadIdx.x >> 5;
#pragma unroll
    for (int o = 16; o; o >>= 1) {
        float u = __shfl_xor_sync(0xffffffffu, v, o);
        v = is_max ? fmaxf(v, u) : v + u;
    }
    if (!lane) red[wid] = v;
    __syncthreads();
    int nw = (blockDim.x + 31) >> 5;
    v = (lane < nw) ? red[lane] : (is_max ? -1e30f : 0.0f);
    if (!wid) {
#pragma unroll
        for (int o = 16; o; o >>= 1) {
            float u = __shfl_xor_sync(0xffffffffu, v, o);
            v = is_max ? fmaxf(v, u) : v + u;
        }
        if (!lane) red[0] = v;
    }
    __syncthreads();
    v = red[0];
    __syncthreads();
    return v;
}

// ---------------- LayerNorm ----------------
__global__ void ln_kernel(const float* __restrict__ in, const float* __restrict__ g,
                          const float* __restrict__ b, float* __restrict__ out,
                          const float* __restrict__ pos, float* __restrict__ out2) {
    __shared__ float red[32];
    int l = blockIdx.x, c = threadIdx.x;
    float x = in[l * CD + c];
    float m = block_reduce(x, red, false) * (1.0f / CD);
    float d = x - m;
    float var = block_reduce(d * d, red, false) * (1.0f / CD);
    float y = d * rsqrtf(var + 1e-5f) * g[c] + b[c];
    out[l * CD + c] = y;
    if (out2) out2[l * CD + c] = y + pos[l * CD + c];
}

// ---------------- 3xTF32 GEMM (unchanged from R4) ----------------
__global__ __launch_bounds__(256) void gemm_kernel(
        const float* __restrict__ A, const float* __restrict__ W,
        const float* __restrict__ bias, const float* __restrict__ res,
        float* __restrict__ C, int M, int N, int K) {
    __shared__ uint32_t Ah[64][20], Al[64][20];
    __shared__ uint32_t Wh[64][20], Wl[64][20];
    int tid = threadIdx.x;
    int bm = blockIdx.y * 64, bn = blockIdx.x * 64;
    int lr = tid >> 2, lc4 = (tid & 3) * 4;
    int wid = tid >> 5, lane = tid & 31;
    int wm = wid & 3, wn = wid >> 2;
    int g = lane >> 2, t = lane & 3;
    float acc[4][4] = {};

    const float* Ap = A + (size_t)(bm + lr) * K + lc4;
    bool wok = (bn + lr) < N;
    const float* Wp = W + (size_t)(wok ? bn + lr : 0) * K + lc4;
    float4 pa = *reinterpret_cast<const float4*>(Ap);
    float4 pw = wok ? *reinterpret_cast<const float4*>(Wp)
                    : make_float4(0.f, 0.f, 0.f, 0.f);

    for (int k0 = 0; k0 < K; k0 += 16) {
        float av[4] = {pa.x, pa.y, pa.z, pa.w};
        float wv[4] = {pw.x, pw.y, pw.z, pw.w};
#pragma unroll
        for (int e = 0; e < 4; e++) {
            uint32_t h = f2tf32(av[e]);
            Ah[lr][lc4 + e] = h;
            Al[lr][lc4 + e] = f2tf32(av[e] - __uint_as_float(h));
            uint32_t h2 = f2tf32(wv[e]);
            Wh[lr][lc4 + e] = h2;
            Wl[lr][lc4 + e] = f2tf32(wv[e] - __uint_as_float(h2));
        }
        __syncthreads();
        if (k0 + 16 < K) {
            pa = *reinterpret_cast<const float4*>(Ap + k0 + 16);
            pw = wok ? *reinterpret_cast<const float4*>(Wp + k0 + 16)
                     : make_float4(0.f, 0.f, 0.f, 0.f);
        }
#pragma unroll
        for (int ks = 0; ks < 2; ks++) {
            int kk = ks * 8 + t;
            int mr = wm * 16 + g;
            uint32_t ah[4], al[4];
            ah[0] = Ah[mr][kk];     ah[1] = Ah[mr + 8][kk];
            ah[2] = Ah[mr][kk + 4]; ah[3] = Ah[mr + 8][kk + 4];
            al[0] = Al[mr][kk];     al[1] = Al[mr + 8][kk];
            al[2] = Al[mr][kk + 4]; al[3] = Al[mr + 8][kk + 4];
#pragma unroll
            for (int nt = 0; nt < 4; nt++) {
                int nr = wn * 32 + nt * 8 + g;
                uint32_t bh[2], bl[2];
                bh[0] = Wh[nr][kk]; bh[1] = Wh[nr][kk + 4];
                bl[0] = Wl[nr][kk]; bl[1] = Wl[nr][kk + 4];
                mma16n8k8(acc[nt], ah, bh);
                mma16n8k8(acc[nt], ah, bl);
                mma16n8k8(acc[nt], al, bh);
            }
        }
        __syncthreads();
    }

    int m0 = bm + wm * 16 + g;
    if (bn + 64 <= N) {
#pragma unroll
        for (int nt = 0; nt < 4; nt++) {
            int n = bn + wn * 32 + nt * 8 + 2 * t;
            float2 bv = *reinterpret_cast<const float2*>(bias + n);
            size_t o0 = (size_t)m0 * N + n;
            size_t o1 = (size_t)(m0 + 8) * N + n;
            float2 r0 = make_float2(acc[nt][0] + bv.x, acc[nt][1] + bv.y);
            float2 r1 = make_float2(acc[nt][2] + bv.x, acc[nt][3] + bv.y);
            if (res) {
                float2 e0 = *reinterpret_cast<const float2*>(res + o0);
                float2 e1 = *reinterpret_cast<const float2*>(res + o1);
                r0.x += e0.x; r0.y += e0.y; r1.x += e1.x; r1.y += e1.y;
            }
            *reinterpret_cast<float2*>(C + o0) = r0;
            *reinterpret_cast<float2*>(C + o1) = r1;
        }
    } else {
#pragma unroll
        for (int nt = 0; nt < 4; nt++) {
            int n = bn + wn * 32 + nt * 8 + 2 * t;
#pragma unroll
            for (int e = 0; e < 2; e++) {
                if (n + e >= N) continue;
                float v0 = acc[nt][e] + bias[n + e];
                float v1 = acc[nt][2 + e] + bias[n + e];
                if (res) {
                    v0 += res[(size_t)m0 * N + n + e];
                    v1 += res[(size_t)(m0 + 8) * N + n + e];
                }
                C[(size_t)m0 * N + n + e] = v0;
                C[(size_t)(m0 + 8) * N + n + e] = v1;
            }
        }
    }
}

// ---------------- tensor-core flash attention (bf16 hi/lo split) ----------------
// block = (64 queries, 1 head), 8 warps = 4(m) x 2(n-half of keys)
__global__ __launch_bounds__(256) void flash_attn_tc(
        const float* __restrict__ Q, int ldq,
        const float* __restrict__ K, int ldk,
        const float* __restrict__ V, int ldv,
        float* __restrict__ O) {
    __shared__ uint32_t Qhi[64][20], Qlo[64][20];
    __shared__ uint32_t Khi[64][20], Klo[64][20];
    __shared__ uint32_t Vthi[32][36], Vtlo[32][36];   // V transposed: [d][key-pair]
    __shared__ float redmax[2][64], redsum[2][64];
    __shared__ float Osm[64][33];

    int h = blockIdx.y, q0 = blockIdx.x * BQ;
    int tid = threadIdx.x, wid = tid >> 5, lane = tid & 31;
    int wm = wid & 3, wn = wid >> 2;
    int g = lane >> 2, t = lane & 3;
    int m0 = wm * 16;
    int lrow = tid >> 2, lcol = (tid & 3) * 8;

    // stage Q (scaled, hi/lo split)
    {
        const float* qp = Q + (size_t)(q0 + lrow) * ldq + h * HD + lcol;
        float4 a = *reinterpret_cast<const float4*>(qp);
        float4 b = *reinterpret_cast<const float4*>(qp + 4);
        float xv[8] = {a.x, a.y, a.z, a.w, b.x, b.y, b.z, b.w};
#pragma unroll
        for (int j = 0; j < 4; j++) {
            uint32_t hi, lo;
            split_bf16_pair(xv[2 * j] * SCALE, xv[2 * j + 1] * SCALE, hi, lo);
            Qhi[lrow][lcol / 2 + j] = hi;
            Qlo[lrow][lcol / 2 + j] = lo;
        }
    }

    float mrow[2] = {-1e30f, -1e30f}, lsum[2] = {0.f, 0.f};
    float Oacc[4][4] = {};   // [d-tile][c]

    for (int kt = 0; kt < LQ; kt += BK) {
        const float* kp = K + (size_t)(kt + lrow) * ldk + h * HD + lcol;
        const float* vp = V + (size_t)(kt + lrow) * ldv + h * HD + lcol;
        float4 ka = *reinterpret_cast<const float4*>(kp);
        float4 kb = *reinterpret_cast<const float4*>(kp + 4);
        float4 va = *reinterpret_cast<const float4*>(vp);
        float4 vb = *reinterpret_cast<const float4*>(vp + 4);
        __syncthreads();   // prev tile done reading K/Vt/redsum
        {
            float kv[8] = {ka.x, ka.y, ka.z, ka.w, kb.x, kb.y, kb.z, kb.w};
#pragma unroll
            for (int j = 0; j < 4; j++) {
                uint32_t hi, lo;
                split_bf16_pair(kv[2 * j], kv[2 * j + 1], hi, lo);
                Khi[lrow][lcol / 2 + j] = hi;
                Klo[lrow][lcol / 2 + j] = lo;
            }
            float vv[8] = {va.x, va.y, va.z, va.w, vb.x, vb.y, vb.z, vb.w};
            __nv_bfloat16* VH = reinterpret_cast<__nv_bfloat16*>(Vthi);
            __nv_bfloat16* VL = reinterpret_cast<__nv_bfloat16*>(Vtlo);
#pragma unroll
            for (int j = 0; j < 8; j++) {
                int d = lcol + j;
                float x = vv[j];
                __nv_bfloat16 hb = __float2bfloat16(x);
                VH[d * 72 + lrow] = hb;
                VL[d * 72 + lrow] = __float2bfloat16(x - __bfloat162float(hb));
            }
        }
        __syncthreads();

        // S = Q K^T for this warp's 16x32 tile
        float S[4][4];
#pragma unroll
        for (int nt = 0; nt < 4; nt++)
#pragma unroll
            for (int c = 0; c < 4; c++) S[nt][c] = 0.f;
#pragma unroll
        for (int kc = 0; kc < 2; kc++) {
            uint32_t ah[4], al[4];
            ah[0] = Qhi[m0 + g][kc * 8 + t];     ah[1] = Qhi[m0 + 8 + g][kc * 8 + t];
            ah[2] = Qhi[m0 + g][kc * 8 + t + 4]; ah[3] = Qhi[m0 + 8 + g][kc * 8 + t + 4];
            al[0] = Qlo[m0 + g][kc * 8 + t];     al[1] = Qlo[m0 + 8 + g][kc * 8 + t];
            al[2] = Qlo[m0 + g][kc * 8 + t + 4]; al[3] = Qlo[m0 + 8 + g][kc * 8 + t + 4];
#pragma unroll
            for (int nt = 0; nt < 4; nt++) {
                int kr = wn * 32 + nt * 8 + g;
                uint32_t bh[2] = {Khi[kr][kc * 8 + t], Khi[kr][kc * 8 + t + 4]};
                uint32_t bl[2] = {Klo[kr][kc * 8 + t], Klo[kr][kc * 8 + t + 4]};
                mma_bf16(S[nt], ah, bh);
                mma_bf16(S[nt], ah, bl);
                mma_bf16(S[nt], al, bh);
            }
        }

        // cross-warp online softmax (rows g -> [0], g+8 -> [1])
        float pmA = -1e30f, pmB = -1e30f;
#pragma unroll
        for (int nt = 0; nt < 4; nt++) {
            pmA = fmaxf(pmA, fmaxf(S[nt][0], S[nt][1]));
            pmB = fmaxf(pmB, fmaxf(S[nt][2], S[nt][3]));
        }
        pmA = fmaxf(pmA, __shfl_xor_sync(0xffffffffu, pmA, 1));
        pmA = fmaxf(pmA, __shfl_xor_sync(0xffffffffu, pmA, 2));
        pmB = fmaxf(pmB, __shfl_xor_sync(0xffffffffu, pmB, 1));
        pmB = fmaxf(pmB, __shfl_xor_sync(0xffffffffu, pmB, 2));
        if (t == 0) {
            redmax[wn][m0 + g] = pmA;
            redmax[wn][m0 + 8 + g] = pmB;
        }
        __syncthreads();
        float nmA = fmaxf(mrow[0], fmaxf(redmax[0][m0 + g], redmax[1][m0 + g]));
        float nmB = fmaxf(mrow[1], fmaxf(redmax[0][m0 + 8 + g], redmax[1][m0 + 8 + g]));
        float alA = __expf(mrow[0] - nmA), alB = __expf(mrow[1] - nmB);
        mrow[0] = nmA; mrow[1] = nmB;
        float psA = 0.f, psB = 0.f;
#pragma unroll
        for (int nt = 0; nt < 4; nt++) {
            S[nt][0] = __expf(S[nt][0] - nmA); S[nt][1] = __expf(S[nt][1] - nmA);
            S[nt][2] = __expf(S[nt][2] - nmB); S[nt][3] = __expf(S[nt][3] - nmB);
            psA += S[nt][0] + S[nt][1];
            psB += S[nt][2] + S[nt][3];
        }
        psA += __shfl_xor_sync(0xffffffffu, psA, 1);
        psA += __shfl_xor_sync(0xffffffffu, psA, 2);
        psB += __shfl_xor_sync(0xffffffffu, psB, 1);
        psB += __shfl_xor_sync(0xffffffffu, psB, 2);
        if (t == 0) {
            redsum[wn][m0 + g] = psA;
            redsum[wn][m0 + 8 + g] = psB;
        }
#pragma unroll
        for (int nt = 0; nt < 4; nt++) {
            Oacc[nt][0] *= alA; Oacc[nt][1] *= alA;
            Oacc[nt][2] *= alB; Oacc[nt][3] *= alB;
        }
        __syncthreads();
        lsum[0] = lsum[0] * alA + redsum[0][m0 + g] + redsum[1][m0 + g];
        lsum[1] = lsum[1] * alB + redsum[0][m0 + 8 + g] + redsum[1][m0 + 8 + g];

        // PV: P (registers, A-frag layout) x V^T (smem)
#pragma unroll
        for (int kc2 = 0; kc2 < 2; kc2++) {
            uint32_t ph[4], pl[4];
            split_bf16_pair(S[2 * kc2][0], S[2 * kc2][1], ph[0], pl[0]);
            split_bf16_pair(S[2 * kc2][2], S[2 * kc2][3], ph[1], pl[1]);
            split_bf16_pair(S[2 * kc2 + 1][0], S[2 * kc2 + 1][1], ph[2], pl[2]);
            split_bf16_pair(S[2 * kc2 + 1][2], S[2 * kc2 + 1][3], ph[3], pl[3]);
            int cb = wn * 16 + kc2 * 8 + t;
#pragma unroll
            for (int ntv = 0; ntv < 4; ntv++) {
                int vr = ntv * 8 + g;
                uint32_t bh[2] = {Vthi[vr][cb], Vthi[vr][cb + 4]};
                uint32_t bl[2] = {Vtlo[vr][cb], Vtlo[vr][cb + 4]};
                mma_bf16(Oacc[ntv], ph, bh);
                mma_bf16(Oacc[ntv], ph, bl);
                mma_bf16(Oacc[ntv], pl, bh);
            }
        }
    }

    // epilogue: combine the two n-half warps, divide by l
    if (wn == 0) {
#pragma unroll
        for (int ntv = 0; ntv < 4; ntv++) {
            int d = ntv * 8 + 2 * t;
            Osm[m0 + g][d] = Oacc[ntv][0];
            Osm[m0 + g][d + 1] = Oacc[ntv][1];
            Osm[m0 + 8 + g][d] = Oacc[ntv][2];
            Osm[m0 + 8 + g][d + 1] = Oacc[ntv][3];
        }
    }
    __syncthreads();
    if (wn == 1) {
        float invA = 1.0f / lsum[0], invB = 1.0f / lsum[1];
#pragma unroll
        for (int ntv = 0; ntv < 4; ntv++) {
            int d = ntv * 8 + 2 * t;
            float* op0 = O + (size_t)(q0 + m0 + g) * CD + h * HD + d;
            float* op1 = O + (size_t)(q0 + m0 + 8 + g) * CD + h * HD + d;
            op0[0] = (Oacc[ntv][0] + Osm[m0 + g][d]) * invA;
            op0[1] = (Oacc[ntv][1] + Osm[m0 + g][d + 1]) * invA;
            op1[0] = (Oacc[ntv][2] + Osm[m0 + 8 + g][d]) * invB;
            op1[1] = (Oacc[ntv][3] + Osm[m0 + 8 + g][d + 1]) * invB;
        }
    }
}

// ---------------- tiled local attention: block = (8x8 query tile, head) ----------------
// Window 22x22 staged once for K and V (dynamic smem ~133KB), p via per-warp smem strip.
__global__ __launch_bounds__(256) void local_attn_tile(
        const float* __restrict__ Q, int ldq,
        const float* __restrict__ K, const float* __restrict__ V,
        float* __restrict__ O) {
    extern __shared__ float sm[];
    float* winK = sm;                      // [484][33]
    float* winV = sm + LTWW * 33;          // [484][33]
    float* pb = sm + 2 * LTWW * 33;        // [8][264]
    int h = blockIdx.y;
    int ty0 = (blockIdx.x / 5) * 8, tx0 = (blockIdx.x % 5) * 8;
    int wy0 = ty0 - PADR, wx0 = tx0 - PADR;
    int tid = threadIdx.x, w = tid >> 5, lane = tid & 31;

    for (int idx = tid; idx < LTWW * 32; idx += 256) {
        int pos = idx >> 5, d = idx & 31;
        int gy = wy0 + pos / LTW, gx = wx0 + pos % LTW;
        bool ok = ((unsigned)gy < H2D) && ((unsigned)gx < W2D);
        size_t goff = (size_t)(gy * W2D + gx) * CD + h * HD + d;
        winK[pos * 33 + d] = ok ? K[goff] : 0.f;
        winV[pos * 33 + d] = ok ? V[goff] : 0.f;
    }
    __syncthreads();

    int qy = ty0 + w;   // warp w = query row w of the tile
    for (int qi = 0; qi < 8; qi++) {
        int qx = tx0 + qi;
        float qv = Q[(size_t)(qy * W2D + qx) * ldq + h * HD + lane] * SCALE;
        float lg[8];
        int wi[8];
        bool val[8];
#pragma unroll
        for (int c = 0; c < 8; c++) {
            int j = c * 32 + lane;
            int jr = j / 15, jc = j - jr * 15;
            int gy2 = qy + jr - PADR, gx2 = qx + jc - PADR;
            val[c] = (j < WSQ) && ((unsigned)gy2 < H2D) && ((unsigned)gx2 < W2D);
            wi[c] = (j < WSQ) ? ((w + jr) * LTW + (qi + jc)) : 0;
            lg[c] = 0.f;
        }
#pragma unroll 8
        for (int d = 0; d < 32; d++) {
            float qd = __shfl_sync(0xffffffffu, qv, d);
#pragma unroll
            for (int c = 0; c < 8; c++)
                lg[c] = fmaf(qd, winK[wi[c] * 33 + d], lg[c]);
        }
        float mx = -1e30f;
#pragma unroll
        for (int c = 0; c < 8; c++) {
            lg[c] = val[c] ? lg[c] : -1e30f;
            mx = fmaxf(mx, lg[c]);
        }
#pragma unroll
        for (int o = 16; o; o >>= 1) mx = fmaxf(mx, __shfl_xor_sync(0xffffffffu, mx, o));
        float s = 0.f;
#pragma unroll
        for (int c = 0; c < 8; c++) {
            lg[c] = __expf(lg[c] - mx);
            s += lg[c];
        }
#pragma unroll
        for (int o = 16; o; o >>= 1) s += __shfl_xor_sync(0xffffffffu, s, o);
        float inv = 1.0f / s;
#pragma unroll
        for (int c = 0; c < 8; c++) pb[w * 264 + c * 32 + lane] = lg[c] * inv;
        __syncwarp();

        // PV: lane = output channel d
        float oacc = 0.f;
        int j = 0;
#pragma unroll
        for (int jr = 0; jr < 15; jr++) {
            int base = ((w + jr) * LTW + qi) * 33 + lane;
#pragma unroll
            for (int jc = 0; jc < 15; jc++) {
                oacc = fmaf(pb[w * 264 + j], winV[base + jc * 33], oacc);
                j++;
            }
        }
        O[(size_t)(qy * W2D + qx) * CD + h * HD + lane] = oacc;
        __syncwarp();
    }
}

// ---------------- global K/V construction ----------------
__global__ void make_global_kv(const float* __restrict__ qv, const float* __restrict__ idkv,
                               float* __restrict__ gK, float* __restrict__ gV) {
    int i = blockIdx.x * blockDim.x + threadIdx.x;
    if (i >= LQ * CD) return;
    int l = i >> 8, c = i & 255, h = c >> 5;
    float ik = idkv[l * 264 + h];
    gK[i] = qv[(size_t)l * 512 + c] * (1.0f + tanhf(ik));
    gV[i] = qv[(size_t)l * 512 + 256 + c] + idkv[l * 264 + 8 + c];
}

// ---------------- GroupNorm stats ----------------
__global__ void gn_stats(const float* __restrict__ x, float* __restrict__ stats) {
    __shared__ float red[32];
    int g = blockIdx.x;
    float s = 0.f, ss = 0.f;
    for (int i = threadIdx.x; i < LQ * 32; i += blockDim.x) {
        int l = i >> 5, c = (g << 5) + (i & 31);
        float v = x[(size_t)l * DFF + c];
        s += v;
        ss = fmaf(v, v, ss);
    }
    s = block_reduce(s, red, false);
    ss = block_reduce(ss, red, false);
    if (!threadIdx.x) {
        const float inv = 1.0f / (LQ * 32.0f);
        float m = s * inv;
        float var = ss * inv - m * m;
        stats[g * 2] = m;
        stats[g * 2 + 1] = rsqrtf(var + 1e-5f);
    }
}

// ---------------- GN apply + affine + exact GELU ----------------
__global__ void gn_apply_gelu(const float* __restrict__ x, const float* __restrict__ stats,
                              const float* __restrict__ gg, const float* __restrict__ gb,
                              float* __restrict__ y) {
    int i = blockIdx.x * blockDim.x + threadIdx.x;
    if (i >= LQ * DFF) return;
    int c = i & (DFF - 1);
    int grp = c >> 5;
    float m = stats[grp * 2], r = stats[grp * 2 + 1];
    float v = (x[i] - m) * r * gg[c] + gb[c];
    y[i] = 0.5f * v * (1.0f + erff(v * 0.70710678118654752f));
}

// ---------------- depthwise 5x5 conv, pad 2 ----------------
__global__ void dwconv_kernel(const float* __restrict__ x, const float* __restrict__ k,
                              float* __restrict__ y) {
    int l = blockIdx.x;
    int yy = l / W2D, xx = l % W2D;
    for (int c = threadIdx.x; c < DFF; c += blockDim.x) {
        float acc = 0.f;
#pragma unroll
        for (int i = 0; i < 5; i++) {
            int ny = yy + i - 2;
            if (ny < 0 || ny >= H2D) continue;
#pragma unroll
            for (int j = 0; j < 5; j++) {
                int nx = xx + j - 2;
                if (nx < 0 || nx >= W2D) continue;
                acc = fmaf(x[(size_t)(ny * W2D + nx) * DFF + c], k[c * 25 + i * 5 + j], acc);
            }
        }
        y[(size_t)l * DFF + c] = acc;
    }
}

// ---------------- host ----------------
static void launch_gemm(const float* A, const float* W, const float* bias, const float* res,
                        float* C, int M, int N, int K) {
    dim3 grid((N + 63) / 64, (M + 63) / 64);
    gemm_kernel<<<grid, 256>>>(A, W, bias, res, C, M, N, K);
}

extern "C" void kernel_launch(void* const* d_in, const int* in_sizes, int n_in,
                              void* d_out, int out_size) {
    const float* tgt = (const float*)d_in[0];
    const float* curr_id_emb = (const float*)d_in[1];
    const float* self_pos = (const float*)d_in[2];
    const float* ln1_g = (const float*)d_in[3];
    const float* ln1_b = (const float*)d_in[4];
    const float* sa_wq = (const float*)d_in[5];
    const float* sa_bq = (const float*)d_in[6];
    const float* sa_wk = (const float*)d_in[7];
    const float* sa_bk = (const float*)d_in[8];
    const float* sa_wv = (const float*)d_in[9];
    const float* sa_bv = (const float*)d_in[10];
    const float* sa_wo = (const float*)d_in[11];
    const float* sa_bo = (const float*)d_in[12];
    const float* ln2_g = (const float*)d_in[13];
    const float* ln2_b = (const float*)d_in[14];
    const float* w_qv = (const float*)d_in[15];
    const float* b_qv = (const float*)d_in[16];
    const float* w_id = (const float*)d_in[17];
    const float* b_id = (const float*)d_in[18];
    const float* lt_wo = (const float*)d_in[19];
    const float* lt_bo = (const float*)d_in[20];
    const float* st_wo = (const float*)d_in[21];
    const float* st_bo = (const float*)d_in[22];
    const float* ln3_g = (const float*)d_in[23];
    const float* ln3_b = (const float*)d_in[24];
    const float* w1 = (const float*)d_in[25];
    const float* b1 = (const float*)d_in[26];
    const float* gn_g = (const float*)d_in[27];
    const float* gn_b = (const float*)d_in[28];
    const float* dw_k = (const float*)d_in[29];
    const float* w2 = (const float*)d_in[30];
    const float* b2 = (const float*)d_in[31];
    float* out = (float*)d_out;

    float *tln, *qkin, *q, *k, *v, *att, *tgt1, *qv, *idkv, *gK, *gV, *st, *tmp, *tgt2, *x1, *x2, *gn;
    cudaGetSymbolAddress((void**)&tln, g_tln);
    cudaGetSymbolAddress((void**)&qkin, g_qkin);
    cudaGetSymbolAddress((void**)&q, g_q);
    cudaGetSymbolAddress((void**)&k, g_k);
    cudaGetSymbolAddress((void**)&v, g_v);
    cudaGetSymbolAddress((void**)&att, g_att);
    cudaGetSymbolAddress((void**)&tgt1, g_tgt1);
    cudaGetSymbolAddress((void**)&qv, g_qv);
    cudaGetSymbolAddress((void**)&idkv, g_idkv);
    cudaGetSymbolAddress((void**)&gK, g_gK);
    cudaGetSymbolAddress((void**)&gV, g_gV);
    cudaGetSymbolAddress((void**)&st, g_st);
    cudaGetSymbolAddress((void**)&tmp, g_tmp);
    cudaGetSymbolAddress((void**)&tgt2, g_tgt2);
    cudaGetSymbolAddress((void**)&x1, g_x1);
    cudaGetSymbolAddress((void**)&x2, g_x2);
    cudaGetSymbolAddress((void**)&gn, g_gn);

    const int LOCAL_SMEM = (2 * LTWW * 33 + 8 * 264) * (int)sizeof(float);
    cudaFuncSetAttribute(local_attn_tile, cudaFuncAttributeMaxDynamicSharedMemorySize, LOCAL_SMEM);

    // ---- self-attention block ----
    ln_kernel<<<LQ, 256>>>(tgt, ln1_g, ln1_b, tln, self_pos, qkin);
    launch_gemm(qkin, sa_wq, sa_bq, nullptr, q, LQ, CD, CD);
    launch_gemm(qkin, sa_wk, sa_bk, nullptr, k, LQ, CD, CD);
    launch_gemm(tln, sa_wv, sa_bv, nullptr, v, LQ, CD, CD);
    flash_attn_tc<<<dim3(LQ / BQ, NH), 256>>>(q, CD, k, CD, v, CD, att);
    launch_gemm(att, sa_wo, sa_bo, tgt, tgt1, LQ, CD, CD);   // tgt1 = tgt + SA(tgt)

    // ---- long/short-term block ----
    ln_kernel<<<LQ, 256>>>(tgt1, ln2_g, ln2_b, tln, nullptr, nullptr);
    launch_gemm(tln, w_qv, b_qv, nullptr, qv, LQ, 512, CD);          // [curr_Q|curr_V]
    launch_gemm(curr_id_emb, w_id, b_id, nullptr, idkv, LQ, CD + NH, CD);
    make_global_kv<<<(LQ * CD + 255) / 256, 256>>>(qv, idkv, gK, gV);
    flash_attn_tc<<<dim3(LQ / BQ, NH), 256>>>(qv, 512, gK, CD, gV, CD, att);
    launch_gemm(att, lt_wo, lt_bo, tgt1, tmp, LQ, CD, CD);   // tmp = tgt1 + LT
    local_attn_tile<<<dim3(25, NH), 256, LOCAL_SMEM>>>(qv, 512, gK, gV, st);
    launch_gemm(st, st_wo, st_bo, tmp, tgt2, LQ, CD, CD);    // tgt2 = tgt1 + LT + ST

    // ---- FFN block ----
    ln_kernel<<<LQ, 256>>>(tgt2, ln3_g, ln3_b, tln, nullptr, nullptr);
    launch_gemm(tln, w1, b1, nullptr, x1, LQ, DFF, CD);
    gn_stats<<<32, 256>>>(x1, gn);
    gn_apply_gelu<<<(LQ * DFF + 255) / 256, 256>>>(x1, gn, gn_g, gn_b, x2);
    dwconv_kernel<<<LQ, 256>>>(x2, dw_k, x1);
    launch_gemm(x1, w2, b2, tgt2, out, LQ, CD, DFF);         // out = tgt2 + FFN
}

// round 6
// speedup vs baseline: 12.7245x; 1.1547x over previous
#include <cuda_runtime.h>
#include <cuda_bf16.h>
#include <math.h>
#include <stdint.h>

#define LQ 1600
#define CD 256
#define NH 8
#define HD 32
#define DFF 1024
#define H2D 40
#define W2D 40
#define WS 15
#define WSQ 225
#define PADR 7
#define SCALE 0.17677669529663687f  // 1/sqrt(32)

#define BQ 64
#define BK 64
#define LTW 22
#define LTWW (LTW * LTW)  // 484

// GEMM chunking
#define KC 128            // K elements staged per chunk
#define KP 64             // k-pairs per chunk
#define KPP 66            // padded row stride (words); 66 % 32 = 2 -> conflict-free
#define GSEG (64 * KPP)   // words per smem array

// ---------------- scratch (device globals; no allocation) ----------------
__device__ float g_tln[LQ * CD];
__device__ float g_qkin[LQ * CD];
__device__ float g_q[LQ * CD];
__device__ float g_k[LQ * CD];
__device__ float g_v[LQ * CD];
__device__ float g_att[LQ * CD];
__device__ float g_tgt1[LQ * CD];
__device__ float g_qv[LQ * 512];     // [curr_Q | curr_V] fused
__device__ float g_idkv[LQ * 264];
__device__ float g_gK[LQ * CD];
__device__ float g_gV[LQ * CD];
__device__ float g_st[LQ * CD];
__device__ float g_tmp[LQ * CD];
__device__ float g_tgt2[LQ * CD];
__device__ float g_x1[LQ * DFF];
__device__ float g_x2[LQ * DFF];
__device__ float g_gn[32 * 2];

// ---------------- mma helpers ----------------
__device__ __forceinline__ void mma_bf16(float* c, const uint32_t* a, const uint32_t* b) {
    asm volatile(
        "mma.sync.aligned.m16n8k16.row.col.f32.bf16.bf16.f32 "
        "{%0,%1,%2,%3}, {%4,%5,%6,%7}, {%8,%9}, {%0,%1,%2,%3};"
        : "+f"(c[0]), "+f"(c[1]), "+f"(c[2]), "+f"(c[3])
        : "r"(a[0]), "r"(a[1]), "r"(a[2]), "r"(a[3]), "r"(b[0]), "r"(b[1]));
}

// pack two floats to bf16x2: low half = first arg
__device__ __forceinline__ uint32_t pack_bf16(float lo, float hi) {
    uint32_t r;
    asm("cvt.rn.bf16x2.f32 %0, %1, %2;" : "=r"(r) : "f"(hi), "f"(lo));
    return r;
}

__device__ __forceinline__ void split_bf16_pair(float x0, float x1, uint32_t& hi, uint32_t& lo) {
    hi = pack_bf16(x0, x1);
    float h0 = __uint_as_float(hi << 16);
    float h1 = __uint_as_float(hi & 0xffff0000u);
    lo = pack_bf16(x0 - h0, x1 - h1);
}

// ---------------- reductions ----------------
__device__ __forceinline__ float block_reduce(float v, float* red, bool is_max) {
    int lane = threadIdx.x & 31, wid = threadIdx.x >> 5;
#pragma unroll
    for (int o = 16; o; o >>= 1) {
        float u = __shfl_xor_sync(0xffffffffu, v, o);
        v = is_max ? fmaxf(v, u) : v + u;
    }
    if (!lane) red[wid] = v;
    __syncthreads();
    int nw = (blockDim.x + 31) >> 5;
    v = (lane < nw) ? red[lane] : (is_max ? -1e30f : 0.0f);
    if (!wid) {
#pragma unroll
        for (int o = 16; o; o >>= 1) {
            float u = __shfl_xor_sync(0xffffffffu, v, o);
            v = is_max ? fmaxf(v, u) : v + u;
        }
        if (!lane) red[0] = v;
    }
    __syncthreads();
    v = red[0];
    __syncthreads();
    return v;
}

// ---------------- LayerNorm ----------------
__global__ void ln_kernel(const float* __restrict__ in, const float* __restrict__ g,
                          const float* __restrict__ b, float* __restrict__ out,
                          const float* __restrict__ pos, float* __restrict__ out2) {
    __shared__ float red[32];
    int l = blockIdx.x, c = threadIdx.x;
    float x = in[l * CD + c];
    float m = block_reduce(x, red, false) * (1.0f / CD);
    float d = x - m;
    float var = block_reduce(d * d, red, false) * (1.0f / CD);
    float y = d * rsqrtf(var + 1e-5f) * g[c] + b[c];
    out[l * CD + c] = y;
    if (out2) out2[l * CD + c] = y + pos[l * CD + c];
}

// ---------------- bf16-split tensor-core GEMM ----------------
// C[m,n] = sum_k A[m,k]*W[n,k] + bias[n] (+res). BM=BN=64, K chunked by 128.
// 8 warps = 4(m) x 2(n), warp tile 16x32, m16n8k16 bf16 with hi/lo 3-term split.
// Requires M % 64 == 0, K % 128 == 0. N arbitrary.
__global__ __launch_bounds__(256) void gemm_tc(
        const float* __restrict__ A, const float* __restrict__ W,
        const float* __restrict__ bias, const float* __restrict__ res,
        float* __restrict__ C, int M, int N, int K) {
    extern __shared__ uint32_t su[];
    uint32_t* Ah = su;
    uint32_t* Al = su + GSEG;
    uint32_t* Wh = su + 2 * GSEG;
    uint32_t* Wl = su + 3 * GSEG;

    int tid = threadIdx.x;
    int bm = blockIdx.y * 64, bn = blockIdx.x * 64;
    int wid = tid >> 5, lane = tid & 31;
    int wm = wid & 3, wn = wid >> 2;
    int g = lane >> 2, t = lane & 3;
    int m0 = wm * 16;
    float acc[4][4] = {};

    int srow = tid >> 2, sc0 = tid & 3;   // 4 threads per row, each 8 float4s
    bool wok = (bn + srow) < N;
    const float* Ap = A + (size_t)(bm + srow) * K;
    const float* Wp = W + (size_t)(wok ? bn + srow : 0) * K;

    for (int k0 = 0; k0 < K; k0 += KC) {
        if (k0) __syncthreads();
        // stage chunk: fp32 -> bf16 hi/lo pairs
#pragma unroll
        for (int c = sc0; c < KC / 4; c += 4) {
            float4 a = *reinterpret_cast<const float4*>(Ap + k0 + c * 4);
            uint32_t h0, l0, h1, l1;
            split_bf16_pair(a.x, a.y, h0, l0);
            split_bf16_pair(a.z, a.w, h1, l1);
            Ah[srow * KPP + 2 * c] = h0;     Ah[srow * KPP + 2 * c + 1] = h1;
            Al[srow * KPP + 2 * c] = l0;     Al[srow * KPP + 2 * c + 1] = l1;
            float4 w = wok ? *reinterpret_cast<const float4*>(Wp + k0 + c * 4)
                           : make_float4(0.f, 0.f, 0.f, 0.f);
            split_bf16_pair(w.x, w.y, h0, l0);
            split_bf16_pair(w.z, w.w, h1, l1);
            Wh[srow * KPP + 2 * c] = h0;     Wh[srow * KPP + 2 * c + 1] = h1;
            Wl[srow * KPP + 2 * c] = l0;     Wl[srow * KPP + 2 * c + 1] = l1;
        }
        __syncthreads();

        // 8 k-groups of 16, no barriers
#pragma unroll
        for (int ks = 0; ks < KC / 16; ks++) {
            int kb = ks * 8 + t;
            uint32_t ah[4], al[4];
            ah[0] = Ah[(m0 + g) * KPP + kb];
            ah[1] = Ah[(m0 + 8 + g) * KPP + kb];
            ah[2] = Ah[(m0 + g) * KPP + kb + 4];
            ah[3] = Ah[(m0 + 8 + g) * KPP + kb + 4];
            al[0] = Al[(m0 + g) * KPP + kb];
            al[1] = Al[(m0 + 8 + g) * KPP + kb];
            al[2] = Al[(m0 + g) * KPP + kb + 4];
            al[3] = Al[(m0 + 8 + g) * KPP + kb + 4];
#pragma unroll
            for (int nt = 0; nt < 4; nt++) {
                int nr = wn * 32 + nt * 8 + g;
                uint32_t bh[2] = {Wh[nr * KPP + kb], Wh[nr * KPP + kb + 4]};
                uint32_t bl[2] = {Wl[nr * KPP + kb], Wl[nr * KPP + kb + 4]};
                mma_bf16(acc[nt], ah, bh);
                mma_bf16(acc[nt], ah, bl);
                mma_bf16(acc[nt], al, bh);
            }
        }
    }

    // epilogue: acc[nt] = {c(g,2t), c(g,2t+1), c(g+8,2t), c(g+8,2t+1)}
    int mo = bm + m0 + g;
    if (bn + 64 <= N) {
#pragma unroll
        for (int nt = 0; nt < 4; nt++) {
            int n = bn + wn * 32 + nt * 8 + 2 * t;
            float2 bv = *reinterpret_cast<const float2*>(bias + n);
            size_t o0 = (size_t)mo * N + n;
            size_t o1 = (size_t)(mo + 8) * N + n;
            float2 r0 = make_float2(acc[nt][0] + bv.x, acc[nt][1] + bv.y);
            float2 r1 = make_float2(acc[nt][2] + bv.x, acc[nt][3] + bv.y);
            if (res) {
                float2 e0 = *reinterpret_cast<const float2*>(res + o0);
                float2 e1 = *reinterpret_cast<const float2*>(res + o1);
                r0.x += e0.x; r0.y += e0.y; r1.x += e1.x; r1.y += e1.y;
            }
            *reinterpret_cast<float2*>(C + o0) = r0;
            *reinterpret_cast<float2*>(C + o1) = r1;
        }
    } else {
#pragma unroll
        for (int nt = 0; nt < 4; nt++) {
            int n = bn + wn * 32 + nt * 8 + 2 * t;
#pragma unroll
            for (int e = 0; e < 2; e++) {
                if (n + e >= N) continue;
                float v0 = acc[nt][e] + bias[n + e];
                float v1 = acc[nt][2 + e] + bias[n + e];
                if (res) {
                    v0 += res[(size_t)mo * N + n + e];
                    v1 += res[(size_t)(mo + 8) * N + n + e];
                }
                C[(size_t)mo * N + n + e] = v0;
                C[(size_t)(mo + 8) * N + n + e] = v1;
            }
        }
    }
}

// ---------------- tensor-core flash attention (bf16 hi/lo split) ----------------
__global__ __launch_bounds__(256) void flash_attn_tc(
        const float* __restrict__ Q, int ldq,
        const float* __restrict__ K, int ldk,
        const float* __restrict__ V, int ldv,
        float* __restrict__ O) {
    __shared__ uint32_t Qhi[64][20], Qlo[64][20];
    __shared__ uint32_t Khi[64][20], Klo[64][20];
    __shared__ uint32_t Vthi[32][36], Vtlo[32][36];
    __shared__ float redmax[2][64], redsum[2][64];
    __shared__ float Osm[64][33];

    int h = blockIdx.y, q0 = blockIdx.x * BQ;
    int tid = threadIdx.x, wid = tid >> 5, lane = tid & 31;
    int wm = wid & 3, wn = wid >> 2;
    int g = lane >> 2, t = lane & 3;
    int m0 = wm * 16;
    int lrow = tid >> 2, lcol = (tid & 3) * 8;

    {
        const float* qp = Q + (size_t)(q0 + lrow) * ldq + h * HD + lcol;
        float4 a = *reinterpret_cast<const float4*>(qp);
        float4 b = *reinterpret_cast<const float4*>(qp + 4);
        float xv[8] = {a.x, a.y, a.z, a.w, b.x, b.y, b.z, b.w};
#pragma unroll
        for (int j = 0; j < 4; j++) {
            uint32_t hi, lo;
            split_bf16_pair(xv[2 * j] * SCALE, xv[2 * j + 1] * SCALE, hi, lo);
            Qhi[lrow][lcol / 2 + j] = hi;
            Qlo[lrow][lcol / 2 + j] = lo;
        }
    }

    float mrow[2] = {-1e30f, -1e30f}, lsum[2] = {0.f, 0.f};
    float Oacc[4][4] = {};

    for (int kt = 0; kt < LQ; kt += BK) {
        const float* kp = K + (size_t)(kt + lrow) * ldk + h * HD + lcol;
        const float* vp = V + (size_t)(kt + lrow) * ldv + h * HD + lcol;
        float4 ka = *reinterpret_cast<const float4*>(kp);
        float4 kb = *reinterpret_cast<const float4*>(kp + 4);
        float4 va = *reinterpret_cast<const float4*>(vp);
        float4 vb = *reinterpret_cast<const float4*>(vp + 4);
        __syncthreads();
        {
            float kv[8] = {ka.x, ka.y, ka.z, ka.w, kb.x, kb.y, kb.z, kb.w};
#pragma unroll
            for (int j = 0; j < 4; j++) {
                uint32_t hi, lo;
                split_bf16_pair(kv[2 * j], kv[2 * j + 1], hi, lo);
                Khi[lrow][lcol / 2 + j] = hi;
                Klo[lrow][lcol / 2 + j] = lo;
            }
            float vv[8] = {va.x, va.y, va.z, va.w, vb.x, vb.y, vb.z, vb.w};
            __nv_bfloat16* VH = reinterpret_cast<__nv_bfloat16*>(Vthi);
            __nv_bfloat16* VL = reinterpret_cast<__nv_bfloat16*>(Vtlo);
#pragma unroll
            for (int j = 0; j < 8; j++) {
                int d = lcol + j;
                float x = vv[j];
                __nv_bfloat16 hb = __float2bfloat16(x);
                VH[d * 72 + lrow] = hb;
                VL[d * 72 + lrow] = __float2bfloat16(x - __bfloat162float(hb));
            }
        }
        __syncthreads();

        float S[4][4];
#pragma unroll
        for (int nt = 0; nt < 4; nt++)
#pragma unroll
            for (int c = 0; c < 4; c++) S[nt][c] = 0.f;
#pragma unroll
        for (int kc = 0; kc < 2; kc++) {
            uint32_t ah[4], al[4];
            ah[0] = Qhi[m0 + g][kc * 8 + t];     ah[1] = Qhi[m0 + 8 + g][kc * 8 + t];
            ah[2] = Qhi[m0 + g][kc * 8 + t + 4]; ah[3] = Qhi[m0 + 8 + g][kc * 8 + t + 4];
            al[0] = Qlo[m0 + g][kc * 8 + t];     al[1] = Qlo[m0 + 8 + g][kc * 8 + t];
            al[2] = Qlo[m0 + g][kc * 8 + t + 4]; al[3] = Qlo[m0 + 8 + g][kc * 8 + t + 4];
#pragma unroll
            for (int nt = 0; nt < 4; nt++) {
                int kr = wn * 32 + nt * 8 + g;
                uint32_t bh[2] = {Khi[kr][kc * 8 + t], Khi[kr][kc * 8 + t + 4]};
                uint32_t bl[2] = {Klo[kr][kc * 8 + t], Klo[kr][kc * 8 + t + 4]};
                mma_bf16(S[nt], ah, bh);
                mma_bf16(S[nt], ah, bl);
                mma_bf16(S[nt], al, bh);
            }
        }

        float pmA = -1e30f, pmB = -1e30f;
#pragma unroll
        for (int nt = 0; nt < 4; nt++) {
            pmA = fmaxf(pmA, fmaxf(S[nt][0], S[nt][1]));
            pmB = fmaxf(pmB, fmaxf(S[nt][2], S[nt][3]));
        }
        pmA = fmaxf(pmA, __shfl_xor_sync(0xffffffffu, pmA, 1));
        pmA = fmaxf(pmA, __shfl_xor_sync(0xffffffffu, pmA, 2));
        pmB = fmaxf(pmB, __shfl_xor_sync(0xffffffffu, pmB, 1));
        pmB = fmaxf(pmB, __shfl_xor_sync(0xffffffffu, pmB, 2));
        if (t == 0) {
            redmax[wn][m0 + g] = pmA;
            redmax[wn][m0 + 8 + g] = pmB;
        }
        __syncthreads();
        float nmA = fmaxf(mrow[0], fmaxf(redmax[0][m0 + g], redmax[1][m0 + g]));
        float nmB = fmaxf(mrow[1], fmaxf(redmax[0][m0 + 8 + g], redmax[1][m0 + 8 + g]));
        float alA = __expf(mrow[0] - nmA), alB = __expf(mrow[1] - nmB);
        mrow[0] = nmA; mrow[1] = nmB;
        float psA = 0.f, psB = 0.f;
#pragma unroll
        for (int nt = 0; nt < 4; nt++) {
            S[nt][0] = __expf(S[nt][0] - nmA); S[nt][1] = __expf(S[nt][1] - nmA);
            S[nt][2] = __expf(S[nt][2] - nmB); S[nt][3] = __expf(S[nt][3] - nmB);
            psA += S[nt][0] + S[nt][1];
            psB += S[nt][2] + S[nt][3];
        }
        psA += __shfl_xor_sync(0xffffffffu, psA, 1);
        psA += __shfl_xor_sync(0xffffffffu, psA, 2);
        psB += __shfl_xor_sync(0xffffffffu, psB, 1);
        psB += __shfl_xor_sync(0xffffffffu, psB, 2);
        if (t == 0) {
            redsum[wn][m0 + g] = psA;
            redsum[wn][m0 + 8 + g] = psB;
        }
#pragma unroll
        for (int nt = 0; nt < 4; nt++) {
            Oacc[nt][0] *= alA; Oacc[nt][1] *= alA;
            Oacc[nt][2] *= alB; Oacc[nt][3] *= alB;
        }
        __syncthreads();
        lsum[0] = lsum[0] * alA + redsum[0][m0 + g] + redsum[1][m0 + g];
        lsum[1] = lsum[1] * alB + redsum[0][m0 + 8 + g] + redsum[1][m0 + 8 + g];

#pragma unroll
        for (int kc2 = 0; kc2 < 2; kc2++) {
            uint32_t ph[4], pl[4];
            split_bf16_pair(S[2 * kc2][0], S[2 * kc2][1], ph[0], pl[0]);
            split_bf16_pair(S[2 * kc2][2], S[2 * kc2][3], ph[1], pl[1]);
            split_bf16_pair(S[2 * kc2 + 1][0], S[2 * kc2 + 1][1], ph[2], pl[2]);
            split_bf16_pair(S[2 * kc2 + 1][2], S[2 * kc2 + 1][3], ph[3], pl[3]);
            int cb = wn * 16 + kc2 * 8 + t;
#pragma unroll
            for (int ntv = 0; ntv < 4; ntv++) {
                int vr = ntv * 8 + g;
                uint32_t bh[2] = {Vthi[vr][cb], Vthi[vr][cb + 4]};
                uint32_t bl[2] = {Vtlo[vr][cb], Vtlo[vr][cb + 4]};
                mma_bf16(Oacc[ntv], ph, bh);
                mma_bf16(Oacc[ntv], ph, bl);
                mma_bf16(Oacc[ntv], pl, bh);
            }
        }
    }

    if (wn == 0) {
#pragma unroll
        for (int ntv = 0; ntv < 4; ntv++) {
            int d = ntv * 8 + 2 * t;
            Osm[m0 + g][d] = Oacc[ntv][0];
            Osm[m0 + g][d + 1] = Oacc[ntv][1];
            Osm[m0 + 8 + g][d] = Oacc[ntv][2];
            Osm[m0 + 8 + g][d + 1] = Oacc[ntv][3];
        }
    }
    __syncthreads();
    if (wn == 1) {
        float invA = 1.0f / lsum[0], invB = 1.0f / lsum[1];
#pragma unroll
        for (int ntv = 0; ntv < 4; ntv++) {
            int d = ntv * 8 + 2 * t;
            float* op0 = O + (size_t)(q0 + m0 + g) * CD + h * HD + d;
            float* op1 = O + (size_t)(q0 + m0 + 8 + g) * CD + h * HD + d;
            op0[0] = (Oacc[ntv][0] + Osm[m0 + g][d]) * invA;
            op0[1] = (Oacc[ntv][1] + Osm[m0 + g][d + 1]) * invA;
            op1[0] = (Oacc[ntv][2] + Osm[m0 + 8 + g][d]) * invB;
            op1[1] = (Oacc[ntv][3] + Osm[m0 + 8 + g][d + 1]) * invB;
        }
    }
}

// ---------------- tiled local attention ----------------
__global__ __launch_bounds__(256) void local_attn_tile(
        const float* __restrict__ Q, int ldq,
        const float* __restrict__ K, const float* __restrict__ V,
        float* __restrict__ O) {
    extern __shared__ float sm[];
    float* winK = sm;
    float* winV = sm + LTWW * 33;
    float* pb = sm + 2 * LTWW * 33;
    int h = blockIdx.y;
    int ty0 = (blockIdx.x / 5) * 8, tx0 = (blockIdx.x % 5) * 8;
    int wy0 = ty0 - PADR, wx0 = tx0 - PADR;
    int tid = threadIdx.x, w = tid >> 5, lane = tid & 31;

    for (int idx = tid; idx < LTWW * 32; idx += 256) {
        int pos = idx >> 5, d = idx & 31;
        int gy = wy0 + pos / LTW, gx = wx0 + pos % LTW;
        bool ok = ((unsigned)gy < H2D) && ((unsigned)gx < W2D);
        size_t goff = (size_t)(gy * W2D + gx) * CD + h * HD + d;
        winK[pos * 33 + d] = ok ? K[goff] : 0.f;
        winV[pos * 33 + d] = ok ? V[goff] : 0.f;
    }
    __syncthreads();

    int qy = ty0 + w;
    for (int qi = 0; qi < 8; qi++) {
        int qx = tx0 + qi;
        float qv = Q[(size_t)(qy * W2D + qx) * ldq + h * HD + lane] * SCALE;
        float lg[8];
        int wi[8];
        bool val[8];
#pragma unroll
        for (int c = 0; c < 8; c++) {
            int j = c * 32 + lane;
            int jr = j / 15, jc = j - jr * 15;
            int gy2 = qy + jr - PADR, gx2 = qx + jc - PADR;
            val[c] = (j < WSQ) && ((unsigned)gy2 < H2D) && ((unsigned)gx2 < W2D);
            wi[c] = (j < WSQ) ? ((w + jr) * LTW + (qi + jc)) : 0;
            lg[c] = 0.f;
        }
#pragma unroll 8
        for (int d = 0; d < 32; d++) {
            float qd = __shfl_sync(0xffffffffu, qv, d);
#pragma unroll
            for (int c = 0; c < 8; c++)
                lg[c] = fmaf(qd, winK[wi[c] * 33 + d], lg[c]);
        }
        float mx = -1e30f;
#pragma unroll
        for (int c = 0; c < 8; c++) {
            lg[c] = val[c] ? lg[c] : -1e30f;
            mx = fmaxf(mx, lg[c]);
        }
#pragma unroll
        for (int o = 16; o; o >>= 1) mx = fmaxf(mx, __shfl_xor_sync(0xffffffffu, mx, o));
        float s = 0.f;
#pragma unroll
        for (int c = 0; c < 8; c++) {
            lg[c] = __expf(lg[c] - mx);
            s += lg[c];
        }
#pragma unroll
        for (int o = 16; o; o >>= 1) s += __shfl_xor_sync(0xffffffffu, s, o);
        float inv = 1.0f / s;
#pragma unroll
        for (int c = 0; c < 8; c++) pb[w * 264 + c * 32 + lane] = lg[c] * inv;
        __syncwarp();

        float oacc = 0.f;
        int j = 0;
#pragma unroll
        for (int jr = 0; jr < 15; jr++) {
            int base = ((w + jr) * LTW + qi) * 33 + lane;
#pragma unroll
            for (int jc = 0; jc < 15; jc++) {
                oacc = fmaf(pb[w * 264 + j], winV[base + jc * 33], oacc);
                j++;
            }
        }
        O[(size_t)(qy * W2D + qx) * CD + h * HD + lane] = oacc;
        __syncwarp();
    }
}

// ---------------- global K/V construction ----------------
__global__ void make_global_kv(const float* __restrict__ qv, const float* __restrict__ idkv,
                               float* __restrict__ gK, float* __restrict__ gV) {
    int i = blockIdx.x * blockDim.x + threadIdx.x;
    if (i >= LQ * CD) return;
    int l = i >> 8, c = i & 255, h = c >> 5;
    float ik = idkv[l * 264 + h];
    gK[i] = qv[(size_t)l * 512 + c] * (1.0f + tanhf(ik));
    gV[i] = qv[(size_t)l * 512 + 256 + c] + idkv[l * 264 + 8 + c];
}

// ---------------- GroupNorm stats ----------------
__global__ void gn_stats(const float* __restrict__ x, float* __restrict__ stats) {
    __shared__ float red[32];
    int g = blockIdx.x;
    float s = 0.f, ss = 0.f;
    for (int i = threadIdx.x; i < LQ * 32; i += blockDim.x) {
        int l = i >> 5, c = (g << 5) + (i & 31);
        float v = x[(size_t)l * DFF + c];
        s += v;
        ss = fmaf(v, v, ss);
    }
    s = block_reduce(s, red, false);
    ss = block_reduce(ss, red, false);
    if (!threadIdx.x) {
        const float inv = 1.0f / (LQ * 32.0f);
        float m = s * inv;
        float var = ss * inv - m * m;
        stats[g * 2] = m;
        stats[g * 2 + 1] = rsqrtf(var + 1e-5f);
    }
}

// ---------------- GN apply + affine + exact GELU ----------------
__global__ void gn_apply_gelu(const float* __restrict__ x, const float* __restrict__ stats,
                              const float* __restrict__ gg, const float* __restrict__ gb,
                              float* __restrict__ y) {
    int i = blockIdx.x * blockDim.x + threadIdx.x;
    if (i >= LQ * DFF) return;
    int c = i & (DFF - 1);
    int grp = c >> 5;
    float m = stats[grp * 2], r = stats[grp * 2 + 1];
    float v = (x[i] - m) * r * gg[c] + gb[c];
    y[i] = 0.5f * v * (1.0f + erff(v * 0.70710678118654752f));
}

// ---------------- depthwise 5x5 conv, pad 2 ----------------
__global__ void dwconv_kernel(const float* __restrict__ x, const float* __restrict__ k,
                              float* __restrict__ y) {
    int l = blockIdx.x;
    int yy = l / W2D, xx = l % W2D;
    for (int c = threadIdx.x; c < DFF; c += blockDim.x) {
        float acc = 0.f;
#pragma unroll
        for (int i = 0; i < 5; i++) {
            int ny = yy + i - 2;
            if (ny < 0 || ny >= H2D) continue;
#pragma unroll
            for (int j = 0; j < 5; j++) {
                int nx = xx + j - 2;
                if (nx < 0 || nx >= W2D) continue;
                acc = fmaf(x[(size_t)(ny * W2D + nx) * DFF + c], k[c * 25 + i * 5 + j], acc);
            }
        }
        y[(size_t)l * DFF + c] = acc;
    }
}

// ---------------- host ----------------
static const int GEMM_SMEM = 4 * GSEG * (int)sizeof(uint32_t);  // 67,584 B

static void launch_gemm(const float* A, const float* W, const float* bias, const float* res,
                        float* C, int M, int N, int K) {
    dim3 grid((N + 63) / 64, (M + 63) / 64);
    gemm_tc<<<grid, 256, GEMM_SMEM>>>(A, W, bias, res, C, M, N, K);
}

extern "C" void kernel_launch(void* const* d_in, const int* in_sizes, int n_in,
                              void* d_out, int out_size) {
    const float* tgt = (const float*)d_in[0];
    const float* curr_id_emb = (const float*)d_in[1];
    const float* self_pos = (const float*)d_in[2];
    const float* ln1_g = (const float*)d_in[3];
    const float* ln1_b = (const float*)d_in[4];
    const float* sa_wq = (const float*)d_in[5];
    const float* sa_bq = (const float*)d_in[6];
    const float* sa_wk = (const float*)d_in[7];
    const float* sa_bk = (const float*)d_in[8];
    const float* sa_wv = (const float*)d_in[9];
    const float* sa_bv = (const float*)d_in[10];
    const float* sa_wo = (const float*)d_in[11];
    const float* sa_bo = (const float*)d_in[12];
    const float* ln2_g = (const float*)d_in[13];
    const float* ln2_b = (const float*)d_in[14];
    const float* w_qv = (const float*)d_in[15];
    const float* b_qv = (const float*)d_in[16];
    const float* w_id = (const float*)d_in[17];
    const float* b_id = (const float*)d_in[18];
    const float* lt_wo = (const float*)d_in[19];
    const float* lt_bo = (const float*)d_in[20];
    const float* st_wo = (const float*)d_in[21];
    const float* st_bo = (const float*)d_in[22];
    const float* ln3_g = (const float*)d_in[23];
    const float* ln3_b = (const float*)d_in[24];
    const float* w1 = (const float*)d_in[25];
    const float* b1 = (const float*)d_in[26];
    const float* gn_g = (const float*)d_in[27];
    const float* gn_b = (const float*)d_in[28];
    const float* dw_k = (const float*)d_in[29];
    const float* w2 = (const float*)d_in[30];
    const float* b2 = (const float*)d_in[31];
    float* out = (float*)d_out;

    float *tln, *qkin, *q, *k, *v, *att, *tgt1, *qv, *idkv, *gK, *gV, *st, *tmp, *tgt2, *x1, *x2, *gn;
    cudaGetSymbolAddress((void**)&tln, g_tln);
    cudaGetSymbolAddress((void**)&qkin, g_qkin);
    cudaGetSymbolAddress((void**)&q, g_q);
    cudaGetSymbolAddress((void**)&k, g_k);
    cudaGetSymbolAddress((void**)&v, g_v);
    cudaGetSymbolAddress((void**)&att, g_att);
    cudaGetSymbolAddress((void**)&tgt1, g_tgt1);
    cudaGetSymbolAddress((void**)&qv, g_qv);
    cudaGetSymbolAddress((void**)&idkv, g_idkv);
    cudaGetSymbolAddress((void**)&gK, g_gK);
    cudaGetSymbolAddress((void**)&gV, g_gV);
    cudaGetSymbolAddress((void**)&st, g_st);
    cudaGetSymbolAddress((void**)&tmp, g_tmp);
    cudaGetSymbolAddress((void**)&tgt2, g_tgt2);
    cudaGetSymbolAddress((void**)&x1, g_x1);
    cudaGetSymbolAddress((void**)&x2, g_x2);
    cudaGetSymbolAddress((void**)&gn, g_gn);

    const int LOCAL_SMEM = (2 * LTWW * 33 + 8 * 264) * (int)sizeof(float);
    cudaFuncSetAttribute(local_attn_tile, cudaFuncAttributeMaxDynamicSharedMemorySize, LOCAL_SMEM);
    cudaFuncSetAttribute(gemm_tc, cudaFuncAttributeMaxDynamicSharedMemorySize, GEMM_SMEM);

    // ---- self-attention block ----
    ln_kernel<<<LQ, 256>>>(tgt, ln1_g, ln1_b, tln, self_pos, qkin);
    launch_gemm(qkin, sa_wq, sa_bq, nullptr, q, LQ, CD, CD);
    launch_gemm(qkin, sa_wk, sa_bk, nullptr, k, LQ, CD, CD);
    launch_gemm(tln, sa_wv, sa_bv, nullptr, v, LQ, CD, CD);
    flash_attn_tc<<<dim3(LQ / BQ, NH), 256>>>(q, CD, k, CD, v, CD, att);
    launch_gemm(att, sa_wo, sa_bo, tgt, tgt1, LQ, CD, CD);   // tgt1 = tgt + SA(tgt)

    // ---- long/short-term block ----
    ln_kernel<<<LQ, 256>>>(tgt1, ln2_g, ln2_b, tln, nullptr, nullptr);
    launch_gemm(tln, w_qv, b_qv, nullptr, qv, LQ, 512, CD);          // [curr_Q|curr_V]
    launch_gemm(curr_id_emb, w_id, b_id, nullptr, idkv, LQ, CD + NH, CD);
    make_global_kv<<<(LQ * CD + 255) / 256, 256>>>(qv, idkv, gK, gV);
    flash_attn_tc<<<dim3(LQ / BQ, NH), 256>>>(qv, 512, gK, CD, gV, CD, att);
    launch_gemm(att, lt_wo, lt_bo, tgt1, tmp, LQ, CD, CD);   // tmp = tgt1 + LT
    local_attn_tile<<<dim3(25, NH), 256, LOCAL_SMEM>>>(qv, 512, gK, gV, st);
    launch_gemm(st, st_wo, st_bo, tmp, tgt2, LQ, CD, CD);    // tgt2 = tgt1 + LT + ST

    // ---- FFN block ----
    ln_kernel<<<LQ, 256>>>(tgt2, ln3_g, ln3_b, tln, nullptr, nullptr);
    launch_gemm(tln, w1, b1, nullptr, x1, LQ, DFF, CD);
    gn_stats<<<32, 256>>>(x1, gn);
    gn_apply_gelu<<<(LQ * DFF + 255) / 256, 256>>>(x1, gn, gn_g, gn_b, x2);
    dwconv_kernel<<<LQ, 256>>>(x2, dw_k, x1);
    launch_gemm(x1, w2, b2, tgt2, out, LQ, CD, DFF);         // out = tgt2 + FFN
}

// round 7
// speedup vs baseline: 14.1056x; 1.1085x over previous
#include <cuda_runtime.h>
#include <cuda_bf16.h>
#include <math.h>
#include <stdint.h>

#define LQ 1600
#define CD 256
#define NH 8
#define HD 32
#define DFF 1024
#define H2D 40
#define W2D 40
#define WS 15
#define WSQ 225
#define PADR 7
#define SCALE 0.17677669529663687f  // 1/sqrt(32)

#define BQ 64
#define BK 64
#define LTW 22
#define LTWW (LTW * LTW)  // 484

// GEMM chunking
#define KC 128            // K floats staged per chunk (= 64 pairs)
#define KPP 68            // padded row stride in words; 68%32=4 -> conflict-free frag reads, 16B-aligned rows
#define GSEG (64 * KPP)

// preconverted weight segment offsets (in bf16x2 pairs)
#define OFF_QK   0         // [512,256]  wq rows 0-255, wk rows 256-511
#define OFF_WV   65536     // [256,256]
#define OFF_WO   98304     // [256,256]
#define OFF_WQV  131072    // [512,256]
#define OFF_WID  196608    // [264,256]
#define OFF_LTST 230400    // [256,512]  k-concat: k<256 lt_wo, k>=256 st_wo
#define OFF_W1   295936    // [1024,256]
#define OFF_W2   427008    // [256,1024]
#define TOTPAIRS 558080

// ---------------- scratch (device globals; no allocation) ----------------
__device__ float g_tln[LQ * CD];
__device__ float g_qkin[LQ * CD];
__device__ float g_qk[LQ * 512];     // [q | k]
__device__ float g_v[LQ * CD];
__device__ float g_cat[LQ * 512];    // [lt-attn out | st-attn out] (also 1st attn out in cols 0-255)
__device__ float g_tgt1[LQ * CD];
__device__ float g_qv[LQ * 512];     // [curr_Q | curr_V]
__device__ float g_idkv[LQ * 264];
__device__ float g_gK[LQ * CD];
__device__ float g_gV[LQ * CD];
__device__ float g_tgt2[LQ * CD];
__device__ float g_x1[LQ * DFF];
__device__ float g_x2[LQ * DFF];
__device__ float g_gn[32 * 2];
__device__ __align__(16) uint32_t g_whi[TOTPAIRS];
__device__ __align__(16) uint32_t g_wlo[TOTPAIRS];
__device__ float g_bqk[512];
__device__ float g_bltst[256];

// ---------------- mma helpers ----------------
__device__ __forceinline__ void mma_bf16(float* c, const uint32_t* a, const uint32_t* b) {
    asm volatile(
        "mma.sync.aligned.m16n8k16.row.col.f32.bf16.bf16.f32 "
        "{%0,%1,%2,%3}, {%4,%5,%6,%7}, {%8,%9}, {%0,%1,%2,%3};"
        : "+f"(c[0]), "+f"(c[1]), "+f"(c[2]), "+f"(c[3])
        : "r"(a[0]), "r"(a[1]), "r"(a[2]), "r"(a[3]), "r"(b[0]), "r"(b[1]));
}

__device__ __forceinline__ uint32_t pack_bf16(float lo, float hi) {
    uint32_t r;
    asm("cvt.rn.bf16x2.f32 %0, %1, %2;" : "=r"(r) : "f"(hi), "f"(lo));
    return r;
}

__device__ __forceinline__ void split_bf16_pair(float x0, float x1, uint32_t& hi, uint32_t& lo) {
    hi = pack_bf16(x0, x1);
    float h0 = __uint_as_float(hi << 16);
    float h1 = __uint_as_float(hi & 0xffff0000u);
    lo = pack_bf16(x0 - h0, x1 - h1);
}

// ---------------- weight pre-conversion (once per launch) ----------------
__global__ void conv_weights(
        const float* __restrict__ wq, const float* __restrict__ wk,
        const float* __restrict__ wv, const float* __restrict__ wo,
        const float* __restrict__ wqv, const float* __restrict__ wid,
        const float* __restrict__ wlt, const float* __restrict__ wst,
        const float* __restrict__ w1, const float* __restrict__ w2,
        const float* __restrict__ bq, const float* __restrict__ bk,
        const float* __restrict__ blt, const float* __restrict__ bst) {
    int p = blockIdx.x * 256 + threadIdx.x;
    if (p < 256) {
        g_bqk[p] = bq[p];
        g_bqk[256 + p] = bk[p];
        g_bltst[p] = blt[p] + bst[p];
    }
    if (p >= TOTPAIRS) return;
    const float* src;
    int idx;
    if (p < OFF_WV) {
        src = (p < 32768) ? wq : wk;
        idx = (p & 32767) * 2;
    } else if (p < OFF_WO) { src = wv; idx = (p - OFF_WV) * 2; }
    else if (p < OFF_WQV) { src = wo; idx = (p - OFF_WO) * 2; }
    else if (p < OFF_WID) { src = wqv; idx = (p - OFF_WQV) * 2; }
    else if (p < OFF_LTST) { src = wid; idx = (p - OFF_WID) * 2; }
    else if (p < OFF_W1) {
        int lp = p - OFF_LTST;
        int n = lp >> 8, c = lp & 255;
        if (c < 128) { src = wlt; idx = (n * 128 + c) * 2; }
        else { src = wst; idx = (n * 128 + c - 128) * 2; }
    } else if (p < OFF_W2) { src = w1; idx = (p - OFF_W1) * 2; }
    else { src = w2; idx = (p - OFF_W2) * 2; }
    uint32_t hi, lo;
    split_bf16_pair(src[idx], src[idx + 1], hi, lo);
    g_whi[p] = hi;
    g_wlo[p] = lo;
}

// ---------------- reductions ----------------
__device__ __forceinline__ float block_reduce(float v, float* red, bool is_max) {
    int lane = threadIdx.x & 31, wid = threadIdx.x >> 5;
#pragma unroll
    for (int o = 16; o; o >>= 1) {
        float u = __shfl_xor_sync(0xffffffffu, v, o);
        v = is_max ? fmaxf(v, u) : v + u;
    }
    if (!lane) red[wid] = v;
    __syncthreads();
    int nw = (blockDim.x + 31) >> 5;
    v = (lane < nw) ? red[lane] : (is_max ? -1e30f : 0.0f);
    if (!wid) {
#pragma unroll
        for (int o = 16; o; o >>= 1) {
            float u = __shfl_xor_sync(0xffffffffu, v, o);
            v = is_max ? fmaxf(v, u) : v + u;
        }
        if (!lane) red[0] = v;
    }
    __syncthreads();
    v = red[0];
    __syncthreads();
    return v;
}

// ---------------- LayerNorm ----------------
__global__ void ln_kernel(const float* __restrict__ in, const float* __restrict__ g,
                          const float* __restrict__ b, float* __restrict__ out,
                          const float* __restrict__ pos, float* __restrict__ out2) {
    __shared__ float red[32];
    int l = blockIdx.x, c = threadIdx.x;
    float x = in[l * CD + c];
    float m = block_reduce(x, red, false) * (1.0f / CD);
    float d = x - m;
    float var = block_reduce(d * d, red, false) * (1.0f / CD);
    float y = d * rsqrtf(var + 1e-5f) * g[c] + b[c];
    out[l * CD + c] = y;
    if (out2) out2[l * CD + c] = y + pos[l * CD + c];
}

// ---------------- bf16-split tensor-core GEMM, preconverted W ----------------
// C[m,n] = sum_k A[m,k]*W[n,k] + bias[n] (+res), A fp32 (lda stride), W bf16 hi/lo pairs.
// BM=BN=64, K chunked by 128, register double-buffered. M%64==0, K%128==0.
__global__ __launch_bounds__(256) void gemm_tc2(
        const float* __restrict__ A, int lda,
        const uint32_t* __restrict__ Whg, const uint32_t* __restrict__ Wlg,
        const float* __restrict__ bias, const float* __restrict__ res,
        float* __restrict__ C, int M, int N, int K) {
    extern __shared__ uint32_t su[];
    uint32_t* Ah = su;
    uint32_t* Al = su + GSEG;
    uint32_t* Wh = su + 2 * GSEG;
    uint32_t* Wl = su + 3 * GSEG;

    int tid = threadIdx.x;
    int bm = blockIdx.y * 64, bn = blockIdx.x * 64;
    int wid = tid >> 5, lane = tid & 31;
    int wm = wid & 3, wn = wid >> 2;
    int g = lane >> 2, t = lane & 3;
    int m0 = wm * 16;
    int Kp = K >> 1;
    float acc[4][4] = {};

    int srow = tid >> 2, sc0 = tid & 3;
    bool wok = (bn + srow) < N;
    const float* Ap = A + (size_t)(bm + srow) * lda;
    const uint32_t* Whp = Whg + (size_t)(wok ? bn + srow : 0) * Kp;
    const uint32_t* Wlp = Wlg + (size_t)(wok ? bn + srow : 0) * Kp;

    float4 pa[8];
    uint4 pwh[4], pwl[4];
    const uint4 z4 = make_uint4(0, 0, 0, 0);

#define LOADCHUNK(k0)                                                          \
    {                                                                          \
        int kp0 = (k0) >> 1;                                                   \
        _Pragma("unroll")                                                      \
        for (int i = 0; i < 4; i++) {                                          \
            int cA = (k0) + (2 * sc0 + 8 * i) * 4;                             \
            pa[2 * i] = *reinterpret_cast<const float4*>(Ap + cA);             \
            pa[2 * i + 1] = *reinterpret_cast<const float4*>(Ap + cA + 4);     \
            int pp = kp0 + (sc0 + 4 * i) * 4;                                  \
            pwh[i] = wok ? *reinterpret_cast<const uint4*>(Whp + pp) : z4;     \
            pwl[i] = wok ? *reinterpret_cast<const uint4*>(Wlp + pp) : z4;     \
        }                                                                      \
    }

    LOADCHUNK(0)

    for (int k0 = 0; k0 < K; k0 += KC) {
        if (k0) __syncthreads();
#pragma unroll
        for (int i = 0; i < 4; i++) {
            int pp = (sc0 + 4 * i) * 4;
            uint32_t h0, l0, h1, l1, h2, l2, h3, l3;
            split_bf16_pair(pa[2 * i].x, pa[2 * i].y, h0, l0);
            split_bf16_pair(pa[2 * i].z, pa[2 * i].w, h1, l1);
            split_bf16_pair(pa[2 * i + 1].x, pa[2 * i + 1].y, h2, l2);
            split_bf16_pair(pa[2 * i + 1].z, pa[2 * i + 1].w, h3, l3);
            *reinterpret_cast<uint4*>(&Ah[srow * KPP + pp]) = make_uint4(h0, h1, h2, h3);
            *reinterpret_cast<uint4*>(&Al[srow * KPP + pp]) = make_uint4(l0, l1, l2, l3);
            *reinterpret_cast<uint4*>(&Wh[srow * KPP + pp]) = pwh[i];
            *reinterpret_cast<uint4*>(&Wl[srow * KPP + pp]) = pwl[i];
        }
        __syncthreads();
        if (k0 + KC < K) LOADCHUNK(k0 + KC)

#pragma unroll
        for (int ks = 0; ks < KC / 16; ks++) {
            int kb = ks * 8 + t;
            uint32_t ah[4], al[4];
            ah[0] = Ah[(m0 + g) * KPP + kb];
            ah[1] = Ah[(m0 + 8 + g) * KPP + kb];
            ah[2] = Ah[(m0 + g) * KPP + kb + 4];
            ah[3] = Ah[(m0 + 8 + g) * KPP + kb + 4];
            al[0] = Al[(m0 + g) * KPP + kb];
            al[1] = Al[(m0 + 8 + g) * KPP + kb];
            al[2] = Al[(m0 + g) * KPP + kb + 4];
            al[3] = Al[(m0 + 8 + g) * KPP + kb + 4];
#pragma unroll
            for (int nt = 0; nt < 4; nt++) {
                int nr = wn * 32 + nt * 8 + g;
                uint32_t bh[2] = {Wh[nr * KPP + kb], Wh[nr * KPP + kb + 4]};
                uint32_t bl[2] = {Wl[nr * KPP + kb], Wl[nr * KPP + kb + 4]};
                mma_bf16(acc[nt], ah, bh);
                mma_bf16(acc[nt], ah, bl);
                mma_bf16(acc[nt], al, bh);
            }
        }
    }

    int mo = bm + m0 + g;
    if (bn + 64 <= N) {
#pragma unroll
        for (int nt = 0; nt < 4; nt++) {
            int n = bn + wn * 32 + nt * 8 + 2 * t;
            float2 bv = *reinterpret_cast<const float2*>(bias + n);
            size_t o0 = (size_t)mo * N + n;
            size_t o1 = (size_t)(mo + 8) * N + n;
            float2 r0 = make_float2(acc[nt][0] + bv.x, acc[nt][1] + bv.y);
            float2 r1 = make_float2(acc[nt][2] + bv.x, acc[nt][3] + bv.y);
            if (res) {
                float2 e0 = *reinterpret_cast<const float2*>(res + o0);
                float2 e1 = *reinterpret_cast<const float2*>(res + o1);
                r0.x += e0.x; r0.y += e0.y; r1.x += e1.x; r1.y += e1.y;
            }
            *reinterpret_cast<float2*>(C + o0) = r0;
            *reinterpret_cast<float2*>(C + o1) = r1;
        }
    } else {
#pragma unroll
        for (int nt = 0; nt < 4; nt++) {
            int n = bn + wn * 32 + nt * 8 + 2 * t;
#pragma unroll
            for (int e = 0; e < 2; e++) {
                if (n + e >= N) continue;
                float v0 = acc[nt][e] + bias[n + e];
                float v1 = acc[nt][2 + e] + bias[n + e];
                if (res) {
                    v0 += res[(size_t)mo * N + n + e];
                    v1 += res[(size_t)(mo + 8) * N + n + e];
                }
                C[(size_t)mo * N + n + e] = v0;
                C[(size_t)(mo + 8) * N + n + e] = v1;
            }
        }
    }
#undef LOADCHUNK
}

// ---------------- tensor-core flash attention (bf16 hi/lo split) ----------------
__global__ __launch_bounds__(256) void flash_attn_tc(
        const float* __restrict__ Q, int ldq,
        const float* __restrict__ K, int ldk,
        const float* __restrict__ V, int ldv,
        float* __restrict__ O, int ldo) {
    __shared__ uint32_t Qhi[64][20], Qlo[64][20];
    __shared__ uint32_t Khi[64][20], Klo[64][20];
    __shared__ uint32_t Vthi[32][36], Vtlo[32][36];
    __shared__ float redmax[2][64], redsum[2][64];
    __shared__ float Osm[64][33];

    int h = blockIdx.y, q0 = blockIdx.x * BQ;
    int tid = threadIdx.x, wid = tid >> 5, lane = tid & 31;
    int wm = wid & 3, wn = wid >> 2;
    int g = lane >> 2, t = lane & 3;
    int m0 = wm * 16;
    int lrow = tid >> 2, lcol = (tid & 3) * 8;

    {
        const float* qp = Q + (size_t)(q0 + lrow) * ldq + h * HD + lcol;
        float4 a = *reinterpret_cast<const float4*>(qp);
        float4 b = *reinterpret_cast<const float4*>(qp + 4);
        float xv[8] = {a.x, a.y, a.z, a.w, b.x, b.y, b.z, b.w};
#pragma unroll
        for (int j = 0; j < 4; j++) {
            uint32_t hi, lo;
            split_bf16_pair(xv[2 * j] * SCALE, xv[2 * j + 1] * SCALE, hi, lo);
            Qhi[lrow][lcol / 2 + j] = hi;
            Qlo[lrow][lcol / 2 + j] = lo;
        }
    }

    float mrow[2] = {-1e30f, -1e30f}, lsum[2] = {0.f, 0.f};
    float Oacc[4][4] = {};

    for (int kt = 0; kt < LQ; kt += BK) {
        const float* kp = K + (size_t)(kt + lrow) * ldk + h * HD + lcol;
        const float* vp = V + (size_t)(kt + lrow) * ldv + h * HD + lcol;
        float4 ka = *reinterpret_cast<const float4*>(kp);
        float4 kb = *reinterpret_cast<const float4*>(kp + 4);
        float4 va = *reinterpret_cast<const float4*>(vp);
        float4 vb = *reinterpret_cast<const float4*>(vp + 4);
        __syncthreads();
        {
            float kv[8] = {ka.x, ka.y, ka.z, ka.w, kb.x, kb.y, kb.z, kb.w};
#pragma unroll
            for (int j = 0; j < 4; j++) {
                uint32_t hi, lo;
                split_bf16_pair(kv[2 * j], kv[2 * j + 1], hi, lo);
                Khi[lrow][lcol / 2 + j] = hi;
                Klo[lrow][lcol / 2 + j] = lo;
            }
            float vv[8] = {va.x, va.y, va.z, va.w, vb.x, vb.y, vb.z, vb.w};
            __nv_bfloat16* VH = reinterpret_cast<__nv_bfloat16*>(Vthi);
            __nv_bfloat16* VL = reinterpret_cast<__nv_bfloat16*>(Vtlo);
#pragma unroll
            for (int j = 0; j < 8; j++) {
                int d = lcol + j;
                float x = vv[j];
                __nv_bfloat16 hb = __float2bfloat16(x);
                VH[d * 72 + lrow] = hb;
                VL[d * 72 + lrow] = __float2bfloat16(x - __bfloat162float(hb));
            }
        }
        __syncthreads();

        float S[4][4];
#pragma unroll
        for (int nt = 0; nt < 4; nt++)
#pragma unroll
            for (int c = 0; c < 4; c++) S[nt][c] = 0.f;
#pragma unroll
        for (int kc = 0; kc < 2; kc++) {
            uint32_t ah[4], al[4];
            ah[0] = Qhi[m0 + g][kc * 8 + t];     ah[1] = Qhi[m0 + 8 + g][kc * 8 + t];
            ah[2] = Qhi[m0 + g][kc * 8 + t + 4]; ah[3] = Qhi[m0 + 8 + g][kc * 8 + t + 4];
            al[0] = Qlo[m0 + g][kc * 8 + t];     al[1] = Qlo[m0 + 8 + g][kc * 8 + t];
            al[2] = Qlo[m0 + g][kc * 8 + t + 4]; al[3] = Qlo[m0 + 8 + g][kc * 8 + t + 4];
#pragma unroll
            for (int nt = 0; nt < 4; nt++) {
                int kr = wn * 32 + nt * 8 + g;
                uint32_t bh[2] = {Khi[kr][kc * 8 + t], Khi[kr][kc * 8 + t + 4]};
                uint32_t bl[2] = {Klo[kr][kc * 8 + t], Klo[kr][kc * 8 + t + 4]};
                mma_bf16(S[nt], ah, bh);
                mma_bf16(S[nt], ah, bl);
                mma_bf16(S[nt], al, bh);
            }
        }

        float pmA = -1e30f, pmB = -1e30f;
#pragma unroll
        for (int nt = 0; nt < 4; nt++) {
            pmA = fmaxf(pmA, fmaxf(S[nt][0], S[nt][1]));
            pmB = fmaxf(pmB, fmaxf(S[nt][2], S[nt][3]));
        }
        pmA = fmaxf(pmA, __shfl_xor_sync(0xffffffffu, pmA, 1));
        pmA = fmaxf(pmA, __shfl_xor_sync(0xffffffffu, pmA, 2));
        pmB = fmaxf(pmB, __shfl_xor_sync(0xffffffffu, pmB, 1));
        pmB = fmaxf(pmB, __shfl_xor_sync(0xffffffffu, pmB, 2));
        if (t == 0) {
            redmax[wn][m0 + g] = pmA;
            redmax[wn][m0 + 8 + g] = pmB;
        }
        __syncthreads();
        float nmA = fmaxf(mrow[0], fmaxf(redmax[0][m0 + g], redmax[1][m0 + g]));
        float nmB = fmaxf(mrow[1], fmaxf(redmax[0][m0 + 8 + g], redmax[1][m0 + 8 + g]));
        float alA = __expf(mrow[0] - nmA), alB = __expf(mrow[1] - nmB);
        mrow[0] = nmA; mrow[1] = nmB;
        float psA = 0.f, psB = 0.f;
#pragma unroll
        for (int nt = 0; nt < 4; nt++) {
            S[nt][0] = __expf(S[nt][0] - nmA); S[nt][1] = __expf(S[nt][1] - nmA);
            S[nt][2] = __expf(S[nt][2] - nmB); S[nt][3] = __expf(S[nt][3] - nmB);
            psA += S[nt][0] + S[nt][1];
            psB += S[nt][2] + S[nt][3];
        }
        psA += __shfl_xor_sync(0xffffffffu, psA, 1);
        psA += __shfl_xor_sync(0xffffffffu, psA, 2);
        psB += __shfl_xor_sync(0xffffffffu, psB, 1);
        psB += __shfl_xor_sync(0xffffffffu, psB, 2);
        if (t == 0) {
            redsum[wn][m0 + g] = psA;
            redsum[wn][m0 + 8 + g] = psB;
        }
#pragma unroll
        for (int nt = 0; nt < 4; nt++) {
            Oacc[nt][0] *= alA; Oacc[nt][1] *= alA;
            Oacc[nt][2] *= alB; Oacc[nt][3] *= alB;
        }
        __syncthreads();
        lsum[0] = lsum[0] * alA + redsum[0][m0 + g] + redsum[1][m0 + g];
        lsum[1] = lsum[1] * alB + redsum[0][m0 + 8 + g] + redsum[1][m0 + 8 + g];

#pragma unroll
        for (int kc2 = 0; kc2 < 2; kc2++) {
            uint32_t ph[4], pl[4];
            split_bf16_pair(S[2 * kc2][0], S[2 * kc2][1], ph[0], pl[0]);
            split_bf16_pair(S[2 * kc2][2], S[2 * kc2][3], ph[1], pl[1]);
            split_bf16_pair(S[2 * kc2 + 1][0], S[2 * kc2 + 1][1], ph[2], pl[2]);
            split_bf16_pair(S[2 * kc2 + 1][2], S[2 * kc2 + 1][3], ph[3], pl[3]);
            int cb = wn * 16 + kc2 * 8 + t;
#pragma unroll
            for (int ntv = 0; ntv < 4; ntv++) {
                int vr = ntv * 8 + g;
                uint32_t bh[2] = {Vthi[vr][cb], Vthi[vr][cb + 4]};
                uint32_t bl[2] = {Vtlo[vr][cb], Vtlo[vr][cb + 4]};
                mma_bf16(Oacc[ntv], ph, bh);
                mma_bf16(Oacc[ntv], ph, bl);
                mma_bf16(Oacc[ntv], pl, bh);
            }
        }
    }

    if (wn == 0) {
#pragma unroll
        for (int ntv = 0; ntv < 4; ntv++) {
            int d = ntv * 8 + 2 * t;
            Osm[m0 + g][d] = Oacc[ntv][0];
            Osm[m0 + g][d + 1] = Oacc[ntv][1];
            Osm[m0 + 8 + g][d] = Oacc[ntv][2];
            Osm[m0 + 8 + g][d + 1] = Oacc[ntv][3];
        }
    }
    __syncthreads();
    if (wn == 1) {
        float invA = 1.0f / lsum[0], invB = 1.0f / lsum[1];
#pragma unroll
        for (int ntv = 0; ntv < 4; ntv++) {
            int d = ntv * 8 + 2 * t;
            float* op0 = O + (size_t)(q0 + m0 + g) * ldo + h * HD + d;
            float* op1 = O + (size_t)(q0 + m0 + 8 + g) * ldo + h * HD + d;
            op0[0] = (Oacc[ntv][0] + Osm[m0 + g][d]) * invA;
            op0[1] = (Oacc[ntv][1] + Osm[m0 + g][d + 1]) * invA;
            op1[0] = (Oacc[ntv][2] + Osm[m0 + 8 + g][d]) * invB;
            op1[1] = (Oacc[ntv][3] + Osm[m0 + 8 + g][d + 1]) * invB;
        }
    }
}

// ---------------- tiled local attention ----------------
__global__ __launch_bounds__(256) void local_attn_tile(
        const float* __restrict__ Q, int ldq,
        const float* __restrict__ K, const float* __restrict__ V,
        float* __restrict__ O, int ldo) {
    extern __shared__ float sm[];
    float* winK = sm;
    float* winV = sm + LTWW * 33;
    float* pb = sm + 2 * LTWW * 33;
    int h = blockIdx.y;
    int ty0 = (blockIdx.x / 5) * 8, tx0 = (blockIdx.x % 5) * 8;
    int wy0 = ty0 - PADR, wx0 = tx0 - PADR;
    int tid = threadIdx.x, w = tid >> 5, lane = tid & 31;

    for (int idx = tid; idx < LTWW * 32; idx += 256) {
        int pos = idx >> 5, d = idx & 31;
        int gy = wy0 + pos / LTW, gx = wx0 + pos % LTW;
        bool ok = ((unsigned)gy < H2D) && ((unsigned)gx < W2D);
        size_t goff = (size_t)(gy * W2D + gx) * CD + h * HD + d;
        winK[pos * 33 + d] = ok ? K[goff] : 0.f;
        winV[pos * 33 + d] = ok ? V[goff] : 0.f;
    }
    __syncthreads();

    int qy = ty0 + w;
    for (int qi = 0; qi < 8; qi++) {
        int qx = tx0 + qi;
        float qv = Q[(size_t)(qy * W2D + qx) * ldq + h * HD + lane] * SCALE;
        float lg[8];
        int wi[8];
        bool val[8];
#pragma unroll
        for (int c = 0; c < 8; c++) {
            int j = c * 32 + lane;
            int jr = j / 15, jc = j - jr * 15;
            int gy2 = qy + jr - PADR, gx2 = qx + jc - PADR;
            val[c] = (j < WSQ) && ((unsigned)gy2 < H2D) && ((unsigned)gx2 < W2D);
            wi[c] = (j < WSQ) ? ((w + jr) * LTW + (qi + jc)) : 0;
            lg[c] = 0.f;
        }
#pragma unroll 8
        for (int d = 0; d < 32; d++) {
            float qd = __shfl_sync(0xffffffffu, qv, d);
#pragma unroll
            for (int c = 0; c < 8; c++)
                lg[c] = fmaf(qd, winK[wi[c] * 33 + d], lg[c]);
        }
        float mx = -1e30f;
#pragma unroll
        for (int c = 0; c < 8; c++) {
            lg[c] = val[c] ? lg[c] : -1e30f;
            mx = fmaxf(mx, lg[c]);
        }
#pragma unroll
        for (int o = 16; o; o >>= 1) mx = fmaxf(mx, __shfl_xor_sync(0xffffffffu, mx, o));
        float s = 0.f;
#pragma unroll
        for (int c = 0; c < 8; c++) {
            lg[c] = __expf(lg[c] - mx);
            s += lg[c];
        }
#pragma unroll
        for (int o = 16; o; o >>= 1) s += __shfl_xor_sync(0xffffffffu, s, o);
        float inv = 1.0f / s;
#pragma unroll
        for (int c = 0; c < 8; c++) pb[w * 264 + c * 32 + lane] = lg[c] * inv;
        __syncwarp();

        float oacc = 0.f;
        int j = 0;
#pragma unroll
        for (int jr = 0; jr < 15; jr++) {
            int base = ((w + jr) * LTW + qi) * 33 + lane;
#pragma unroll
            for (int jc = 0; jc < 15; jc++) {
                oacc = fmaf(pb[w * 264 + j], winV[base + jc * 33], oacc);
                j++;
            }
        }
        O[(size_t)(qy * W2D + qx) * ldo + h * HD + lane] = oacc;
        __syncwarp();
    }
}

// ---------------- global K/V construction ----------------
__global__ void make_global_kv(const float* __restrict__ qv, const float* __restrict__ idkv,
                               float* __restrict__ gK, float* __restrict__ gV) {
    int i = blockIdx.x * blockDim.x + threadIdx.x;
    if (i >= LQ * CD) return;
    int l = i >> 8, c = i & 255, h = c >> 5;
    float ik = idkv[l * 264 + h];
    gK[i] = qv[(size_t)l * 512 + c] * (1.0f + tanhf(ik));
    gV[i] = qv[(size_t)l * 512 + 256 + c] + idkv[l * 264 + 8 + c];
}

// ---------------- GroupNorm stats ----------------
__global__ void gn_stats(const float* __restrict__ x, float* __restrict__ stats) {
    __shared__ float red[32];
    int g = blockIdx.x;
    float s = 0.f, ss = 0.f;
    for (int i = threadIdx.x; i < LQ * 32; i += blockDim.x) {
        int l = i >> 5, c = (g << 5) + (i & 31);
        float v = x[(size_t)l * DFF + c];
        s += v;
        ss = fmaf(v, v, ss);
    }
    s = block_reduce(s, red, false);
    ss = block_reduce(ss, red, false);
    if (!threadIdx.x) {
        const float inv = 1.0f / (LQ * 32.0f);
        float m = s * inv;
        float var = ss * inv - m * m;
        stats[g * 2] = m;
        stats[g * 2 + 1] = rsqrtf(var + 1e-5f);
    }
}

// ---------------- GN apply + affine + exact GELU ----------------
__global__ void gn_apply_gelu(const float* __restrict__ x, const float* __restrict__ stats,
                              const float* __restrict__ gg, const float* __restrict__ gb,
                              float* __restrict__ y) {
    int i = blockIdx.x * blockDim.x + threadIdx.x;
    if (i >= LQ * DFF) return;
    int c = i & (DFF - 1);
    int grp = c >> 5;
    float m = stats[grp * 2], r = stats[grp * 2 + 1];
    float v = (x[i] - m) * r * gg[c] + gb[c];
    y[i] = 0.5f * v * (1.0f + erff(v * 0.70710678118654752f));
}

// ---------------- depthwise 5x5 conv, pad 2 ----------------
__global__ void dwconv_kernel(const float* __restrict__ x, const float* __restrict__ k,
                              float* __restrict__ y) {
    int l = blockIdx.x;
    int yy = l / W2D, xx = l % W2D;
    for (int c = threadIdx.x; c < DFF; c += blockDim.x) {
        float acc = 0.f;
#pragma unroll
        for (int i = 0; i < 5; i++) {
            int ny = yy + i - 2;
            if (ny < 0 || ny >= H2D) continue;
#pragma unroll
            for (int j = 0; j < 5; j++) {
                int nx = xx + j - 2;
                if (nx < 0 || nx >= W2D) continue;
                acc = fmaf(x[(size_t)(ny * W2D + nx) * DFF + c], k[c * 25 + i * 5 + j], acc);
            }
        }
        y[(size_t)l * DFF + c] = acc;
    }
}

// ---------------- host ----------------
static const int GEMM_SMEM = 4 * GSEG * (int)sizeof(uint32_t);  // 69,632 B

extern "C" void kernel_launch(void* const* d_in, const int* in_sizes, int n_in,
                              void* d_out, int out_size) {
    const float* tgt = (const float*)d_in[0];
    const float* curr_id_emb = (const float*)d_in[1];
    const float* self_pos = (const float*)d_in[2];
    const float* ln1_g = (const float*)d_in[3];
    const float* ln1_b = (const float*)d_in[4];
    const float* sa_wq = (const float*)d_in[5];
    const float* sa_bq = (const float*)d_in[6];
    const float* sa_wk = (const float*)d_in[7];
    const float* sa_bk = (const float*)d_in[8];
    const float* sa_wv = (const float*)d_in[9];
    const float* sa_bv = (const float*)d_in[10];
    const float* sa_wo = (const float*)d_in[11];
    const float* sa_bo = (const float*)d_in[12];
    const float* ln2_g = (const float*)d_in[13];
    const float* ln2_b = (const float*)d_in[14];
    const float* w_qv = (const float*)d_in[15];
    const float* b_qv = (const float*)d_in[16];
    const float* w_id = (const float*)d_in[17];
    const float* b_id = (const float*)d_in[18];
    const float* lt_wo = (const float*)d_in[19];
    const float* lt_bo = (const float*)d_in[20];
    const float* st_wo = (const float*)d_in[21];
    const float* st_bo = (const float*)d_in[22];
    const float* ln3_g = (const float*)d_in[23];
    const float* ln3_b = (const float*)d_in[24];
    const float* w1 = (const float*)d_in[25];
    const float* b1 = (const float*)d_in[26];
    const float* gn_g = (const float*)d_in[27];
    const float* gn_b = (const float*)d_in[28];
    const float* dw_k = (const float*)d_in[29];
    const float* w2 = (const float*)d_in[30];
    const float* b2 = (const float*)d_in[31];
    float* out = (float*)d_out;

    float *tln, *qkin, *qk, *v, *cat, *tgt1, *qv, *idkv, *gK, *gV, *tgt2, *x1, *x2, *gn;
    float *bqk, *bltst;
    uint32_t *whi, *wlo;
    cudaGetSymbolAddress((void**)&tln, g_tln);
    cudaGetSymbolAddress((void**)&qkin, g_qkin);
    cudaGetSymbolAddress((void**)&qk, g_qk);
    cudaGetSymbolAddress((void**)&v, g_v);
    cudaGetSymbolAddress((void**)&cat, g_cat);
    cudaGetSymbolAddress((void**)&tgt1, g_tgt1);
    cudaGetSymbolAddress((void**)&qv, g_qv);
    cudaGetSymbolAddress((void**)&idkv, g_idkv);
    cudaGetSymbolAddress((void**)&gK, g_gK);
    cudaGetSymbolAddress((void**)&gV, g_gV);
    cudaGetSymbolAddress((void**)&tgt2, g_tgt2);
    cudaGetSymbolAddress((void**)&x1, g_x1);
    cudaGetSymbolAddress((void**)&x2, g_x2);
    cudaGetSymbolAddress((void**)&gn, g_gn);
    cudaGetSymbolAddress((void**)&bqk, g_bqk);
    cudaGetSymbolAddress((void**)&bltst, g_bltst);
    cudaGetSymbolAddress((void**)&whi, g_whi);
    cudaGetSymbolAddress((void**)&wlo, g_wlo);

    const int LOCAL_SMEM = (2 * LTWW * 33 + 8 * 264) * (int)sizeof(float);
    cudaFuncSetAttribute(local_attn_tile, cudaFuncAttributeMaxDynamicSharedMemorySize, LOCAL_SMEM);
    cudaFuncSetAttribute(gemm_tc2, cudaFuncAttributeMaxDynamicSharedMemorySize, GEMM_SMEM);

    auto GEMM = [&](const float* A, int lda, int woff, const float* bias, const float* res,
                    float* C, int M, int N, int K) {
        dim3 grid((N + 63) / 64, (M + 63) / 64);
        gemm_tc2<<<grid, 256, GEMM_SMEM>>>(A, lda, whi + woff, wlo + woff, bias, res, C, M, N, K);
    };

    // ---- weight pre-conversion ----
    conv_weights<<<(TOTPAIRS + 255) / 256, 256>>>(
        sa_wq, sa_wk, sa_wv, sa_wo, w_qv, w_id, lt_wo, st_wo, w1, w2,
        sa_bq, sa_bk, lt_bo, st_bo);

    // ---- self-attention block ----
    ln_kernel<<<LQ, 256>>>(tgt, ln1_g, ln1_b, tln, self_pos, qkin);
    GEMM(qkin, CD, OFF_QK, bqk, nullptr, qk, LQ, 512, CD);            // [q|k]
    GEMM(tln, CD, OFF_WV, sa_bv, nullptr, v, LQ, CD, CD);
    flash_attn_tc<<<dim3(LQ / BQ, NH), 256>>>(qk, 512, qk + 256, 512, v, CD, cat, 512);
    GEMM(cat, 512, OFF_WO, sa_bo, tgt, tgt1, LQ, CD, CD);             // tgt1 = tgt + SA

    // ---- long/short-term block ----
    ln_kernel<<<LQ, 256>>>(tgt1, ln2_g, ln2_b, tln, nullptr, nullptr);
    GEMM(tln, CD, OFF_WQV, b_qv, nullptr, qv, LQ, 512, CD);           // [curr_Q|curr_V]
    GEMM(curr_id_emb, CD, OFF_WID, b_id, nullptr, idkv, LQ, 264, CD);
    make_global_kv<<<(LQ * CD + 255) / 256, 256>>>(qv, idkv, gK, gV);
    flash_attn_tc<<<dim3(LQ / BQ, NH), 256>>>(qv, 512, gK, CD, gV, CD, cat, 512);
    local_attn_tile<<<dim3(25, NH), 256, LOCAL_SMEM>>>(qv, 512, gK, gV, cat + 256, 512);
    GEMM(cat, 512, OFF_LTST, bltst, tgt1, tgt2, LQ, CD, 512);         // tgt2 = tgt1 + LT + ST

    // ---- FFN block ----
    ln_kernel<<<LQ, 256>>>(tgt2, ln3_g, ln3_b, tln, nullptr, nullptr);
    GEMM(tln, CD, OFF_W1, b1, nullptr, x1, LQ, DFF, CD);
    gn_stats<<<32, 256>>>(x1, gn);
    gn_apply_gelu<<<(LQ * DFF + 255) / 256, 256>>>(x1, gn, gn_g, gn_b, x2);
    dwconv_kernel<<<LQ, 256>>>(x2, dw_k, x1);
    GEMM(x1, DFF, OFF_W2, b2, tgt2, out, LQ, CD, DFF);                // out = tgt2 + FFN
}

// round 8
// speedup vs baseline: 15.7736x; 1.1183x over previous
#include <cuda_runtime.h>
#include <cuda_bf16.h>
#include <math.h>
#include <stdint.h>

#define LQ 1600
#define CD 256
#define NH 8
#define HD 32
#define DFF 1024
#define H2D 40
#define W2D 40
#define WS 15
#define WSQ 225
#define PADR 7
#define SCALE 0.17677669529663687f  // 1/sqrt(32)

#define BQ 64
#define BK 64
#define LTW 22
#define LTWW (LTW * LTW)  // 484

// GEMM chunking
#define KC 128
#define KPP 68
#define GSEG (64 * KPP)

// preconverted weight segment offsets (in bf16x2 pairs)
#define OFF_QK   0
#define OFF_WV   65536
#define OFF_WO   98304
#define OFF_WQV  131072
#define OFF_WID  196608
#define OFF_LTST 230400
#define OFF_W1   295936
#define OFF_W2   427008
#define TOTPAIRS 558080

// ---------------- scratch (device globals; no allocation) ----------------
__device__ float g_tln[LQ * CD];
__device__ float g_qkin[LQ * CD];
__device__ float g_qk[LQ * 512];
__device__ float g_v[LQ * CD];
__device__ float g_cat[LQ * 512];
__device__ float g_tgt1[LQ * CD];
__device__ float g_qv[LQ * 512];
__device__ float g_idkv[LQ * 264];
__device__ float g_gK[LQ * CD];
__device__ float g_gV[LQ * CD];
__device__ float g_tgt2[LQ * CD];
__device__ float g_x1[LQ * DFF];
__device__ float g_x2[LQ * DFF];
__device__ float g_gnacc[64];
__device__ __align__(16) uint32_t g_whi[TOTPAIRS];
__device__ __align__(16) uint32_t g_wlo[TOTPAIRS];
__device__ float g_bqk[512];
__device__ float g_bltst[256];

// ---------------- mma helpers ----------------
__device__ __forceinline__ void mma_bf16(float* c, const uint32_t* a, const uint32_t* b) {
    asm volatile(
        "mma.sync.aligned.m16n8k16.row.col.f32.bf16.bf16.f32 "
        "{%0,%1,%2,%3}, {%4,%5,%6,%7}, {%8,%9}, {%0,%1,%2,%3};"
        : "+f"(c[0]), "+f"(c[1]), "+f"(c[2]), "+f"(c[3])
        : "r"(a[0]), "r"(a[1]), "r"(a[2]), "r"(a[3]), "r"(b[0]), "r"(b[1]));
}

__device__ __forceinline__ uint32_t pack_bf16(float lo, float hi) {
    uint32_t r;
    asm("cvt.rn.bf16x2.f32 %0, %1, %2;" : "=r"(r) : "f"(hi), "f"(lo));
    return r;
}

__device__ __forceinline__ void split_bf16_pair(float x0, float x1, uint32_t& hi, uint32_t& lo) {
    hi = pack_bf16(x0, x1);
    float h0 = __uint_as_float(hi << 16);
    float h1 = __uint_as_float(hi & 0xffff0000u);
    lo = pack_bf16(x0 - h0, x1 - h1);
}

// ---------------- weight pre-conversion (once per launch) ----------------
__global__ void conv_weights(
        const float* __restrict__ wq, const float* __restrict__ wk,
        const float* __restrict__ wv, const float* __restrict__ wo,
        const float* __restrict__ wqv, const float* __restrict__ wid,
        const float* __restrict__ wlt, const float* __restrict__ wst,
        const float* __restrict__ w1, const float* __restrict__ w2,
        const float* __restrict__ bq, const float* __restrict__ bk,
        const float* __restrict__ blt, const float* __restrict__ bst) {
    int p = blockIdx.x * 256 + threadIdx.x;
    if (p < 256) {
        g_bqk[p] = bq[p];
        g_bqk[256 + p] = bk[p];
        g_bltst[p] = blt[p] + bst[p];
    }
    if (p < 64) g_gnacc[p] = 0.f;   // zero GN accumulators every replay
    if (p >= TOTPAIRS) return;
    const float* src;
    int idx;
    if (p < OFF_WV) {
        src = (p < 32768) ? wq : wk;
        idx = (p & 32767) * 2;
    } else if (p < OFF_WO) { src = wv; idx = (p - OFF_WV) * 2; }
    else if (p < OFF_WQV) { src = wo; idx = (p - OFF_WO) * 2; }
    else if (p < OFF_WID) { src = wqv; idx = (p - OFF_WQV) * 2; }
    else if (p < OFF_LTST) { src = wid; idx = (p - OFF_WID) * 2; }
    else if (p < OFF_W1) {
        int lp = p - OFF_LTST;
        int n = lp >> 8, c = lp & 255;
        if (c < 128) { src = wlt; idx = (n * 128 + c) * 2; }
        else { src = wst; idx = (n * 128 + c - 128) * 2; }
    } else if (p < OFF_W2) { src = w1; idx = (p - OFF_W1) * 2; }
    else { src = w2; idx = (p - OFF_W2) * 2; }
    uint32_t hi, lo;
    split_bf16_pair(src[idx], src[idx + 1], hi, lo);
    g_whi[p] = hi;
    g_wlo[p] = lo;
}

// ---------------- reductions ----------------
__device__ __forceinline__ float block_reduce(float v, float* red, bool is_max) {
    int lane = threadIdx.x & 31, wid = threadIdx.x >> 5;
#pragma unroll
    for (int o = 16; o; o >>= 1) {
        float u = __shfl_xor_sync(0xffffffffu, v, o);
        v = is_max ? fmaxf(v, u) : v + u;
    }
    if (!lane) red[wid] = v;
    __syncthreads();
    int nw = (blockDim.x + 31) >> 5;
    v = (lane < nw) ? red[lane] : (is_max ? -1e30f : 0.0f);
    if (!wid) {
#pragma unroll
        for (int o = 16; o; o >>= 1) {
            float u = __shfl_xor_sync(0xffffffffu, v, o);
            v = is_max ? fmaxf(v, u) : v + u;
        }
        if (!lane) red[0] = v;
    }
    __syncthreads();
    v = red[0];
    __syncthreads();
    return v;
}

// ---------------- LayerNorm ----------------
__global__ void ln_kernel(const float* __restrict__ in, const float* __restrict__ g,
                          const float* __restrict__ b, float* __restrict__ out,
                          const float* __restrict__ pos, float* __restrict__ out2) {
    __shared__ float red[32];
    int l = blockIdx.x, c = threadIdx.x;
    float x = in[l * CD + c];
    float m = block_reduce(x, red, false) * (1.0f / CD);
    float d = x - m;
    float var = block_reduce(d * d, red, false) * (1.0f / CD);
    float y = d * rsqrtf(var + 1e-5f) * g[c] + b[c];
    out[l * CD + c] = y;
    if (out2) out2[l * CD + c] = y + pos[l * CD + c];
}

// ---------------- bf16-split tensor-core GEMM, preconverted W ----------------
__global__ __launch_bounds__(256) void gemm_tc2(
        const float* __restrict__ A, int lda,
        const uint32_t* __restrict__ Whg, const uint32_t* __restrict__ Wlg,
        const float* __restrict__ bias, const float* __restrict__ res,
        float* __restrict__ C, int M, int N, int K) {
    extern __shared__ uint32_t su[];
    uint32_t* Ah = su;
    uint32_t* Al = su + GSEG;
    uint32_t* Wh = su + 2 * GSEG;
    uint32_t* Wl = su + 3 * GSEG;

    int tid = threadIdx.x;
    int bm = blockIdx.y * 64, bn = blockIdx.x * 64;
    int wid = tid >> 5, lane = tid & 31;
    int wm = wid & 3, wn = wid >> 2;
    int g = lane >> 2, t = lane & 3;
    int m0 = wm * 16;
    int Kp = K >> 1;
    float acc[4][4] = {};

    int srow = tid >> 2, sc0 = tid & 3;
    bool wok = (bn + srow) < N;
    const float* Ap = A + (size_t)(bm + srow) * lda;
    const uint32_t* Whp = Whg + (size_t)(wok ? bn + srow : 0) * Kp;
    const uint32_t* Wlp = Wlg + (size_t)(wok ? bn + srow : 0) * Kp;

    float4 pa[8];
    uint4 pwh[4], pwl[4];
    const uint4 z4 = make_uint4(0, 0, 0, 0);

#define LOADCHUNK(k0)                                                          \
    {                                                                          \
        int kp0 = (k0) >> 1;                                                   \
        _Pragma("unroll")                                                      \
        for (int i = 0; i < 4; i++) {                                          \
            int cA = (k0) + (2 * sc0 + 8 * i) * 4;                             \
            pa[2 * i] = *reinterpret_cast<const float4*>(Ap + cA);             \
            pa[2 * i + 1] = *reinterpret_cast<const float4*>(Ap + cA + 4);     \
            int pp = kp0 + (sc0 + 4 * i) * 4;                                  \
            pwh[i] = wok ? *reinterpret_cast<const uint4*>(Whp + pp) : z4;     \
            pwl[i] = wok ? *reinterpret_cast<const uint4*>(Wlp + pp) : z4;     \
        }                                                                      \
    }

    LOADCHUNK(0)

    for (int k0 = 0; k0 < K; k0 += KC) {
        if (k0) __syncthreads();
#pragma unroll
        for (int i = 0; i < 4; i++) {
            int pp = (sc0 + 4 * i) * 4;
            uint32_t h0, l0, h1, l1, h2, l2, h3, l3;
            split_bf16_pair(pa[2 * i].x, pa[2 * i].y, h0, l0);
            split_bf16_pair(pa[2 * i].z, pa[2 * i].w, h1, l1);
            split_bf16_pair(pa[2 * i + 1].x, pa[2 * i + 1].y, h2, l2);
            split_bf16_pair(pa[2 * i + 1].z, pa[2 * i + 1].w, h3, l3);
            *reinterpret_cast<uint4*>(&Ah[srow * KPP + pp]) = make_uint4(h0, h1, h2, h3);
            *reinterpret_cast<uint4*>(&Al[srow * KPP + pp]) = make_uint4(l0, l1, l2, l3);
            *reinterpret_cast<uint4*>(&Wh[srow * KPP + pp]) = pwh[i];
            *reinterpret_cast<uint4*>(&Wl[srow * KPP + pp]) = pwl[i];
        }
        __syncthreads();
        if (k0 + KC < K) LOADCHUNK(k0 + KC)

#pragma unroll
        for (int ks = 0; ks < KC / 16; ks++) {
            int kb = ks * 8 + t;
            uint32_t ah[4], al[4];
            ah[0] = Ah[(m0 + g) * KPP + kb];
            ah[1] = Ah[(m0 + 8 + g) * KPP + kb];
            ah[2] = Ah[(m0 + g) * KPP + kb + 4];
            ah[3] = Ah[(m0 + 8 + g) * KPP + kb + 4];
            al[0] = Al[(m0 + g) * KPP + kb];
            al[1] = Al[(m0 + 8 + g) * KPP + kb];
            al[2] = Al[(m0 + g) * KPP + kb + 4];
            al[3] = Al[(m0 + 8 + g) * KPP + kb + 4];
#pragma unroll
            for (int nt = 0; nt < 4; nt++) {
                int nr = wn * 32 + nt * 8 + g;
                uint32_t bh[2] = {Wh[nr * KPP + kb], Wh[nr * KPP + kb + 4]};
                uint32_t bl[2] = {Wl[nr * KPP + kb], Wl[nr * KPP + kb + 4]};
                mma_bf16(acc[nt], ah, bh);
                mma_bf16(acc[nt], ah, bl);
                mma_bf16(acc[nt], al, bh);
            }
        }
    }

    int mo = bm + m0 + g;
    if (bn + 64 <= N) {
#pragma unroll
        for (int nt = 0; nt < 4; nt++) {
            int n = bn + wn * 32 + nt * 8 + 2 * t;
            float2 bv = *reinterpret_cast<const float2*>(bias + n);
            size_t o0 = (size_t)mo * N + n;
            size_t o1 = (size_t)(mo + 8) * N + n;
            float2 r0 = make_float2(acc[nt][0] + bv.x, acc[nt][1] + bv.y);
            float2 r1 = make_float2(acc[nt][2] + bv.x, acc[nt][3] + bv.y);
            if (res) {
                float2 e0 = *reinterpret_cast<const float2*>(res + o0);
                float2 e1 = *reinterpret_cast<const float2*>(res + o1);
                r0.x += e0.x; r0.y += e0.y; r1.x += e1.x; r1.y += e1.y;
            }
            *reinterpret_cast<float2*>(C + o0) = r0;
            *reinterpret_cast<float2*>(C + o1) = r1;
        }
    } else {
#pragma unroll
        for (int nt = 0; nt < 4; nt++) {
            int n = bn + wn * 32 + nt * 8 + 2 * t;
#pragma unroll
            for (int e = 0; e < 2; e++) {
                if (n + e >= N) continue;
                float v0 = acc[nt][e] + bias[n + e];
                float v1 = acc[nt][2 + e] + bias[n + e];
                if (res) {
                    v0 += res[(size_t)mo * N + n + e];
                    v1 += res[(size_t)(mo + 8) * N + n + e];
                }
                C[(size_t)mo * N + n + e] = v0;
                C[(size_t)(mo + 8) * N + n + e] = v1;
            }
        }
    }
#undef LOADCHUNK
}

// ---------------- tensor-core flash attention (bf16 hi/lo split) ----------------
__global__ __launch_bounds__(256) void flash_attn_tc(
        const float* __restrict__ Q, int ldq,
        const float* __restrict__ K, int ldk,
        const float* __restrict__ V, int ldv,
        float* __restrict__ O, int ldo) {
    __shared__ uint32_t Qhi[64][20], Qlo[64][20];
    __shared__ uint32_t Khi[64][20], Klo[64][20];
    __shared__ uint32_t Vthi[32][36], Vtlo[32][36];
    __shared__ float redmax[2][64], redsum[2][64];
    __shared__ float Osm[64][33];

    int h = blockIdx.y, q0 = blockIdx.x * BQ;
    int tid = threadIdx.x, wid = tid >> 5, lane = tid & 31;
    int wm = wid & 3, wn = wid >> 2;
    int g = lane >> 2, t = lane & 3;
    int m0 = wm * 16;
    int lrow = tid >> 2, lcol = (tid & 3) * 8;

    {
        const float* qp = Q + (size_t)(q0 + lrow) * ldq + h * HD + lcol;
        float4 a = *reinterpret_cast<const float4*>(qp);
        float4 b = *reinterpret_cast<const float4*>(qp + 4);
        float xv[8] = {a.x, a.y, a.z, a.w, b.x, b.y, b.z, b.w};
#pragma unroll
        for (int j = 0; j < 4; j++) {
            uint32_t hi, lo;
            split_bf16_pair(xv[2 * j] * SCALE, xv[2 * j + 1] * SCALE, hi, lo);
            Qhi[lrow][lcol / 2 + j] = hi;
            Qlo[lrow][lcol / 2 + j] = lo;
        }
    }

    float mrow[2] = {-1e30f, -1e30f}, lsum[2] = {0.f, 0.f};
    float Oacc[4][4] = {};

    for (int kt = 0; kt < LQ; kt += BK) {
        const float* kp = K + (size_t)(kt + lrow) * ldk + h * HD + lcol;
        const float* vp = V + (size_t)(kt + lrow) * ldv + h * HD + lcol;
        float4 ka = *reinterpret_cast<const float4*>(kp);
        float4 kb = *reinterpret_cast<const float4*>(kp + 4);
        float4 va = *reinterpret_cast<const float4*>(vp);
        float4 vb = *reinterpret_cast<const float4*>(vp + 4);
        __syncthreads();
        {
            float kv[8] = {ka.x, ka.y, ka.z, ka.w, kb.x, kb.y, kb.z, kb.w};
#pragma unroll
            for (int j = 0; j < 4; j++) {
                uint32_t hi, lo;
                split_bf16_pair(kv[2 * j], kv[2 * j + 1], hi, lo);
                Khi[lrow][lcol / 2 + j] = hi;
                Klo[lrow][lcol / 2 + j] = lo;
            }
            float vv[8] = {va.x, va.y, va.z, va.w, vb.x, vb.y, vb.z, vb.w};
            __nv_bfloat16* VH = reinterpret_cast<__nv_bfloat16*>(Vthi);
            __nv_bfloat16* VL = reinterpret_cast<__nv_bfloat16*>(Vtlo);
#pragma unroll
            for (int j = 0; j < 8; j++) {
                int d = lcol + j;
                float x = vv[j];
                __nv_bfloat16 hb = __float2bfloat16(x);
                VH[d * 72 + lrow] = hb;
                VL[d * 72 + lrow] = __float2bfloat16(x - __bfloat162float(hb));
            }
        }
        __syncthreads();

        float S[4][4];
#pragma unroll
        for (int nt = 0; nt < 4; nt++)
#pragma unroll
            for (int c = 0; c < 4; c++) S[nt][c] = 0.f;
#pragma unroll
        for (int kc = 0; kc < 2; kc++) {
            uint32_t ah[4], al[4];
            ah[0] = Qhi[m0 + g][kc * 8 + t];     ah[1] = Qhi[m0 + 8 + g][kc * 8 + t];
            ah[2] = Qhi[m0 + g][kc * 8 + t + 4]; ah[3] = Qhi[m0 + 8 + g][kc * 8 + t + 4];
            al[0] = Qlo[m0 + g][kc * 8 + t];     al[1] = Qlo[m0 + 8 + g][kc * 8 + t];
            al[2] = Qlo[m0 + g][kc * 8 + t + 4]; al[3] = Qlo[m0 + 8 + g][kc * 8 + t + 4];
#pragma unroll
            for (int nt = 0; nt < 4; nt++) {
                int kr = wn * 32 + nt * 8 + g;
                uint32_t bh[2] = {Khi[kr][kc * 8 + t], Khi[kr][kc * 8 + t + 4]};
                uint32_t bl[2] = {Klo[kr][kc * 8 + t], Klo[kr][kc * 8 + t + 4]};
                mma_bf16(S[nt], ah, bh);
                mma_bf16(S[nt], ah, bl);
                mma_bf16(S[nt], al, bh);
            }
        }

        float pmA = -1e30f, pmB = -1e30f;
#pragma unroll
        for (int nt = 0; nt < 4; nt++) {
            pmA = fmaxf(pmA, fmaxf(S[nt][0], S[nt][1]));
            pmB = fmaxf(pmB, fmaxf(S[nt][2], S[nt][3]));
        }
        pmA = fmaxf(pmA, __shfl_xor_sync(0xffffffffu, pmA, 1));
        pmA = fmaxf(pmA, __shfl_xor_sync(0xffffffffu, pmA, 2));
        pmB = fmaxf(pmB, __shfl_xor_sync(0xffffffffu, pmB, 1));
        pmB = fmaxf(pmB, __shfl_xor_sync(0xffffffffu, pmB, 2));
        if (t == 0) {
            redmax[wn][m0 + g] = pmA;
            redmax[wn][m0 + 8 + g] = pmB;
        }
        __syncthreads();
        float nmA = fmaxf(mrow[0], fmaxf(redmax[0][m0 + g], redmax[1][m0 + g]));
        float nmB = fmaxf(mrow[1], fmaxf(redmax[0][m0 + 8 + g], redmax[1][m0 + 8 + g]));
        float alA = __expf(mrow[0] - nmA), alB = __expf(mrow[1] - nmB);
        mrow[0] = nmA; mrow[1] = nmB;
        float psA = 0.f, psB = 0.f;
#pragma unroll
        for (int nt = 0; nt < 4; nt++) {
            S[nt][0] = __expf(S[nt][0] - nmA); S[nt][1] = __expf(S[nt][1] - nmA);
            S[nt][2] = __expf(S[nt][2] - nmB); S[nt][3] = __expf(S[nt][3] - nmB);
            psA += S[nt][0] + S[nt][1];
            psB += S[nt][2] + S[nt][3];
        }
        psA += __shfl_xor_sync(0xffffffffu, psA, 1);
        psA += __shfl_xor_sync(0xffffffffu, psA, 2);
        psB += __shfl_xor_sync(0xffffffffu, psB, 1);
        psB += __shfl_xor_sync(0xffffffffu, psB, 2);
        if (t == 0) {
            redsum[wn][m0 + g] = psA;
            redsum[wn][m0 + 8 + g] = psB;
        }
#pragma unroll
        for (int nt = 0; nt < 4; nt++) {
            Oacc[nt][0] *= alA; Oacc[nt][1] *= alA;
            Oacc[nt][2] *= alB; Oacc[nt][3] *= alB;
        }
        __syncthreads();
        lsum[0] = lsum[0] * alA + redsum[0][m0 + g] + redsum[1][m0 + g];
        lsum[1] = lsum[1] * alB + redsum[0][m0 + 8 + g] + redsum[1][m0 + 8 + g];

#pragma unroll
        for (int kc2 = 0; kc2 < 2; kc2++) {
            uint32_t ph[4], pl[4];
            split_bf16_pair(S[2 * kc2][0], S[2 * kc2][1], ph[0], pl[0]);
            split_bf16_pair(S[2 * kc2][2], S[2 * kc2][3], ph[1], pl[1]);
            split_bf16_pair(S[2 * kc2 + 1][0], S[2 * kc2 + 1][1], ph[2], pl[2]);
            split_bf16_pair(S[2 * kc2 + 1][2], S[2 * kc2 + 1][3], ph[3], pl[3]);
            int cb = wn * 16 + kc2 * 8 + t;
#pragma unroll
            for (int ntv = 0; ntv < 4; ntv++) {
                int vr = ntv * 8 + g;
                uint32_t bh[2] = {Vthi[vr][cb], Vthi[vr][cb + 4]};
                uint32_t bl[2] = {Vtlo[vr][cb], Vtlo[vr][cb + 4]};
                mma_bf16(Oacc[ntv], ph, bh);
                mma_bf16(Oacc[ntv], ph, bl);
                mma_bf16(Oacc[ntv], pl, bh);
            }
        }
    }

    if (wn == 0) {
#pragma unroll
        for (int ntv = 0; ntv < 4; ntv++) {
            int d = ntv * 8 + 2 * t;
            Osm[m0 + g][d] = Oacc[ntv][0];
            Osm[m0 + g][d + 1] = Oacc[ntv][1];
            Osm[m0 + 8 + g][d] = Oacc[ntv][2];
            Osm[m0 + 8 + g][d + 1] = Oacc[ntv][3];
        }
    }
    __syncthreads();
    if (wn == 1) {
        float invA = 1.0f / lsum[0], invB = 1.0f / lsum[1];
#pragma unroll
        for (int ntv = 0; ntv < 4; ntv++) {
            int d = ntv * 8 + 2 * t;
            float* op0 = O + (size_t)(q0 + m0 + g) * ldo + h * HD + d;
            float* op1 = O + (size_t)(q0 + m0 + 8 + g) * ldo + h * HD + d;
            op0[0] = (Oacc[ntv][0] + Osm[m0 + g][d]) * invA;
            op0[1] = (Oacc[ntv][1] + Osm[m0 + g][d + 1]) * invA;
            op1[0] = (Oacc[ntv][2] + Osm[m0 + 8 + g][d]) * invB;
            op1[1] = (Oacc[ntv][3] + Osm[m0 + 8 + g][d + 1]) * invB;
        }
    }
}

// ---------------- tiled local attention ----------------
__global__ __launch_bounds__(256) void local_attn_tile(
        const float* __restrict__ Q, int ldq,
        const float* __restrict__ K, const float* __restrict__ V,
        float* __restrict__ O, int ldo) {
    extern __shared__ float sm[];
    float* winK = sm;
    float* winV = sm + LTWW * 33;
    float* pb = sm + 2 * LTWW * 33;
    int h = blockIdx.y;
    int ty0 = (blockIdx.x / 5) * 8, tx0 = (blockIdx.x % 5) * 8;
    int wy0 = ty0 - PADR, wx0 = tx0 - PADR;
    int tid = threadIdx.x, w = tid >> 5, lane = tid & 31;

    for (int idx = tid; idx < LTWW * 32; idx += 256) {
        int pos = idx >> 5, d = idx & 31;
        int gy = wy0 + pos / LTW, gx = wx0 + pos % LTW;
        bool ok = ((unsigned)gy < H2D) && ((unsigned)gx < W2D);
        size_t goff = (size_t)(gy * W2D + gx) * CD + h * HD + d;
        winK[pos * 33 + d] = ok ? K[goff] : 0.f;
        winV[pos * 33 + d] = ok ? V[goff] : 0.f;
    }
    __syncthreads();

    int qy = ty0 + w;
    for (int qi = 0; qi < 8; qi++) {
        int qx = tx0 + qi;
        float qv = Q[(size_t)(qy * W2D + qx) * ldq + h * HD + lane] * SCALE;
        float lg[8];
        int wi[8];
        bool val[8];
#pragma unroll
        for (int c = 0; c < 8; c++) {
            int j = c * 32 + lane;
            int jr = j / 15, jc = j - jr * 15;
            int gy2 = qy + jr - PADR, gx2 = qx + jc - PADR;
            val[c] = (j < WSQ) && ((unsigned)gy2 < H2D) && ((unsigned)gx2 < W2D);
            wi[c] = (j < WSQ) ? ((w + jr) * LTW + (qi + jc)) : 0;
            lg[c] = 0.f;
        }
#pragma unroll 8
        for (int d = 0; d < 32; d++) {
            float qd = __shfl_sync(0xffffffffu, qv, d);
#pragma unroll
            for (int c = 0; c < 8; c++)
                lg[c] = fmaf(qd, winK[wi[c] * 33 + d], lg[c]);
        }
        float mx = -1e30f;
#pragma unroll
        for (int c = 0; c < 8; c++) {
            lg[c] = val[c] ? lg[c] : -1e30f;
            mx = fmaxf(mx, lg[c]);
        }
#pragma unroll
        for (int o = 16; o; o >>= 1) mx = fmaxf(mx, __shfl_xor_sync(0xffffffffu, mx, o));
        float s = 0.f;
#pragma unroll
        for (int c = 0; c < 8; c++) {
            lg[c] = __expf(lg[c] - mx);
            s += lg[c];
        }
#pragma unroll
        for (int o = 16; o; o >>= 1) s += __shfl_xor_sync(0xffffffffu, s, o);
        float inv = 1.0f / s;
#pragma unroll
        for (int c = 0; c < 8; c++) pb[w * 264 + c * 32 + lane] = lg[c] * inv;
        __syncwarp();

        float oacc = 0.f;
        int j = 0;
#pragma unroll
        for (int jr = 0; jr < 15; jr++) {
            int base = ((w + jr) * LTW + qi) * 33 + lane;
#pragma unroll
            for (int jc = 0; jc < 15; jc++) {
                oacc = fmaf(pb[w * 264 + j], winV[base + jc * 33], oacc);
                j++;
            }
        }
        O[(size_t)(qy * W2D + qx) * ldo + h * HD + lane] = oacc;
        __syncwarp();
    }
}

// ---------------- global K/V construction ----------------
__global__ void make_global_kv(const float* __restrict__ qv, const float* __restrict__ idkv,
                               float* __restrict__ gK, float* __restrict__ gV) {
    int i = blockIdx.x * blockDim.x + threadIdx.x;
    if (i >= LQ * CD) return;
    int l = i >> 8, c = i & 255, h = c >> 5;
    float ik = idkv[l * 264 + h];
    gK[i] = qv[(size_t)l * 512 + c] * (1.0f + tanhf(ik));
    gV[i] = qv[(size_t)l * 512 + 256 + c] + idkv[l * 264 + 8 + c];
}

// ---------------- GroupNorm stats: grid (32 groups, 8 row-slabs), atomic accumulate ----------------
__global__ __launch_bounds__(256) void gn_stats_at(const float* __restrict__ x,
                                                   float* __restrict__ acc) {
    __shared__ float red[32];
    int grp = blockIdx.x, slab = blockIdx.y;
    float s = 0.f, ss = 0.f;
    for (int i = threadIdx.x; i < 200 * 32; i += 256) {
        int l = slab * 200 + (i >> 5);
        int c = grp * 32 + (i & 31);
        float v = x[(size_t)l * DFF + c];
        s += v;
        ss = fmaf(v, v, ss);
    }
    s = block_reduce(s, red, false);
    ss = block_reduce(ss, red, false);
    if (!threadIdx.x) {
        atomicAdd(&acc[grp * 2], s);
        atomicAdd(&acc[grp * 2 + 1], ss);
    }
}

// ---------------- fused GN-apply + GELU + depthwise 5x5 conv ----------------
// block = (8x8 spatial tile, 128-channel slab); grid (25, 8)
#define DWP 144          // 12x12 halo positions
__global__ __launch_bounds__(256) void dwconv_gn(
        const float* __restrict__ x1, const float* __restrict__ acc,
        const float* __restrict__ gg, const float* __restrict__ gb,
        const float* __restrict__ dwk, float* __restrict__ y) {
    extern __shared__ float sm[];
    float* winX = sm;                       // [144][128]
    float* wk = sm + DWP * 128;             // [128][25]
    float* sgg = wk + 128 * 25;             // [128]
    float* sgb = sgg + 128;                 // [128]
    float* smr = sgb + 128;                 // [8]
    int tile = blockIdx.x, slab = blockIdx.y;
    int ty0 = (tile / 5) * 8, tx0 = (tile % 5) * 8;
    int tid = threadIdx.x;
    int c0 = slab * 128;

    if (tid < 4) {
        int gidx = (c0 >> 5) + tid;
        const float inv = 1.0f / 51200.0f;
        float s = acc[gidx * 2], ss = acc[gidx * 2 + 1];
        float m = s * inv;
        float var = ss * inv - m * m;
        smr[tid] = m;
        smr[4 + tid] = rsqrtf(var + 1e-5f);
    }
    if (tid < 128) {
        sgg[tid] = gg[c0 + tid];
        sgb[tid] = gb[c0 + tid];
    }
    for (int i = tid; i < 128 * 25; i += 256) wk[i] = dwk[c0 * 25 + i];
    __syncthreads();

    // stage halo tile with GN + affine + exact GELU applied on the fly
    for (int idx = tid; idx < DWP * 32; idx += 256) {
        int pos = idx >> 5, f4 = idx & 31;
        int gy = ty0 - 2 + pos / 12, gx = tx0 - 2 + pos % 12;
        bool ok = ((unsigned)gy < H2D) && ((unsigned)gx < W2D);
        float4 v = ok ? *reinterpret_cast<const float4*>(
                            x1 + (size_t)(gy * W2D + gx) * DFF + c0 + f4 * 4)
                      : make_float4(0.f, 0.f, 0.f, 0.f);
        int grp = f4 >> 3;
        float m = smr[grp], r = smr[4 + grp];
        int cl = f4 * 4;
        float e[4] = {v.x, v.y, v.z, v.w};
#pragma unroll
        for (int j = 0; j < 4; j++) {
            float t2 = (e[j] - m) * r * sgg[cl + j] + sgb[cl + j];
            e[j] = 0.5f * t2 * (1.0f + erff(t2 * 0.70710678118654752f));
        }
        float4 o = make_float4(ok ? e[0] : 0.f, ok ? e[1] : 0.f,
                               ok ? e[2] : 0.f, ok ? e[3] : 0.f);
        *reinterpret_cast<float4*>(&winX[pos * 128 + cl]) = o;
    }
    __syncthreads();

    // compute: thread = (channel c, pos-group pg of 4 output rows)
    int c = tid & 127, pg = tid >> 7;   // pg 0,1 -> output rows 0-3 / 4-7
    float wreg[25];
#pragma unroll
    for (int k = 0; k < 25; k++) wreg[k] = wk[c * 25 + k];

#pragma unroll
    for (int py = 0; py < 4; py++) {
        int oy = pg * 4 + py;
        float oac[8] = {};
#pragma unroll
        for (int dy = 0; dy < 5; dy++) {
            float rv[12];
            int rb = (oy + dy) * 12;
#pragma unroll
            for (int j = 0; j < 12; j++) rv[j] = winX[(rb + j) * 128 + c];
#pragma unroll
            for (int dx = 0; dx < 5; dx++) {
                float wv = wreg[dy * 5 + dx];
#pragma unroll
                for (int o = 0; o < 8; o++)
                    oac[o] = fmaf(rv[o + dx], wv, oac[o]);
            }
        }
#pragma unroll
        for (int o = 0; o < 8; o++)
            y[(size_t)((ty0 + oy) * W2D + tx0 + o) * DFF + c0 + c] = oac[o];
    }
}

// ---------------- host ----------------
static const int GEMM_SMEM = 4 * GSEG * (int)sizeof(uint32_t);  // 69,632 B
static const int DW_SMEM = (DWP * 128 + 128 * 25 + 256 + 8) * (int)sizeof(float);

extern "C" void kernel_launch(void* const* d_in, const int* in_sizes, int n_in,
                              void* d_out, int out_size) {
    const float* tgt = (const float*)d_in[0];
    const float* curr_id_emb = (const float*)d_in[1];
    const float* self_pos = (const float*)d_in[2];
    const float* ln1_g = (const float*)d_in[3];
    const float* ln1_b = (const float*)d_in[4];
    const float* sa_wq = (const float*)d_in[5];
    const float* sa_bq = (const float*)d_in[6];
    const float* sa_wk = (const float*)d_in[7];
    const float* sa_bk = (const float*)d_in[8];
    const float* sa_wv = (const float*)d_in[9];
    const float* sa_bv = (const float*)d_in[10];
    const float* sa_wo = (const float*)d_in[11];
    const float* sa_bo = (const float*)d_in[12];
    const float* ln2_g = (const float*)d_in[13];
    const float* ln2_b = (const float*)d_in[14];
    const float* w_qv = (const float*)d_in[15];
    const float* b_qv = (const float*)d_in[16];
    const float* w_id = (const float*)d_in[17];
    const float* b_id = (const float*)d_in[18];
    const float* lt_wo = (const float*)d_in[19];
    const float* lt_bo = (const float*)d_in[20];
    const float* st_wo = (const float*)d_in[21];
    const float* st_bo = (const float*)d_in[22];
    const float* ln3_g = (const float*)d_in[23];
    const float* ln3_b = (const float*)d_in[24];
    const float* w1 = (const float*)d_in[25];
    const float* b1 = (const float*)d_in[26];
    const float* gn_g = (const float*)d_in[27];
    const float* gn_b = (const float*)d_in[28];
    const float* dw_k = (const float*)d_in[29];
    const float* w2 = (const float*)d_in[30];
    const float* b2 = (const float*)d_in[31];
    float* out = (float*)d_out;

    float *tln, *qkin, *qk, *v, *cat, *tgt1, *qv, *idkv, *gK, *gV, *tgt2, *x1, *x2, *gnacc;
    float *bqk, *bltst;
    uint32_t *whi, *wlo;
    cudaGetSymbolAddress((void**)&tln, g_tln);
    cudaGetSymbolAddress((void**)&qkin, g_qkin);
    cudaGetSymbolAddress((void**)&qk, g_qk);
    cudaGetSymbolAddress((void**)&v, g_v);
    cudaGetSymbolAddress((void**)&cat, g_cat);
    cudaGetSymbolAddress((void**)&tgt1, g_tgt1);
    cudaGetSymbolAddress((void**)&qv, g_qv);
    cudaGetSymbolAddress((void**)&idkv, g_idkv);
    cudaGetSymbolAddress((void**)&gK, g_gK);
    cudaGetSymbolAddress((void**)&gV, g_gV);
    cudaGetSymbolAddress((void**)&tgt2, g_tgt2);
    cudaGetSymbolAddress((void**)&x1, g_x1);
    cudaGetSymbolAddress((void**)&x2, g_x2);
    cudaGetSymbolAddress((void**)&gnacc, g_gnacc);
    cudaGetSymbolAddress((void**)&bqk, g_bqk);
    cudaGetSymbolAddress((void**)&bltst, g_bltst);
    cudaGetSymbolAddress((void**)&whi, g_whi);
    cudaGetSymbolAddress((void**)&wlo, g_wlo);

    const int LOCAL_SMEM = (2 * LTWW * 33 + 8 * 264) * (int)sizeof(float);
    cudaFuncSetAttribute(local_attn_tile, cudaFuncAttributeMaxDynamicSharedMemorySize, LOCAL_SMEM);
    cudaFuncSetAttribute(gemm_tc2, cudaFuncAttributeMaxDynamicSharedMemorySize, GEMM_SMEM);
    cudaFuncSetAttribute(dwconv_gn, cudaFuncAttributeMaxDynamicSharedMemorySize, DW_SMEM);

    auto GEMM = [&](const float* A, int lda, int woff, const float* bias, const float* res,
                    float* C, int M, int N, int K) {
        dim3 grid((N + 63) / 64, (M + 63) / 64);
        gemm_tc2<<<grid, 256, GEMM_SMEM>>>(A, lda, whi + woff, wlo + woff, bias, res, C, M, N, K);
    };

    // ---- weight pre-conversion + GN accumulator zero ----
    conv_weights<<<(TOTPAIRS + 255) / 256, 256>>>(
        sa_wq, sa_wk, sa_wv, sa_wo, w_qv, w_id, lt_wo, st_wo, w1, w2,
        sa_bq, sa_bk, lt_bo, st_bo);

    // ---- self-attention block ----
    ln_kernel<<<LQ, 256>>>(tgt, ln1_g, ln1_b, tln, self_pos, qkin);
    GEMM(qkin, CD, OFF_QK, bqk, nullptr, qk, LQ, 512, CD);            // [q|k]
    GEMM(tln, CD, OFF_WV, sa_bv, nullptr, v, LQ, CD, CD);
    flash_attn_tc<<<dim3(LQ / BQ, NH), 256>>>(qk, 512, qk + 256, 512, v, CD, cat, 512);
    GEMM(cat, 512, OFF_WO, sa_bo, tgt, tgt1, LQ, CD, CD);             // tgt1 = tgt + SA

    // ---- long/short-term block ----
    ln_kernel<<<LQ, 256>>>(tgt1, ln2_g, ln2_b, tln, nullptr, nullptr);
    GEMM(tln, CD, OFF_WQV, b_qv, nullptr, qv, LQ, 512, CD);           // [curr_Q|curr_V]
    GEMM(curr_id_emb, CD, OFF_WID, b_id, nullptr, idkv, LQ, 264, CD);
    make_global_kv<<<(LQ * CD + 255) / 256, 256>>>(qv, idkv, gK, gV);
    flash_attn_tc<<<dim3(LQ / BQ, NH), 256>>>(qv, 512, gK, CD, gV, CD, cat, 512);
    local_attn_tile<<<dim3(25, NH), 256, LOCAL_SMEM>>>(qv, 512, gK, gV, cat + 256, 512);
    GEMM(cat, 512, OFF_LTST, bltst, tgt1, tgt2, LQ, CD, 512);         // tgt2 = tgt1 + LT + ST

    // ---- FFN block ----
    ln_kernel<<<LQ, 256>>>(tgt2, ln3_g, ln3_b, tln, nullptr, nullptr);
    GEMM(tln, CD, OFF_W1, b1, nullptr, x1, LQ, DFF, CD);
    gn_stats_at<<<dim3(32, 8), 256>>>(x1, gnacc);
    dwconv_gn<<<dim3(25, 8), 256, DW_SMEM>>>(x1, gnacc, gn_g, gn_b, dw_k, x2);
    GEMM(x2, DFF, OFF_W2, b2, tgt2, out, LQ, CD, DFF);                // out = tgt2 + FFN
}

// round 9
// speedup vs baseline: 16.2840x; 1.0324x over previous
#include <cuda_runtime.h>
#include <cuda_bf16.h>
#include <math.h>
#include <stdint.h>

#define LQ 1600
#define CD 256
#define NH 8
#define HD 32
#define DFF 1024
#define H2D 40
#define W2D 40
#define WS 15
#define WSQ 225
#define PADR 7
#define SCALE 0.17677669529663687f  // 1/sqrt(32)

#define BQ 64
#define BK 64
#define LTW 22
#define LTWW (LTW * LTW)  // 484

// GEMM chunking
#define KC 128
#define KPP 68
#define GSEG (64 * KPP)

// preconverted weight segment offsets (in bf16x2 pairs)
#define OFF_QK   0
#define OFF_WV   65536
#define OFF_WO   98304
#define OFF_WQV  131072
#define OFF_WID  196608
#define OFF_LTST 230400
#define OFF_W1   295936
#define OFF_W2   427008
#define TOTPAIRS 558080

// ---------------- scratch (device globals; no allocation) ----------------
__device__ float g_tln[LQ * CD];
__device__ float g_qkin[LQ * CD];
__device__ float g_qk[LQ * 512];
__device__ float g_v[LQ * CD];
__device__ float g_cat[LQ * 512];
__device__ float g_tgt1[LQ * CD];
__device__ float g_qv[LQ * 512];
__device__ float g_idkv[LQ * 264];
__device__ float g_tgt2[LQ * CD];
__device__ float g_x1[LQ * DFF];
__device__ float g_x2[LQ * DFF];
__device__ float g_gnacc[64];
__device__ __align__(16) uint32_t g_whi[TOTPAIRS];
__device__ __align__(16) uint32_t g_wlo[TOTPAIRS];
__device__ float g_bqk[512];
__device__ float g_bltst[256];

// ---------------- mma helpers ----------------
__device__ __forceinline__ void mma_bf16(float* c, const uint32_t* a, const uint32_t* b) {
    asm volatile(
        "mma.sync.aligned.m16n8k16.row.col.f32.bf16.bf16.f32 "
        "{%0,%1,%2,%3}, {%4,%5,%6,%7}, {%8,%9}, {%0,%1,%2,%3};"
        : "+f"(c[0]), "+f"(c[1]), "+f"(c[2]), "+f"(c[3])
        : "r"(a[0]), "r"(a[1]), "r"(a[2]), "r"(a[3]), "r"(b[0]), "r"(b[1]));
}

__device__ __forceinline__ uint32_t pack_bf16(float lo, float hi) {
    uint32_t r;
    asm("cvt.rn.bf16x2.f32 %0, %1, %2;" : "=r"(r) : "f"(hi), "f"(lo));
    return r;
}

__device__ __forceinline__ void split_bf16_pair(float x0, float x1, uint32_t& hi, uint32_t& lo) {
    hi = pack_bf16(x0, x1);
    float h0 = __uint_as_float(hi << 16);
    float h1 = __uint_as_float(hi & 0xffff0000u);
    lo = pack_bf16(x0 - h0, x1 - h1);
}

// ---------------- weight pre-conversion (once per launch) ----------------
__global__ void conv_weights(
        const float* __restrict__ wq, const float* __restrict__ wk,
        const float* __restrict__ wv, const float* __restrict__ wo,
        const float* __restrict__ wqv, const float* __restrict__ wid,
        const float* __restrict__ wlt, const float* __restrict__ wst,
        const float* __restrict__ w1, const float* __restrict__ w2,
        const float* __restrict__ bq, const float* __restrict__ bk,
        const float* __restrict__ blt, const float* __restrict__ bst) {
    int p = blockIdx.x * 256 + threadIdx.x;
    if (p < 256) {
        g_bqk[p] = bq[p];
        g_bqk[256 + p] = bk[p];
        g_bltst[p] = blt[p] + bst[p];
    }
    if (p < 64) g_gnacc[p] = 0.f;   // zero GN accumulators every replay
    if (p >= TOTPAIRS) return;
    const float* src;
    int idx;
    if (p < OFF_WV) {
        src = (p < 32768) ? wq : wk;
        idx = (p & 32767) * 2;
    } else if (p < OFF_WO) { src = wv; idx = (p - OFF_WV) * 2; }
    else if (p < OFF_WQV) { src = wo; idx = (p - OFF_WO) * 2; }
    else if (p < OFF_WID) { src = wqv; idx = (p - OFF_WQV) * 2; }
    else if (p < OFF_LTST) { src = wid; idx = (p - OFF_WID) * 2; }
    else if (p < OFF_W1) {
        int lp = p - OFF_LTST;
        int n = lp >> 8, c = lp & 255;
        if (c < 128) { src = wlt; idx = (n * 128 + c) * 2; }
        else { src = wst; idx = (n * 128 + c - 128) * 2; }
    } else if (p < OFF_W2) { src = w1; idx = (p - OFF_W1) * 2; }
    else { src = w2; idx = (p - OFF_W2) * 2; }
    uint32_t hi, lo;
    split_bf16_pair(src[idx], src[idx + 1], hi, lo);
    g_whi[p] = hi;
    g_wlo[p] = lo;
}

// ---------------- reductions ----------------
__device__ __forceinline__ float block_reduce(float v, float* red, bool is_max) {
    int lane = threadIdx.x & 31, wid = threadIdx.x >> 5;
#pragma unroll
    for (int o = 16; o; o >>= 1) {
        float u = __shfl_xor_sync(0xffffffffu, v, o);
        v = is_max ? fmaxf(v, u) : v + u;
    }
    if (!lane) red[wid] = v;
    __syncthreads();
    int nw = (blockDim.x + 31) >> 5;
    v = (lane < nw) ? red[lane] : (is_max ? -1e30f : 0.0f);
    if (!wid) {
#pragma unroll
        for (int o = 16; o; o >>= 1) {
            float u = __shfl_xor_sync(0xffffffffu, v, o);
            v = is_max ? fmaxf(v, u) : v + u;
        }
        if (!lane) red[0] = v;
    }
    __syncthreads();
    v = red[0];
    __syncthreads();
    return v;
}

// ---------------- LayerNorm ----------------
__global__ void ln_kernel(const float* __restrict__ in, const float* __restrict__ g,
                          const float* __restrict__ b, float* __restrict__ out,
                          const float* __restrict__ pos, float* __restrict__ out2) {
    __shared__ float red[32];
    int l = blockIdx.x, c = threadIdx.x;
    float x = in[l * CD + c];
    float m = block_reduce(x, red, false) * (1.0f / CD);
    float d = x - m;
    float var = block_reduce(d * d, red, false) * (1.0f / CD);
    float y = d * rsqrtf(var + 1e-5f) * g[c] + b[c];
    out[l * CD + c] = y;
    if (out2) out2[l * CD + c] = y + pos[l * CD + c];
}

// ---------------- bf16-split tensor-core GEMM, preconverted W ----------------
// Optional gnacc: fused GroupNorm sum/sumsq of output (full tiles, res==null path).
__global__ __launch_bounds__(256) void gemm_tc2(
        const float* __restrict__ A, int lda,
        const uint32_t* __restrict__ Whg, const uint32_t* __restrict__ Wlg,
        const float* __restrict__ bias, const float* __restrict__ res,
        float* __restrict__ C, int M, int N, int K, float* __restrict__ gnacc) {
    extern __shared__ uint32_t su[];
    uint32_t* Ah = su;
    uint32_t* Al = su + GSEG;
    uint32_t* Wh = su + 2 * GSEG;
    uint32_t* Wl = su + 3 * GSEG;
    __shared__ float gsum[8], gss2[8];

    int tid = threadIdx.x;
    int bm = blockIdx.y * 64, bn = blockIdx.x * 64;
    int wid = tid >> 5, lane = tid & 31;
    int wm = wid & 3, wn = wid >> 2;
    int g = lane >> 2, t = lane & 3;
    int m0 = wm * 16;
    int Kp = K >> 1;
    float acc[4][4] = {};

    int srow = tid >> 2, sc0 = tid & 3;
    bool wok = (bn + srow) < N;
    const float* Ap = A + (size_t)(bm + srow) * lda;
    const uint32_t* Whp = Whg + (size_t)(wok ? bn + srow : 0) * Kp;
    const uint32_t* Wlp = Wlg + (size_t)(wok ? bn + srow : 0) * Kp;

    float4 pa[8];
    uint4 pwh[4], pwl[4];
    const uint4 z4 = make_uint4(0, 0, 0, 0);

#define LOADCHUNK(k0)                                                          \
    {                                                                          \
        int kp0 = (k0) >> 1;                                                   \
        _Pragma("unroll")                                                      \
        for (int i = 0; i < 4; i++) {                                          \
            int cA = (k0) + (2 * sc0 + 8 * i) * 4;                             \
            pa[2 * i] = *reinterpret_cast<const float4*>(Ap + cA);             \
            pa[2 * i + 1] = *reinterpret_cast<const float4*>(Ap + cA + 4);     \
            int pp = kp0 + (sc0 + 4 * i) * 4;                                  \
            pwh[i] = wok ? *reinterpret_cast<const uint4*>(Whp + pp) : z4;     \
            pwl[i] = wok ? *reinterpret_cast<const uint4*>(Wlp + pp) : z4;     \
        }                                                                      \
    }

    LOADCHUNK(0)

    for (int k0 = 0; k0 < K; k0 += KC) {
        if (k0) __syncthreads();
#pragma unroll
        for (int i = 0; i < 4; i++) {
            int pp = (sc0 + 4 * i) * 4;
            uint32_t h0, l0, h1, l1, h2, l2, h3, l3;
            split_bf16_pair(pa[2 * i].x, pa[2 * i].y, h0, l0);
            split_bf16_pair(pa[2 * i].z, pa[2 * i].w, h1, l1);
            split_bf16_pair(pa[2 * i + 1].x, pa[2 * i + 1].y, h2, l2);
            split_bf16_pair(pa[2 * i + 1].z, pa[2 * i + 1].w, h3, l3);
            *reinterpret_cast<uint4*>(&Ah[srow * KPP + pp]) = make_uint4(h0, h1, h2, h3);
            *reinterpret_cast<uint4*>(&Al[srow * KPP + pp]) = make_uint4(l0, l1, l2, l3);
            *reinterpret_cast<uint4*>(&Wh[srow * KPP + pp]) = pwh[i];
            *reinterpret_cast<uint4*>(&Wl[srow * KPP + pp]) = pwl[i];
        }
        __syncthreads();
        if (k0 + KC < K) LOADCHUNK(k0 + KC)

#pragma unroll
        for (int ks = 0; ks < KC / 16; ks++) {
            int kb = ks * 8 + t;
            uint32_t ah[4], al[4];
            ah[0] = Ah[(m0 + g) * KPP + kb];
            ah[1] = Ah[(m0 + 8 + g) * KPP + kb];
            ah[2] = Ah[(m0 + g) * KPP + kb + 4];
            ah[3] = Ah[(m0 + 8 + g) * KPP + kb + 4];
            al[0] = Al[(m0 + g) * KPP + kb];
            al[1] = Al[(m0 + 8 + g) * KPP + kb];
            al[2] = Al[(m0 + g) * KPP + kb + 4];
            al[3] = Al[(m0 + 8 + g) * KPP + kb + 4];
#pragma unroll
            for (int nt = 0; nt < 4; nt++) {
                int nr = wn * 32 + nt * 8 + g;
                uint32_t bh[2] = {Wh[nr * KPP + kb], Wh[nr * KPP + kb + 4]};
                uint32_t bl[2] = {Wl[nr * KPP + kb], Wl[nr * KPP + kb + 4]};
                mma_bf16(acc[nt], ah, bh);
                mma_bf16(acc[nt], ah, bl);
                mma_bf16(acc[nt], al, bh);
            }
        }
    }

    int mo = bm + m0 + g;
    float ts = 0.f, tss = 0.f;
    if (bn + 64 <= N) {
#pragma unroll
        for (int nt = 0; nt < 4; nt++) {
            int n = bn + wn * 32 + nt * 8 + 2 * t;
            float2 bv = *reinterpret_cast<const float2*>(bias + n);
            size_t o0 = (size_t)mo * N + n;
            size_t o1 = (size_t)(mo + 8) * N + n;
            float2 r0 = make_float2(acc[nt][0] + bv.x, acc[nt][1] + bv.y);
            float2 r1 = make_float2(acc[nt][2] + bv.x, acc[nt][3] + bv.y);
            if (res) {
                float2 e0 = *reinterpret_cast<const float2*>(res + o0);
                float2 e1 = *reinterpret_cast<const float2*>(res + o1);
                r0.x += e0.x; r0.y += e0.y; r1.x += e1.x; r1.y += e1.y;
            }
            if (gnacc) {
                ts += (r0.x + r0.y) + (r1.x + r1.y);
                tss += r0.x * r0.x + r0.y * r0.y + r1.x * r1.x + r1.y * r1.y;
            }
            *reinterpret_cast<float2*>(C + o0) = r0;
            *reinterpret_cast<float2*>(C + o1) = r1;
        }
    } else {
#pragma unroll
        for (int nt = 0; nt < 4; nt++) {
            int n = bn + wn * 32 + nt * 8 + 2 * t;
#pragma unroll
            for (int e = 0; e < 2; e++) {
                if (n + e >= N) continue;
                float v0 = acc[nt][e] + bias[n + e];
                float v1 = acc[nt][2 + e] + bias[n + e];
                if (res) {
                    v0 += res[(size_t)mo * N + n + e];
                    v1 += res[(size_t)(mo + 8) * N + n + e];
                }
                C[(size_t)mo * N + n + e] = v0;
                C[(size_t)(mo + 8) * N + n + e] = v1;
            }
        }
    }
    if (gnacc) {
#pragma unroll
        for (int o = 16; o; o >>= 1) {
            ts += __shfl_xor_sync(0xffffffffu, ts, o);
            tss += __shfl_xor_sync(0xffffffffu, tss, o);
        }
        if (!lane) { gsum[wid] = ts; gss2[wid] = tss; }
        __syncthreads();
        if (tid < 2) {
            float S = gsum[tid * 4] + gsum[tid * 4 + 1] + gsum[tid * 4 + 2] + gsum[tid * 4 + 3];
            float SS = gss2[tid * 4] + gss2[tid * 4 + 1] + gss2[tid * 4 + 2] + gss2[tid * 4 + 3];
            int grp = (bn >> 5) + tid;
            atomicAdd(&gnacc[grp * 2], S);
            atomicAdd(&gnacc[grp * 2 + 1], SS);
        }
    }
#undef LOADCHUNK
}

// ---------------- tensor-core flash attention (bf16 hi/lo split) ----------------
// If idkv != null: K rows scaled by (1+tanh(id_k[h])) and V rows offset by id_v (fused global-KV).
__global__ __launch_bounds__(256) void flash_attn_tc(
        const float* __restrict__ Q, int ldq,
        const float* __restrict__ K, int ldk,
        const float* __restrict__ V, int ldv,
        const float* __restrict__ idkv,
        float* __restrict__ O, int ldo) {
    __shared__ uint32_t Qhi[64][20], Qlo[64][20];
    __shared__ uint32_t Khi[64][20], Klo[64][20];
    __shared__ uint32_t Vthi[32][36], Vtlo[32][36];
    __shared__ float redmax[2][64], redsum[2][64];
    __shared__ float Osm[64][33];

    int h = blockIdx.y, q0 = blockIdx.x * BQ;
    int tid = threadIdx.x, wid = tid >> 5, lane = tid & 31;
    int wm = wid & 3, wn = wid >> 2;
    int g = lane >> 2, t = lane & 3;
    int m0 = wm * 16;
    int lrow = tid >> 2, lcol = (tid & 3) * 8;

    {
        const float* qp = Q + (size_t)(q0 + lrow) * ldq + h * HD + lcol;
        float4 a = *reinterpret_cast<const float4*>(qp);
        float4 b = *reinterpret_cast<const float4*>(qp + 4);
        float xv[8] = {a.x, a.y, a.z, a.w, b.x, b.y, b.z, b.w};
#pragma unroll
        for (int j = 0; j < 4; j++) {
            uint32_t hi, lo;
            split_bf16_pair(xv[2 * j] * SCALE, xv[2 * j + 1] * SCALE, hi, lo);
            Qhi[lrow][lcol / 2 + j] = hi;
            Qlo[lrow][lcol / 2 + j] = lo;
        }
    }

    float mrow[2] = {-1e30f, -1e30f}, lsum[2] = {0.f, 0.f};
    float Oacc[4][4] = {};

    for (int kt = 0; kt < LQ; kt += BK) {
        const float* kp = K + (size_t)(kt + lrow) * ldk + h * HD + lcol;
        const float* vp = V + (size_t)(kt + lrow) * ldv + h * HD + lcol;
        float4 ka = *reinterpret_cast<const float4*>(kp);
        float4 kb = *reinterpret_cast<const float4*>(kp + 4);
        float4 va = *reinterpret_cast<const float4*>(vp);
        float4 vb = *reinterpret_cast<const float4*>(vp + 4);
        float kmul = 1.f;
        float4 ia = make_float4(0.f, 0.f, 0.f, 0.f), ib = ia;
        if (idkv) {
            const float* ip = idkv + (size_t)(kt + lrow) * 264;
            kmul = 1.f + tanhf(ip[h]);
            ia = *reinterpret_cast<const float4*>(ip + 8 + h * HD + lcol);
            ib = *reinterpret_cast<const float4*>(ip + 8 + h * HD + lcol + 4);
        }
        __syncthreads();
        {
            float kv[8] = {ka.x * kmul, ka.y * kmul, ka.z * kmul, ka.w * kmul,
                           kb.x * kmul, kb.y * kmul, kb.z * kmul, kb.w * kmul};
#pragma unroll
            for (int j = 0; j < 4; j++) {
                uint32_t hi, lo;
                split_bf16_pair(kv[2 * j], kv[2 * j + 1], hi, lo);
                Khi[lrow][lcol / 2 + j] = hi;
                Klo[lrow][lcol / 2 + j] = lo;
            }
            float vv[8] = {va.x + ia.x, va.y + ia.y, va.z + ia.z, va.w + ia.w,
                           vb.x + ib.x, vb.y + ib.y, vb.z + ib.z, vb.w + ib.w};
            __nv_bfloat16* VH = reinterpret_cast<__nv_bfloat16*>(Vthi);
            __nv_bfloat16* VL = reinterpret_cast<__nv_bfloat16*>(Vtlo);
#pragma unroll
            for (int j = 0; j < 8; j++) {
                int d = lcol + j;
                float x = vv[j];
                __nv_bfloat16 hb = __float2bfloat16(x);
                VH[d * 72 + lrow] = hb;
                VL[d * 72 + lrow] = __float2bfloat16(x - __bfloat162float(hb));
            }
        }
        __syncthreads();

        float S[4][4];
#pragma unroll
        for (int nt = 0; nt < 4; nt++)
#pragma unroll
            for (int c = 0; c < 4; c++) S[nt][c] = 0.f;
#pragma unroll
        for (int kc = 0; kc < 2; kc++) {
            uint32_t ah[4], al[4];
            ah[0] = Qhi[m0 + g][kc * 8 + t];     ah[1] = Qhi[m0 + 8 + g][kc * 8 + t];
            ah[2] = Qhi[m0 + g][kc * 8 + t + 4]; ah[3] = Qhi[m0 + 8 + g][kc * 8 + t + 4];
            al[0] = Qlo[m0 + g][kc * 8 + t];     al[1] = Qlo[m0 + 8 + g][kc * 8 + t];
            al[2] = Qlo[m0 + g][kc * 8 + t + 4]; al[3] = Qlo[m0 + 8 + g][kc * 8 + t + 4];
#pragma unroll
            for (int nt = 0; nt < 4; nt++) {
                int kr = wn * 32 + nt * 8 + g;
                uint32_t bh[2] = {Khi[kr][kc * 8 + t], Khi[kr][kc * 8 + t + 4]};
                uint32_t bl[2] = {Klo[kr][kc * 8 + t], Klo[kr][kc * 8 + t + 4]};
                mma_bf16(S[nt], ah, bh);
                mma_bf16(S[nt], ah, bl);
                mma_bf16(S[nt], al, bh);
            }
        }

        float pmA = -1e30f, pmB = -1e30f;
#pragma unroll
        for (int nt = 0; nt < 4; nt++) {
            pmA = fmaxf(pmA, fmaxf(S[nt][0], S[nt][1]));
            pmB = fmaxf(pmB, fmaxf(S[nt][2], S[nt][3]));
        }
        pmA = fmaxf(pmA, __shfl_xor_sync(0xffffffffu, pmA, 1));
        pmA = fmaxf(pmA, __shfl_xor_sync(0xffffffffu, pmA, 2));
        pmB = fmaxf(pmB, __shfl_xor_sync(0xffffffffu, pmB, 1));
        pmB = fmaxf(pmB, __shfl_xor_sync(0xffffffffu, pmB, 2));
        if (t == 0) {
            redmax[wn][m0 + g] = pmA;
            redmax[wn][m0 + 8 + g] = pmB;
        }
        __syncthreads();
        float nmA = fmaxf(mrow[0], fmaxf(redmax[0][m0 + g], redmax[1][m0 + g]));
        float nmB = fmaxf(mrow[1], fmaxf(redmax[0][m0 + 8 + g], redmax[1][m0 + 8 + g]));
        float alA = __expf(mrow[0] - nmA), alB = __expf(mrow[1] - nmB);
        mrow[0] = nmA; mrow[1] = nmB;
        float psA = 0.f, psB = 0.f;
#pragma unroll
        for (int nt = 0; nt < 4; nt++) {
            S[nt][0] = __expf(S[nt][0] - nmA); S[nt][1] = __expf(S[nt][1] - nmA);
            S[nt][2] = __expf(S[nt][2] - nmB); S[nt][3] = __expf(S[nt][3] - nmB);
            psA += S[nt][0] + S[nt][1];
            psB += S[nt][2] + S[nt][3];
        }
        psA += __shfl_xor_sync(0xffffffffu, psA, 1);
        psA += __shfl_xor_sync(0xffffffffu, psA, 2);
        psB += __shfl_xor_sync(0xffffffffu, psB, 1);
        psB += __shfl_xor_sync(0xffffffffu, psB, 2);
        if (t == 0) {
            redsum[wn][m0 + g] = psA;
            redsum[wn][m0 + 8 + g] = psB;
        }
#pragma unroll
        for (int nt = 0; nt < 4; nt++) {
            Oacc[nt][0] *= alA; Oacc[nt][1] *= alA;
            Oacc[nt][2] *= alB; Oacc[nt][3] *= alB;
        }
        __syncthreads();
        lsum[0] = lsum[0] * alA + redsum[0][m0 + g] + redsum[1][m0 + g];
        lsum[1] = lsum[1] * alB + redsum[0][m0 + 8 + g] + redsum[1][m0 + 8 + g];

#pragma unroll
        for (int kc2 = 0; kc2 < 2; kc2++) {
            uint32_t ph[4], pl[4];
            split_bf16_pair(S[2 * kc2][0], S[2 * kc2][1], ph[0], pl[0]);
            split_bf16_pair(S[2 * kc2][2], S[2 * kc2][3], ph[1], pl[1]);
            split_bf16_pair(S[2 * kc2 + 1][0], S[2 * kc2 + 1][1], ph[2], pl[2]);
            split_bf16_pair(S[2 * kc2 + 1][2], S[2 * kc2 + 1][3], ph[3], pl[3]);
            int cb = wn * 16 + kc2 * 8 + t;
#pragma unroll
            for (int ntv = 0; ntv < 4; ntv++) {
                int vr = ntv * 8 + g;
                uint32_t bh[2] = {Vthi[vr][cb], Vthi[vr][cb + 4]};
                uint32_t bl[2] = {Vtlo[vr][cb], Vtlo[vr][cb + 4]};
                mma_bf16(Oacc[ntv], ph, bh);
                mma_bf16(Oacc[ntv], ph, bl);
                mma_bf16(Oacc[ntv], pl, bh);
            }
        }
    }

    if (wn == 0) {
#pragma unroll
        for (int ntv = 0; ntv < 4; ntv++) {
            int d = ntv * 8 + 2 * t;
            Osm[m0 + g][d] = Oacc[ntv][0];
            Osm[m0 + g][d + 1] = Oacc[ntv][1];
            Osm[m0 + 8 + g][d] = Oacc[ntv][2];
            Osm[m0 + 8 + g][d + 1] = Oacc[ntv][3];
        }
    }
    __syncthreads();
    if (wn == 1) {
        float invA = 1.0f / lsum[0], invB = 1.0f / lsum[1];
#pragma unroll
        for (int ntv = 0; ntv < 4; ntv++) {
            int d = ntv * 8 + 2 * t;
            float* op0 = O + (size_t)(q0 + m0 + g) * ldo + h * HD + d;
            float* op1 = O + (size_t)(q0 + m0 + 8 + g) * ldo + h * HD + d;
            op0[0] = (Oacc[ntv][0] + Osm[m0 + g][d]) * invA;
            op0[1] = (Oacc[ntv][1] + Osm[m0 + g][d + 1]) * invA;
            op1[0] = (Oacc[ntv][2] + Osm[m0 + 8 + g][d]) * invB;
            op1[1] = (Oacc[ntv][3] + Osm[m0 + 8 + g][d + 1]) * invB;
        }
    }
}

// ---------------- tiled local attention with fused global-KV transform ----------------
__global__ __launch_bounds__(256) void local_attn_tile(
        const float* __restrict__ Q, int ldq,
        const float* __restrict__ qvbuf, const float* __restrict__ idkv,
        float* __restrict__ O, int ldo) {
    extern __shared__ float sm[];
    float* winK = sm;
    float* winV = sm + LTWW * 33;
    float* pb = sm + 2 * LTWW * 33;
    int h = blockIdx.y;
    int ty0 = (blockIdx.x / 5) * 8, tx0 = (blockIdx.x % 5) * 8;
    int wy0 = ty0 - PADR, wx0 = tx0 - PADR;
    int tid = threadIdx.x, w = tid >> 5, lane = tid & 31;

    for (int idx = tid; idx < LTWW * 32; idx += 256) {
        int pos = idx >> 5, d = idx & 31;
        int gy = wy0 + pos / LTW, gx = wx0 + pos % LTW;
        bool ok = ((unsigned)gy < H2D) && ((unsigned)gx < W2D);
        float kvv = 0.f, vvv = 0.f;
        if (ok) {
            size_t r = (size_t)(gy * W2D + gx);
            float ik = idkv[r * 264 + h];
            kvv = qvbuf[r * 512 + h * HD + d] * (1.0f + tanhf(ik));
            vvv = qvbuf[r * 512 + 256 + h * HD + d] + idkv[r * 264 + 8 + h * HD + d];
        }
        winK[pos * 33 + d] = kvv;
        winV[pos * 33 + d] = vvv;
    }
    __syncthreads();

    int qy = ty0 + w;
    for (int qi = 0; qi < 8; qi++) {
        int qx = tx0 + qi;
        float qv = Q[(size_t)(qy * W2D + qx) * ldq + h * HD + lane] * SCALE;
        float lg[8];
        int wi[8];
        bool val[8];
#pragma unroll
        for (int c = 0; c < 8; c++) {
            int j = c * 32 + lane;
            int jr = j / 15, jc = j - jr * 15;
            int gy2 = qy + jr - PADR, gx2 = qx + jc - PADR;
            val[c] = (j < WSQ) && ((unsigned)gy2 < H2D) && ((unsigned)gx2 < W2D);
            wi[c] = (j < WSQ) ? ((w + jr) * LTW + (qi + jc)) : 0;
            lg[c] = 0.f;
        }
#pragma unroll 8
        for (int d = 0; d < 32; d++) {
            float qd = __shfl_sync(0xffffffffu, qv, d);
#pragma unroll
            for (int c = 0; c < 8; c++)
                lg[c] = fmaf(qd, winK[wi[c] * 33 + d], lg[c]);
        }
        float mx = -1e30f;
#pragma unroll
        for (int c = 0; c < 8; c++) {
            lg[c] = val[c] ? lg[c] : -1e30f;
            mx = fmaxf(mx, lg[c]);
        }
#pragma unroll
        for (int o = 16; o; o >>= 1) mx = fmaxf(mx, __shfl_xor_sync(0xffffffffu, mx, o));
        float s = 0.f;
#pragma unroll
        for (int c = 0; c < 8; c++) {
            lg[c] = __expf(lg[c] - mx);
            s += lg[c];
        }
#pragma unroll
        for (int o = 16; o; o >>= 1) s += __shfl_xor_sync(0xffffffffu, s, o);
        float inv = 1.0f / s;
#pragma unroll
        for (int c = 0; c < 8; c++) pb[w * 264 + c * 32 + lane] = lg[c] * inv;
        __syncwarp();

        float oacc = 0.f;
        int j = 0;
#pragma unroll
        for (int jr = 0; jr < 15; jr++) {
            int base = ((w + jr) * LTW + qi) * 33 + lane;
#pragma unroll
            for (int jc = 0; jc < 15; jc++) {
                oacc = fmaf(pb[w * 264 + j], winV[base + jc * 33], oacc);
                j++;
            }
        }
        O[(size_t)(qy * W2D + qx) * ldo + h * HD + lane] = oacc;
        __syncwarp();
    }
}

// ---------------- fused GN-apply + GELU + depthwise 5x5 conv ----------------
#define DWP 144          // 12x12 halo positions
__global__ __launch_bounds__(256) void dwconv_gn(
        const float* __restrict__ x1, const float* __restrict__ acc,
        const float* __restrict__ gg, const float* __restrict__ gb,
        const float* __restrict__ dwk, float* __restrict__ y) {
    extern __shared__ float sm[];
    float* winX = sm;                       // [144][128]
    float* wk = sm + DWP * 128;             // [128][25]
    float* sgg = wk + 128 * 25;             // [128]
    float* sgb = sgg + 128;                 // [128]
    float* smr = sgb + 128;                 // [8]
    int tile = blockIdx.x, slab = blockIdx.y;
    int ty0 = (tile / 5) * 8, tx0 = (tile % 5) * 8;
    int tid = threadIdx.x;
    int c0 = slab * 128;

    if (tid < 4) {
        int gidx = (c0 >> 5) + tid;
        const float inv = 1.0f / 51200.0f;
        float s = acc[gidx * 2], ss = acc[gidx * 2 + 1];
        float m = s * inv;
        float var = ss * inv - m * m;
        smr[tid] = m;
        smr[4 + tid] = rsqrtf(var + 1e-5f);
    }
    if (tid < 128) {
        sgg[tid] = gg[c0 + tid];
        sgb[tid] = gb[c0 + tid];
    }
    for (int i = tid; i < 128 * 25; i += 256) wk[i] = dwk[c0 * 25 + i];
    __syncthreads();

    for (int idx = tid; idx < DWP * 32; idx += 256) {
        int pos = idx >> 5, f4 = idx & 31;
        int gy = ty0 - 2 + pos / 12, gx = tx0 - 2 + pos % 12;
        bool ok = ((unsigned)gy < H2D) && ((unsigned)gx < W2D);
        float4 v = ok ? *reinterpret_cast<const float4*>(
                            x1 + (size_t)(gy * W2D + gx) * DFF + c0 + f4 * 4)
                      : make_float4(0.f, 0.f, 0.f, 0.f);
        int grp = f4 >> 3;
        float m = smr[grp], r = smr[4 + grp];
        int cl = f4 * 4;
        float e[4] = {v.x, v.y, v.z, v.w};
#pragma unroll
        for (int j = 0; j < 4; j++) {
            float t2 = (e[j] - m) * r * sgg[cl + j] + sgb[cl + j];
            e[j] = 0.5f * t2 * (1.0f + erff(t2 * 0.70710678118654752f));
        }
        float4 o = make_float4(ok ? e[0] : 0.f, ok ? e[1] : 0.f,
                               ok ? e[2] : 0.f, ok ? e[3] : 0.f);
        *reinterpret_cast<float4*>(&winX[pos * 128 + cl]) = o;
    }
    __syncthreads();

    int c = tid & 127, pg = tid >> 7;
    float wreg[25];
#pragma unroll
    for (int k = 0; k < 25; k++) wreg[k] = wk[c * 25 + k];

#pragma unroll
    for (int py = 0; py < 4; py++) {
        int oy = pg * 4 + py;
        float oac[8] = {};
#pragma unroll
        for (int dy = 0; dy < 5; dy++) {
            float rv[12];
            int rb = (oy + dy) * 12;
#pragma unroll
            for (int j = 0; j < 12; j++) rv[j] = winX[(rb + j) * 128 + c];
#pragma unroll
            for (int dx = 0; dx < 5; dx++) {
                float wv = wreg[dy * 5 + dx];
#pragma unroll
                for (int o = 0; o < 8; o++)
                    oac[o] = fmaf(rv[o + dx], wv, oac[o]);
            }
        }
#pragma unroll
        for (int o = 0; o < 8; o++)
            y[(size_t)((ty0 + oy) * W2D + tx0 + o) * DFF + c0 + c] = oac[o];
    }
}

// ---------------- host ----------------
static const int GEMM_SMEM = 4 * GSEG * (int)sizeof(uint32_t);
static const int DW_SMEM = (DWP * 128 + 128 * 25 + 256 + 8) * (int)sizeof(float);

extern "C" void kernel_launch(void* const* d_in, const int* in_sizes, int n_in,
                              void* d_out, int out_size) {
    const float* tgt = (const float*)d_in[0];
    const float* curr_id_emb = (const float*)d_in[1];
    const float* self_pos = (const float*)d_in[2];
    const float* ln1_g = (const float*)d_in[3];
    const float* ln1_b = (const float*)d_in[4];
    const float* sa_wq = (const float*)d_in[5];
    const float* sa_bq = (const float*)d_in[6];
    const float* sa_wk = (const float*)d_in[7];
    const float* sa_bk = (const float*)d_in[8];
    const float* sa_wv = (const float*)d_in[9];
    const float* sa_bv = (const float*)d_in[10];
    const float* sa_wo = (const float*)d_in[11];
    const float* sa_bo = (const float*)d_in[12];
    const float* ln2_g = (const float*)d_in[13];
    const float* ln2_b = (const float*)d_in[14];
    const float* w_qv = (const float*)d_in[15];
    const float* b_qv = (const float*)d_in[16];
    const float* w_id = (const float*)d_in[17];
    const float* b_id = (const float*)d_in[18];
    const float* lt_wo = (const float*)d_in[19];
    const float* lt_bo = (const float*)d_in[20];
    const float* st_wo = (const float*)d_in[21];
    const float* st_bo = (const float*)d_in[22];
    const float* ln3_g = (const float*)d_in[23];
    const float* ln3_b = (const float*)d_in[24];
    const float* w1 = (const float*)d_in[25];
    const float* b1 = (const float*)d_in[26];
    const float* gn_g = (const float*)d_in[27];
    const float* gn_b = (const float*)d_in[28];
    const float* dw_k = (const float*)d_in[29];
    const float* w2 = (const float*)d_in[30];
    const float* b2 = (const float*)d_in[31];
    float* out = (float*)d_out;

    float *tln, *qkin, *qk, *v, *cat, *tgt1, *qv, *idkv, *tgt2, *x1, *x2, *gnacc;
    float *bqk, *bltst;
    uint32_t *whi, *wlo;
    cudaGetSymbolAddress((void**)&tln, g_tln);
    cudaGetSymbolAddress((void**)&qkin, g_qkin);
    cudaGetSymbolAddress((void**)&qk, g_qk);
    cudaGetSymbolAddress((void**)&v, g_v);
    cudaGetSymbolAddress((void**)&cat, g_cat);
    cudaGetSymbolAddress((void**)&tgt1, g_tgt1);
    cudaGetSymbolAddress((void**)&qv, g_qv);
    cudaGetSymbolAddress((void**)&idkv, g_idkv);
    cudaGetSymbolAddress((void**)&tgt2, g_tgt2);
    cudaGetSymbolAddress((void**)&x1, g_x1);
    cudaGetSymbolAddress((void**)&x2, g_x2);
    cudaGetSymbolAddress((void**)&gnacc, g_gnacc);
    cudaGetSymbolAddress((void**)&bqk, g_bqk);
    cudaGetSymbolAddress((void**)&bltst, g_bltst);
    cudaGetSymbolAddress((void**)&whi, g_whi);
    cudaGetSymbolAddress((void**)&wlo, g_wlo);

    const int LOCAL_SMEM = (2 * LTWW * 33 + 8 * 264) * (int)sizeof(float);

    // one-time setup (first call is the non-captured correctness run)
    static bool init = false;
    static cudaStream_t s1, s2;
    static cudaEvent_t evR, evW, evB, evL1, evV, evQV, evL;
    if (!init) {
        cudaStreamCreateWithFlags(&s1, cudaStreamNonBlocking);
        cudaStreamCreateWithFlags(&s2, cudaStreamNonBlocking);
        cudaEventCreateWithFlags(&evR, cudaEventDisableTiming);
        cudaEventCreateWithFlags(&evW, cudaEventDisableTiming);
        cudaEventCreateWithFlags(&evB, cudaEventDisableTiming);
        cudaEventCreateWithFlags(&evL1, cudaEventDisableTiming);
        cudaEventCreateWithFlags(&evV, cudaEventDisableTiming);
        cudaEventCreateWithFlags(&evQV, cudaEventDisableTiming);
        cudaEventCreateWithFlags(&evL, cudaEventDisableTiming);
        cudaFuncSetAttribute(local_attn_tile, cudaFuncAttributeMaxDynamicSharedMemorySize, LOCAL_SMEM);
        cudaFuncSetAttribute(gemm_tc2, cudaFuncAttributeMaxDynamicSharedMemorySize, GEMM_SMEM);
        cudaFuncSetAttribute(dwconv_gn, cudaFuncAttributeMaxDynamicSharedMemorySize, DW_SMEM);
        init = true;
    }

    auto GEMM = [&](cudaStream_t st, const float* A, int lda, int woff, const float* bias,
                    const float* res, float* C, int M, int N, int K, float* gn) {
        dim3 grid((N + 63) / 64, (M + 63) / 64);
        gemm_tc2<<<grid, 256, GEMM_SMEM, st>>>(A, lda, whi + woff, wlo + woff, bias, res, C,
                                               M, N, K, gn);
    };

    // ---- fork: side stream does weight conversion + idkv GEMM ----
    cudaEventRecord(evR, 0);
    cudaStreamWaitEvent(s1, evR, 0);
    conv_weights<<<(TOTPAIRS + 255) / 256, 256, 0, s1>>>(
        sa_wq, sa_wk, sa_wv, sa_wo, w_qv, w_id, lt_wo, st_wo, w1, w2,
        sa_bq, sa_bk, lt_bo, st_bo);
    cudaEventRecord(evW, s1);
    GEMM(s1, curr_id_emb, CD, OFF_WID, b_id, nullptr, idkv, LQ, 264, CD, nullptr);
    cudaEventRecord(evB, s1);

    // ---- self-attention block (default stream) ----
    ln_kernel<<<LQ, 256>>>(tgt, ln1_g, ln1_b, tln, self_pos, qkin);
    cudaEventRecord(evL1, 0);
    cudaStreamWaitEvent(0, evW, 0);
    GEMM(0, qkin, CD, OFF_QK, bqk, nullptr, qk, LQ, 512, CD, nullptr);      // [q|k]
    cudaStreamWaitEvent(s2, evW, 0);
    cudaStreamWaitEvent(s2, evL1, 0);
    GEMM(s2, tln, CD, OFF_WV, sa_bv, nullptr, v, LQ, CD, CD, nullptr);      // v (parallel)
    cudaEventRecord(evV, s2);
    cudaStreamWaitEvent(0, evV, 0);
    flash_attn_tc<<<dim3(LQ / BQ, NH), 256>>>(qk, 512, qk + 256, 512, v, CD, nullptr, cat, 512);
    GEMM(0, cat, 512, OFF_WO, sa_bo, tgt, tgt1, LQ, CD, CD, nullptr);       // tgt1 = tgt + SA

    // ---- long/short-term block ----
    ln_kernel<<<LQ, 256>>>(tgt1, ln2_g, ln2_b, tln, nullptr, nullptr);
    GEMM(0, tln, CD, OFF_WQV, b_qv, nullptr, qv, LQ, 512, CD, nullptr);     // [curr_Q|curr_V]
    cudaEventRecord(evQV, 0);
    cudaStreamWaitEvent(s2, evQV, 0);
    cudaStreamWaitEvent(s2, evB, 0);
    local_attn_tile<<<dim3(25, NH), 256, LOCAL_SMEM, s2>>>(qv, 512, qv, idkv, cat + 256, 512);
    cudaEventRecord(evL, s2);
    cudaStreamWaitEvent(0, evB, 0);
    flash_attn_tc<<<dim3(LQ / BQ, NH), 256>>>(qv, 512, qv, 512, qv + 256, 512, idkv, cat, 512);
    cudaStreamWaitEvent(0, evL, 0);
    GEMM(0, cat, 512, OFF_LTST, bltst, tgt1, tgt2, LQ, CD, 512, nullptr);   // tgt2 = tgt1+LT+ST

    // ---- FFN block ----
    ln_kernel<<<LQ, 256>>>(tgt2, ln3_g, ln3_b, tln, nullptr, nullptr);
    GEMM(0, tln, CD, OFF_W1, b1, nullptr, x1, LQ, DFF, CD, gnacc);          // + fused GN stats
    dwconv_gn<<<dim3(25, 8), 256, DW_SMEM>>>(x1, gnacc, gn_g, gn_b, dw_k, x2);
    GEMM(0, x2, DFF, OFF_W2, b2, tgt2, out, LQ, CD, DFF, nullptr);          // out = tgt2 + FFN
}